// round 11
// baseline (speedup 1.0000x reference)
#include <cuda_runtime.h>
#include <cuda_bf16.h>
#include <math.h>

#define T_OBS 8
#define EPSBN 1e-5f

typedef unsigned int u32;
typedef unsigned long long u64;

#define MAXB 131072
#define WSTR 88   // padded k-stride (bf16): 176B rows, conflict-free ldmatrix

// ---------------- static device scratch ------------------------------------
__device__ float  g_h[MAXB * 64];
__device__ float  g_c[MAXB * 64];
__device__ float  g_z[MAXB * 16];
__device__ float  g_last[MAXB * 2];
__device__ __align__(16) __nv_bfloat16 g_Wh[256 * WSTR];
__device__ __align__(16) __nv_bfloat16 g_Wl[256 * WSTR];
__device__ float  g_bias[256];
__device__ double g_enc_stats[5];
__device__ double g_se_stats[5];
__device__ double g_hp_stats[32];

// ---------------- helpers ----------------------------------------------------
__device__ __forceinline__ float scalar_f(const void* p) {
    int iv = *(const int*)p;
    float fv = __int_as_float(iv);
    if (fv >= 1e-3f && fv <= 1e7f) return fv;
    return (float)iv;
}
__device__ __forceinline__ float fast_sig(float x) {
    float t; asm("ex2.approx.f32 %0, %1;" : "=f"(t) : "f"(-1.4426950408889634f * x));
    float r; asm("rcp.approx.f32 %0, %1;" : "=f"(r) : "f"(1.0f + t));
    return r;
}
// fused LSTM pointwise: 8 MUFU per cell
__device__ __forceinline__ void lstm_cell(float iv, float fv, float gv, float ov,
                                          float cold, float& cnew, float& hnew) {
    gv = fminf(fmaxf(gv, -30.f), 30.f);
    float tf; asm("ex2.approx.f32 %0, %1;" : "=f"(tf) : "f"(-1.4426950408889634f * fv));
    float sf; asm("rcp.approx.f32 %0, %1;" : "=f"(sf) : "f"(1.0f + tf));
    float ei; asm("ex2.approx.f32 %0, %1;" : "=f"(ei) : "f"(-1.4426950408889634f * iv));
    float eg; asm("ex2.approx.f32 %0, %1;" : "=f"(eg) : "f"(2.8853900817779268f * gv));
    float dig = (1.0f + ei) * (eg + 1.0f);
    float rig; asm("rcp.approx.f32 %0, %1;" : "=f"(rig) : "f"(dig));
    float c2 = sf * cold + (eg - 1.0f) * rig;
    cnew = c2;
    float eo; asm("ex2.approx.f32 %0, %1;" : "=f"(eo) : "f"(-1.4426950408889634f * ov));
    float ec; asm("ex2.approx.f32 %0, %1;" : "=f"(ec) : "f"(2.8853900817779268f * c2));
    float doc = (1.0f + eo) * (ec + 1.0f);
    float roc; asm("rcp.approx.f32 %0, %1;" : "=f"(roc) : "f"(doc));
    hnew = (ec - 1.0f) * roc;
}
__device__ __forceinline__ float wred(float v) {
#pragma unroll
    for (int o = 16; o > 0; o >>= 1) v += __shfl_down_sync(0xffffffffu, v, o);
    return v;
}
__device__ __forceinline__ u32 smem_u32(const void* p) {
    u32 a;
    asm("{ .reg .u64 t; cvta.to.shared.u64 t, %1; cvt.u32.u64 %0, t; }" : "=r"(a) : "l"(p));
    return a;
}
__device__ __forceinline__ void ldsm4(u32* r, u32 addr) {
    asm volatile("ldmatrix.sync.aligned.m8n8.x4.shared.b16 {%0,%1,%2,%3}, [%4];"
        : "=r"(r[0]), "=r"(r[1]), "=r"(r[2]), "=r"(r[3]) : "r"(addr));
}
__device__ __forceinline__ void mma16816(float* d, const u32* a, const u32* b) {
    asm volatile(
        "mma.sync.aligned.m16n8k16.row.col.f32.bf16.bf16.f32 "
        "{%0,%1,%2,%3},{%4,%5,%6,%7},{%8,%9},{%0,%1,%2,%3};"
        : "+f"(d[0]), "+f"(d[1]), "+f"(d[2]), "+f"(d[3])
        : "r"(a[0]), "r"(a[1]), "r"(a[2]), "r"(a[3]), "r"(b[0]), "r"(b[1]));
}
__device__ __forceinline__ u32 pack_bf16_hi(float a0, float a1) {
    __nv_bfloat16 h0 = __float2bfloat16(a0), h1 = __float2bfloat16(a1);
    return ((u32)__bfloat16_as_ushort(h1) << 16) | __bfloat16_as_ushort(h0);
}
__device__ __forceinline__ u32 pack_bf16_lo(float a0, float a1) {
    __nv_bfloat16 h0 = __float2bfloat16(a0), h1 = __float2bfloat16(a1);
    __nv_bfloat16 l0 = __float2bfloat16(a0 - __bfloat162float(h0));
    __nv_bfloat16 l1 = __float2bfloat16(a1 - __bfloat162float(h1));
    return ((u32)__bfloat16_as_ushort(l1) << 16) | __bfloat16_as_ushort(l0);
}

// ---------------- smem layout (double-buffered A) ----------------------------
#define O_WH   0                    // 45056
#define O_WL   45056                // 45056
#define O_AB0  90112                // AH0; AL0=+11264; AH1=+22528; AL1=+33792
#define O_BIAS 135168               // 1024
#define O_FOLD 136192               // 192
#define LSTM_SMEM 136448

// ---------------- prep: fold se_W2/se_b2 into Wih; bf16-split ---------------
__global__ void k_prep(const float* __restrict__ Wih, const float* __restrict__ Whh,
                       const float* __restrict__ bih, const float* __restrict__ bhh,
                       const float* __restrict__ seW2, const float* __restrict__ seb2) {
    int gc = threadIdx.x;
    if (gc < 5) g_enc_stats[gc] = 0.0;
    float wr[64];
#pragma unroll 8
    for (int m = 0; m < 64; m++) wr[m] = Wih[gc * 64 + m];
    float be = bih[gc] + bhh[gc];
#pragma unroll 8
    for (int m = 0; m < 64; m++) be += wr[m] * seb2[m];
    g_bias[gc] = be;
    for (int k = 0; k < WSTR; k++) {
        float w = 0.f;
        if (k < 16) {
#pragma unroll 8
            for (int m = 0; m < 64; m++) w += wr[m] * seW2[m * 16 + k];
        } else if (k < 80) {
            w = Whh[gc * 64 + (k - 16)];
        }
        __nv_bfloat16 hi = __float2bfloat16(w);
        __nv_bfloat16 lo = __float2bfloat16(w - __bfloat162float(hi));
        g_Wh[gc * WSTR + k] = hi;
        g_Wl[gc * WSTR + k] = lo;
    }
}

// ---------------- moments of normalized obs + init last_pos -----------------
__global__ void k_moments(const float* __restrict__ obs, const void* pxm, const void* pym,
                          int TB, int B) {
    __shared__ float red[8][5];
    float invx = 1.0f / scalar_f(pxm), invy = 1.0f / scalar_f(pym);
    int idx = blockIdx.x * blockDim.x + threadIdx.x;
    int stride = gridDim.x * blockDim.x;
    float s[5] = {0, 0, 0, 0, 0};
    for (int i = idx; i < TB; i += stride) {
        float x = obs[2 * i] * invx, y = obs[2 * i + 1] * invy;
        s[0] += x; s[1] += y; s[2] += x * x; s[3] += y * y; s[4] += x * y;
    }
    int wid = threadIdx.x >> 5, lane = threadIdx.x & 31;
#pragma unroll
    for (int k = 0; k < 5; k++) s[k] = wred(s[k]);
    if (lane == 0) {
#pragma unroll
        for (int k = 0; k < 5; k++) red[wid][k] = s[k];
    }
    __syncthreads();
    if (wid == 0 && lane < 5) {
        float t = 0.f;
#pragma unroll
        for (int w = 0; w < 8; w++) t += red[w][lane];
        atomicAdd(&g_enc_stats[lane], (double)t);
    }
    int off = TB - B;
    for (int i = idx; i < B; i += stride) {
        g_last[2 * i]     = obs[2 * (off + i)]     * invx;
        g_last[2 * i + 1] = obs[2 * (off + i) + 1] * invy;
    }
}

// ======================= fused 8-step encoder ================================
__global__ void __launch_bounds__(512, 1)
k_enc(const float* __restrict__ obs, int B, int nTiles,
      const float* __restrict__ seW1, const float* __restrict__ seb1,
      const float* __restrict__ seg_, const float* __restrict__ seb_,
      const void* pxm, const void* pym, float Ninv) {
    extern __shared__ char sm[];
    float* bs = (float*)(sm + O_BIAS);
    float* fold = (float*)(sm + O_FOLD);
    u32 smb = smem_u32(sm);
    int tid = threadIdx.x, wid = tid >> 5, lane = tid & 31;

    {
        const float4* s1 = (const float4*)g_Wh;
        const float4* s2 = (const float4*)g_Wl;
        float4* d1 = (float4*)(sm + O_WH);
        float4* d2 = (float4*)(sm + O_WL);
        for (int i = tid; i < 2816; i += 512) { d1[i] = s1[i]; d2[i] = s2[i]; }
    }
    if (tid < 256) bs[tid] = g_bias[tid];
    if (blockIdx.x == 0 && tid < 32) g_hp_stats[tid] = 0.0;
    if (tid < 16) {   // encode BN fold (analytic, from 5 moments)
        const double* st = g_enc_stats;
        double mx = st[0] * Ninv, my = st[1] * Ninv;
        double vxx = st[2] * Ninv - mx * mx;
        double vyy = st[3] * Ninv - my * my;
        double cxy = st[4] * Ninv - mx * my;
        float w0 = seW1[2 * tid], w1 = seW1[2 * tid + 1];
        float mu = (float)(w0 * mx + w1 * my) + seb1[tid];
        float var = (float)((double)w0 * w0 * vxx + (double)w1 * w1 * vyy +
                            2.0 * (double)w0 * w1 * cxy);
        float sc = seg_[tid] * rsqrtf(var + EPSBN);
        float ix = 1.f / scalar_f(pxm), iy = 1.f / scalar_f(pym);
        fold[tid]      = w0 * sc * ix;
        fold[16 + tid] = w1 * sc * iy;
        fold[32 + tid] = (seb1[tid] - mu) * sc + seb_[tid];
    }
    __syncthreads();

    int wm = wid & 1, wn = wid >> 1;
    int j0 = wn * 8 + (lane & 3) * 2;
    float bj[4][2];
#pragma unroll
    for (int g = 0; g < 4; g++) { bj[g][0] = bs[g * 64 + j0]; bj[g][1] = bs[g * 64 + j0 + 1]; }

    u32 bh[3][4][2];
    {
        u32 nrow = (u32)(wn * 8 + (lane & 7));
        u32 gsel = (u32)(((lane >> 4) & 1) * 64);
        u32 ksel = (u32)(((lane >> 3) & 1) * 16);
#pragma unroll
        for (int kt = 0; kt < 3; kt++) {
#pragma unroll
            for (int p = 0; p < 2; p++) {
                u32 r4[4];
                ldsm4(r4, smb + O_WH +
                      ((u32)(p * 2) * 64 + gsel + nrow) * (WSTR * 2) + ksel + (u32)(kt * 32));
                bh[kt][2 * p][0] = r4[0]; bh[kt][2 * p][1] = r4[1];
                bh[kt][2 * p + 1][0] = r4[2]; bh[kt][2 * p + 1][1] = r4[3];
            }
        }
    }

    u32 aRowOff = (u32)((wm * 32 + (lane & 15)) * (WSTR * 2));
    u32 aColSel = (u32)(((lane >> 4) & 1) * 16);
    u32 bRow = (u32)(wn * 8 + (lane & 7));
    u32 bGsel = (u32)(((lane >> 4) & 1) * 64);
    u32 bKsel = (u32)(((lane >> 3) & 1) * 16);
    int srow = tid >> 3, seg8 = tid & 7, j2 = seg8 * 2;
    float fa0 = fold[j2], fb0 = fold[16 + j2], fc0 = fold[32 + j2];
    float fa1 = fold[j2 + 1], fb1 = fold[16 + j2 + 1], fc1 = fold[32 + j2 + 1];

    {   // prologue: stage feats t0 of first tile into buf0
        int r = blockIdx.x * 64 + srow;
        float2 xy0 = *(const float2*)(obs + 2 * (size_t)r);
        float f0 = fmaxf(fa0 * xy0.x + fb0 * xy0.y + fc0, 0.f);
        float f1 = fmaxf(fa1 * xy0.x + fb1 * xy0.y + fc1, 0.f);
        int off = srow * (WSTR * 2) + j2 * 2;
        *(u32*)(sm + O_AB0 + off) = pack_bf16_hi(f0, f1);
        *(u32*)(sm + O_AB0 + 11264 + off) = pack_bf16_lo(f0, f1);
    }

    for (int tile = blockIdx.x; tile < nTiles; tile += gridDim.x) {
        int row0 = tile * 64;
        int nxt = tile + gridDim.x;
        float creg[2][2][2];

        for (int t = 0; t < T_OBS; t++) {
            u32 ahb = smb + O_AB0 + (u32)((t & 1) * 22528);
            u32 alb = ahb + 11264;
            float2 nxy = make_float2(0.f, 0.f);
            if (t < T_OBS - 1) {
                nxy = *(const float2*)(obs + (size_t)(t + 1) * B * 2 + 2 * (size_t)(row0 + srow));
            } else if (nxt < nTiles) {
                nxy = *(const float2*)(obs + 2 * (size_t)(nxt * 64 + srow));
            }
            __syncthreads();

            float acc[2][4][4];
#pragma unroll
            for (int mt = 0; mt < 2; mt++)
#pragma unroll
                for (int g = 0; g < 4; g++)
#pragma unroll
                    for (int e = 0; e < 4; e++) acc[mt][g][e] = 0.f;
            int nkt = t ? 5 : 1;
#pragma unroll
            for (int kt = 0; kt < 5; kt++) {
                if (kt >= nkt) break;
                u32 kOff = (u32)(kt * 32);
                u32 ah0[4], ah1[4], al0[4], al1[4];
                u32 aAddr = ahb + aRowOff + aColSel + kOff;
                ldsm4(ah0, aAddr);
                ldsm4(ah1, aAddr + 16 * (WSTR * 2));
                u32 aAddrL = alb + aRowOff + aColSel + kOff;
                ldsm4(al0, aAddrL);
                ldsm4(al1, aAddrL + 16 * (WSTR * 2));
                u32 bl[4][2];
#pragma unroll
                for (int p = 0; p < 2; p++) {
                    u32 r4[4];
                    ldsm4(r4, smb + O_WL +
                          ((u32)(p * 2) * 64 + bGsel + bRow) * (WSTR * 2) + bKsel + kOff);
                    bl[2 * p][0] = r4[0]; bl[2 * p][1] = r4[1];
                    bl[2 * p + 1][0] = r4[2]; bl[2 * p + 1][1] = r4[3];
                }
                if (kt < 3) {
#pragma unroll
                    for (int g = 0; g < 4; g++) {
                        mma16816(acc[0][g], ah0, bh[kt][g]);
                        mma16816(acc[1][g], ah1, bh[kt][g]);
                        mma16816(acc[0][g], al0, bh[kt][g]);
                        mma16816(acc[1][g], al1, bh[kt][g]);
                        mma16816(acc[0][g], ah0, bl[g]);
                        mma16816(acc[1][g], ah1, bl[g]);
                    }
                } else {
                    u32 bhd[4][2];
#pragma unroll
                    for (int p = 0; p < 2; p++) {
                        u32 r4[4];
                        ldsm4(r4, smb + O_WH +
                              ((u32)(p * 2) * 64 + bGsel + bRow) * (WSTR * 2) + bKsel + kOff);
                        bhd[2 * p][0] = r4[0]; bhd[2 * p][1] = r4[1];
                        bhd[2 * p + 1][0] = r4[2]; bhd[2 * p + 1][1] = r4[3];
                    }
#pragma unroll
                    for (int g = 0; g < 4; g++) {
                        mma16816(acc[0][g], ah0, bhd[g]);
                        mma16816(acc[1][g], ah1, bhd[g]);
                        mma16816(acc[0][g], al0, bhd[g]);
                        mma16816(acc[1][g], al1, bhd[g]);
                        mma16816(acc[0][g], ah0, bl[g]);
                        mma16816(acc[1][g], ah1, bl[g]);
                    }
                }
            }

            float hn[2][2][2];
#pragma unroll
            for (int mt = 0; mt < 2; mt++)
#pragma unroll
                for (int rr = 0; rr < 2; rr++)
#pragma unroll
                    for (int cc = 0; cc < 2; cc++) {
                        int e = rr * 2 + cc;
                        float iv = acc[mt][0][e] + bj[0][cc];
                        float fv = acc[mt][1][e] + bj[1][cc];
                        float gv = acc[mt][2][e] + bj[2][cc];
                        float ov = acc[mt][3][e] + bj[3][cc];
                        float cold = t ? creg[mt][rr][cc] : 0.f;
                        lstm_cell(iv, fv, gv, ov, cold, creg[mt][rr][cc], hn[mt][rr][cc]);
                    }

            if (t < T_OBS - 1) {
                u32 ahn = smb + O_AB0 + (u32)(((t + 1) & 1) * 22528);
                u32 aln = ahn + 11264;
#pragma unroll
                for (int mt = 0; mt < 2; mt++)
#pragma unroll
                    for (int rr = 0; rr < 2; rr++) {
                        int lrow = wm * 32 + mt * 16 + rr * 8 + (lane >> 2);
                        int off = lrow * (WSTR * 2) + (16 + j0) * 2;
                        *(u32*)(ahn - smb + sm + off) = pack_bf16_hi(hn[mt][rr][0], hn[mt][rr][1]);
                        *(u32*)(aln - smb + sm + off) = pack_bf16_lo(hn[mt][rr][0], hn[mt][rr][1]);
                    }
                float f0 = fmaxf(fa0 * nxy.x + fb0 * nxy.y + fc0, 0.f);
                float f1 = fmaxf(fa1 * nxy.x + fb1 * nxy.y + fc1, 0.f);
                int off = srow * (WSTR * 2) + j2 * 2;
                *(u32*)(ahn - smb + sm + off) = pack_bf16_hi(f0, f1);
                *(u32*)(aln - smb + sm + off) = pack_bf16_lo(f0, f1);
            } else {
#pragma unroll
                for (int mt = 0; mt < 2; mt++)
#pragma unroll
                    for (int rr = 0; rr < 2; rr++) {
                        int r = row0 + wm * 32 + mt * 16 + rr * 8 + (lane >> 2);
                        *(float2*)(g_h + (size_t)r * 64 + j0) =
                            make_float2(hn[mt][rr][0], hn[mt][rr][1]);
                        *(float2*)(g_c + (size_t)r * 64 + j0) =
                            make_float2(creg[mt][rr][0], creg[mt][rr][1]);
                    }
                if (nxt < nTiles) {
                    float f0 = fmaxf(fa0 * nxy.x + fb0 * nxy.y + fc0, 0.f);
                    float f1 = fmaxf(fa1 * nxy.x + fb1 * nxy.y + fc1, 0.f);
                    int off = srow * (WSTR * 2) + j2 * 2;
                    *(u32*)(sm + O_AB0 + off) = pack_bf16_hi(f0, f1);
                    *(u32*)(sm + O_AB0 + 11264 + off) = pack_bf16_lo(f0, f1);
                }
            }
        }
    }
}

// ======================= decode LSTM step (double-buffered A) ================
__global__ void __launch_bounds__(512, 1)
k_dec(int B, int nTiles,
      const float* __restrict__ seW1, const float* __restrict__ seb1,
      const float* __restrict__ seg_, const float* __restrict__ seb_, float Ninv) {
    extern __shared__ char sm[];
    float* bs = (float*)(sm + O_BIAS);
    float* fold = (float*)(sm + O_FOLD);
    u32 smb = smem_u32(sm);
    int tid = threadIdx.x, wid = tid >> 5, lane = tid & 31;

    {
        const float4* s1 = (const float4*)g_Wh;
        const float4* s2 = (const float4*)g_Wl;
        float4* d1 = (float4*)(sm + O_WH);
        float4* d2 = (float4*)(sm + O_WL);
        for (int i = tid; i < 2816; i += 512) { d1[i] = s1[i]; d2[i] = s2[i]; }
    }
    if (tid < 256) bs[tid] = g_bias[tid];
    if (blockIdx.x == 0 && tid < 32) g_hp_stats[tid] = 0.0;
    if (tid < 16) {   // decode BN fold from se stats (inputs already in [0,1])
        const double* st = g_se_stats;
        double mx = st[0] * Ninv, my = st[1] * Ninv;
        double vxx = st[2] * Ninv - mx * mx;
        double vyy = st[3] * Ninv - my * my;
        double cxy = st[4] * Ninv - mx * my;
        float w0 = seW1[2 * tid], w1 = seW1[2 * tid + 1];
        float mu = (float)(w0 * mx + w1 * my) + seb1[tid];
        float var = (float)((double)w0 * w0 * vxx + (double)w1 * w1 * vyy +
                            2.0 * (double)w0 * w1 * cxy);
        float sc = seg_[tid] * rsqrtf(var + EPSBN);
        fold[tid]      = w0 * sc;
        fold[16 + tid] = w1 * sc;
        fold[32 + tid] = (seb1[tid] - mu) * sc + seb_[tid];
    }
    __syncthreads();

    int wm = wid & 1, wn = wid >> 1;
    int j0 = wn * 8 + (lane & 3) * 2;
    float bj[4][2];
#pragma unroll
    for (int g = 0; g < 4; g++) { bj[g][0] = bs[g * 64 + j0]; bj[g][1] = bs[g * 64 + j0 + 1]; }

    u32 bh[3][4][2];
    {
        u32 nrow = (u32)(wn * 8 + (lane & 7));
        u32 gsel = (u32)(((lane >> 4) & 1) * 64);
        u32 ksel = (u32)(((lane >> 3) & 1) * 16);
#pragma unroll
        for (int kt = 0; kt < 3; kt++) {
#pragma unroll
            for (int p = 0; p < 2; p++) {
                u32 r4[4];
                ldsm4(r4, smb + O_WH +
                      ((u32)(p * 2) * 64 + gsel + nrow) * (WSTR * 2) + ksel + (u32)(kt * 32));
                bh[kt][2 * p][0] = r4[0]; bh[kt][2 * p][1] = r4[1];
                bh[kt][2 * p + 1][0] = r4[2]; bh[kt][2 * p + 1][1] = r4[3];
            }
        }
    }

    u32 aRowOff = (u32)((wm * 32 + (lane & 15)) * (WSTR * 2));
    u32 aColSel = (u32)(((lane >> 4) & 1) * 16);
    u32 bRow = (u32)(wn * 8 + (lane & 7));
    u32 bGsel = (u32)(((lane >> 4) & 1) * 64);
    u32 bKsel = (u32)(((lane >> 3) & 1) * 16);
    int srow = tid >> 3, seg8 = tid & 7, j2 = seg8 * 2;
    float fa0 = fold[j2], fb0 = fold[16 + j2], fc0 = fold[32 + j2];
    float fa1 = fold[j2 + 1], fb1 = fold[16 + j2 + 1], fc1 = fold[32 + j2 + 1];

    {   // prologue: stage first tile into buf0
        int r = blockIdx.x * 64 + srow;
        const float4* hp = (const float4*)(g_h + (size_t)r * 64 + seg8 * 8);
        float4 h0 = hp[0], h1 = hp[1];
        float2 lp = *(const float2*)(g_last + 2 * (size_t)r);
        uint4 hi, lo;
        hi.x = pack_bf16_hi(h0.x, h0.y); lo.x = pack_bf16_lo(h0.x, h0.y);
        hi.y = pack_bf16_hi(h0.z, h0.w); lo.y = pack_bf16_lo(h0.z, h0.w);
        hi.z = pack_bf16_hi(h1.x, h1.y); lo.z = pack_bf16_lo(h1.x, h1.y);
        hi.w = pack_bf16_hi(h1.z, h1.w); lo.w = pack_bf16_lo(h1.z, h1.w);
        int off = srow * (WSTR * 2) + 32 + seg8 * 16;
        *(uint4*)(sm + O_AB0 + off) = hi;
        *(uint4*)(sm + O_AB0 + 11264 + off) = lo;
        float f0 = fmaxf(fa0 * lp.x + fb0 * lp.y + fc0, 0.f);
        float f1 = fmaxf(fa1 * lp.x + fb1 * lp.y + fc1, 0.f);
        int offf = srow * (WSTR * 2) + j2 * 2;
        *(u32*)(sm + O_AB0 + offf) = pack_bf16_hi(f0, f1);
        *(u32*)(sm + O_AB0 + 11264 + offf) = pack_bf16_lo(f0, f1);
    }

    int pbuf = 0;
    for (int tile = blockIdx.x; tile < nTiles; tile += gridDim.x) {
        int row0 = tile * 64;
        int nxt = tile + gridDim.x;
        u32 ahb = smb + O_AB0 + (u32)(pbuf * 22528);
        u32 alb = ahb + 11264;

        float4 nh0, nh1; float2 nlp;
        bool hasNext = (nxt < nTiles);
        if (hasNext) {
            int r = nxt * 64 + srow;
            const float4* hp = (const float4*)(g_h + (size_t)r * 64 + seg8 * 8);
            nh0 = hp[0]; nh1 = hp[1];
            nlp = *(const float2*)(g_last + 2 * (size_t)r);
        }
        __syncthreads();

        float acc[2][4][4];
#pragma unroll
        for (int mt = 0; mt < 2; mt++)
#pragma unroll
            for (int g = 0; g < 4; g++)
#pragma unroll
                for (int e = 0; e < 4; e++) acc[mt][g][e] = 0.f;

#pragma unroll
        for (int kt = 0; kt < 5; kt++) {
            u32 kOff = (u32)(kt * 32);
            u32 ah0[4], ah1[4], al0[4], al1[4];
            u32 aAddr = ahb + aRowOff + aColSel + kOff;
            ldsm4(ah0, aAddr);
            ldsm4(ah1, aAddr + 16 * (WSTR * 2));
            u32 aAddrL = alb + aRowOff + aColSel + kOff;
            ldsm4(al0, aAddrL);
            ldsm4(al1, aAddrL + 16 * (WSTR * 2));
            u32 bl[4][2];
#pragma unroll
            for (int p = 0; p < 2; p++) {
                u32 r4[4];
                ldsm4(r4, smb + O_WL +
                      ((u32)(p * 2) * 64 + bGsel + bRow) * (WSTR * 2) + bKsel + kOff);
                bl[2 * p][0] = r4[0]; bl[2 * p][1] = r4[1];
                bl[2 * p + 1][0] = r4[2]; bl[2 * p + 1][1] = r4[3];
            }
            if (kt < 3) {
#pragma unroll
                for (int g = 0; g < 4; g++) {
                    mma16816(acc[0][g], ah0, bh[kt][g]);
                    mma16816(acc[1][g], ah1, bh[kt][g]);
                    mma16816(acc[0][g], al0, bh[kt][g]);
                    mma16816(acc[1][g], al1, bh[kt][g]);
                    mma16816(acc[0][g], ah0, bl[g]);
                    mma16816(acc[1][g], ah1, bl[g]);
                }
            } else {
                u32 bhd[4][2];
#pragma unroll
                for (int p = 0; p < 2; p++) {
                    u32 r4[4];
                    ldsm4(r4, smb + O_WH +
                          ((u32)(p * 2) * 64 + bGsel + bRow) * (WSTR * 2) + bKsel + kOff);
                    bhd[2 * p][0] = r4[0]; bhd[2 * p][1] = r4[1];
                    bhd[2 * p + 1][0] = r4[2]; bhd[2 * p + 1][1] = r4[3];
                }
#pragma unroll
                for (int g = 0; g < 4; g++) {
                    mma16816(acc[0][g], ah0, bhd[g]);
                    mma16816(acc[1][g], ah1, bhd[g]);
                    mma16816(acc[0][g], al0, bhd[g]);
                    mma16816(acc[1][g], al1, bhd[g]);
                    mma16816(acc[0][g], ah0, bl[g]);
                    mma16816(acc[1][g], ah1, bl[g]);
                }
            }
        }

        // epilogue: pointwise -> global h, c
#pragma unroll
        for (int mt = 0; mt < 2; mt++)
#pragma unroll
            for (int rr = 0; rr < 2; rr++) {
                int rw = row0 + wm * 32 + mt * 16 + rr * 8 + (lane >> 2);
                float2 c2 = *(float2*)(g_c + (size_t)rw * 64 + j0);
                float cn[2], hn[2];
#pragma unroll
                for (int cc = 0; cc < 2; cc++) {
                    int e = rr * 2 + cc;
                    float iv = acc[mt][0][e] + bj[0][cc];
                    float fv = acc[mt][1][e] + bj[1][cc];
                    float gv = acc[mt][2][e] + bj[2][cc];
                    float ov = acc[mt][3][e] + bj[3][cc];
                    lstm_cell(iv, fv, gv, ov, cc ? c2.y : c2.x, cn[cc], hn[cc]);
                }
                *(float2*)(g_c + (size_t)rw * 64 + j0) = make_float2(cn[0], cn[1]);
                *(float2*)(g_h + (size_t)rw * 64 + j0) = make_float2(hn[0], hn[1]);
            }

        // stage next tile into the other buffer
        if (hasNext) {
            u32 off1 = (u32)(O_AB0 + (pbuf ^ 1) * 22528);
            uint4 hi, lo;
            hi.x = pack_bf16_hi(nh0.x, nh0.y); lo.x = pack_bf16_lo(nh0.x, nh0.y);
            hi.y = pack_bf16_hi(nh0.z, nh0.w); lo.y = pack_bf16_lo(nh0.z, nh0.w);
            hi.z = pack_bf16_hi(nh1.x, nh1.y); lo.z = pack_bf16_lo(nh1.x, nh1.y);
            hi.w = pack_bf16_hi(nh1.z, nh1.w); lo.w = pack_bf16_lo(nh1.z, nh1.w);
            int off = srow * (WSTR * 2) + 32 + seg8 * 16;
            *(uint4*)(sm + off1 + off) = hi;
            *(uint4*)(sm + off1 + 11264 + off) = lo;
            float f0 = fmaxf(fa0 * nlp.x + fb0 * nlp.y + fc0, 0.f);
            float f1 = fmaxf(fa1 * nlp.x + fb1 * nlp.y + fc1, 0.f);
            int offf = srow * (WSTR * 2) + j2 * 2;
            *(u32*)(sm + off1 + offf) = pack_bf16_hi(f0, f1);
            *(u32*)(sm + off1 + 11264 + offf) = pack_bf16_lo(f0, f1);
        }
        pbuf ^= 1;
    }
}

// ---------------- hidden2pos proj + stats (coalesced, 8 threads/row) --------
__global__ void k_hp(const float* __restrict__ hpW1, const float* __restrict__ hpb1, int B) {
    __shared__ float Ws[1024];
    __shared__ float b1s[16];
    __shared__ float red[8][32];
    for (int i = threadIdx.x; i < 1024; i += 256) Ws[i] = hpW1[i];
    if (threadIdx.x < 16) b1s[threadIdx.x] = hpb1[threadIdx.x];
    if (blockIdx.x == 0 && threadIdx.x < 5) g_se_stats[threadIdx.x] = 0.0;
    __syncthreads();
    int tid = threadIdx.x;
    int t8 = tid & 7;           // k-octet within row
    int rowInBlk = tid >> 3;    // 0..31
    int j2 = t8 * 2;
    float sv0 = 0.f, sv1 = 0.f, qv0 = 0.f, qv1 = 0.f;
    int nGroups = B / 32;
    for (int gi = blockIdx.x; gi < nGroups; gi += gridDim.x) {
        int row = gi * 32 + rowInBlk;
        const float4* hp4 = (const float4*)(g_h + (size_t)row * 64 + t8 * 8);
        float4 a = hp4[0], b = hp4[1];
        float z[16];
#pragma unroll
        for (int j = 0; j < 16; j++) {
            const float4* w = (const float4*)&Ws[j * 64 + t8 * 8];
            float4 w0 = w[0], w1 = w[1];
            z[j] = a.x * w0.x + a.y * w0.y + a.z * w0.z + a.w * w0.w
                 + b.x * w1.x + b.y * w1.y + b.z * w1.z + b.w * w1.w;
        }
#pragma unroll
        for (int j = 0; j < 16; j++) {
            z[j] += __shfl_xor_sync(0xffffffffu, z[j], 1);
            z[j] += __shfl_xor_sync(0xffffffffu, z[j], 2);
            z[j] += __shfl_xor_sync(0xffffffffu, z[j], 4);
            z[j] += b1s[j];
        }
        if (t8 < 4) {
            ((float4*)(g_z + (size_t)row * 16))[t8] =
                make_float4(z[4 * t8], z[4 * t8 + 1], z[4 * t8 + 2], z[4 * t8 + 3]);
        }
        sv0 += z[j2]; sv1 += z[j2 + 1];
        qv0 += z[j2] * z[j2]; qv1 += z[j2 + 1] * z[j2 + 1];
    }
    // reduce the 4 rows within each warp (lanes xor 8, 16 share t8)
    sv0 += __shfl_xor_sync(0xffffffffu, sv0, 8);  sv0 += __shfl_xor_sync(0xffffffffu, sv0, 16);
    sv1 += __shfl_xor_sync(0xffffffffu, sv1, 8);  sv1 += __shfl_xor_sync(0xffffffffu, sv1, 16);
    qv0 += __shfl_xor_sync(0xffffffffu, qv0, 8);  qv0 += __shfl_xor_sync(0xffffffffu, qv0, 16);
    qv1 += __shfl_xor_sync(0xffffffffu, qv1, 8);  qv1 += __shfl_xor_sync(0xffffffffu, qv1, 16);
    int wid = tid >> 5, lane = tid & 31;
    if (lane < 8) {
        red[wid][j2] = sv0; red[wid][j2 + 1] = sv1;
        red[wid][16 + j2] = qv0; red[wid][17 + j2] = qv1;
    }
    __syncthreads();
    if (tid < 32) {
        float tot = 0.f;
#pragma unroll
        for (int w = 0; w < 8; w++) tot += red[w][tid];
        atomicAdd(&g_hp_stats[tid], (double)tot);
    }
}

// ---------------- positions: BN(inline)+relu+W2, sigmoid, out, se moments ---
__global__ void k_pos(const float* __restrict__ hpW2, const float* __restrict__ hpb2,
                      const float* __restrict__ gamma, const float* __restrict__ beta,
                      float* __restrict__ out, const void* pxm, const void* pym,
                      float Binv, int B) {
    __shared__ float sc[16], sh[16];
    __shared__ float red[8][5];
    if (threadIdx.x < 16) {
        int j = threadIdx.x;
        double mu = g_hp_stats[j] * Binv;
        double var = g_hp_stats[16 + j] * Binv - mu * mu;
        float s = gamma[j] * rsqrtf((float)var + EPSBN);
        sc[j] = s;
        sh[j] = beta[j] - (float)mu * s;
    }
    __syncthreads();
    int row = blockIdx.x * 256 + threadIdx.x;
    const float4* zr = (const float4*)(g_z + (size_t)row * 16);
    float px = hpb2[0], py = hpb2[1];
#pragma unroll
    for (int q4 = 0; q4 < 4; q4++) {
        float4 v = zr[q4];
        float vv[4] = {v.x, v.y, v.z, v.w};
#pragma unroll
        for (int e = 0; e < 4; e++) {
            int j = q4 * 4 + e;
            float t = fmaxf(vv[e] * sc[j] + sh[j], 0.f);
            px += t * hpW2[j];
            py += t * hpW2[16 + j];
        }
    }
    float lx = fast_sig(px + g_last[2 * row]);
    float ly = fast_sig(py + g_last[2 * row + 1]);
    g_last[2 * row] = lx;
    g_last[2 * row + 1] = ly;
    out[2 * row]     = lx * scalar_f(pxm);
    out[2 * row + 1] = ly * scalar_f(pym);
    float s[5] = {lx, ly, lx * lx, ly * ly, lx * ly};
    int wid = threadIdx.x >> 5, lane = threadIdx.x & 31;
#pragma unroll
    for (int k = 0; k < 5; k++) s[k] = wred(s[k]);
    if (lane == 0) {
#pragma unroll
        for (int k = 0; k < 5; k++) red[wid][k] = s[k];
    }
    __syncthreads();
    if (wid == 0 && lane < 5) {
        float t = 0.f;
#pragma unroll
        for (int w = 0; w < 8; w++) t += red[w][lane];
        atomicAdd(&g_se_stats[lane], (double)t);
    }
}

// ---------------- launch ------------------------------------------------------
extern "C" void kernel_launch(void* const* d_in, const int* in_sizes, int n_in,
                              void* d_out, int out_size) {
    const float* obs  = (const float*)d_in[0];
    const float* seW1 = (const float*)d_in[1];
    const float* seb1 = (const float*)d_in[2];
    const float* seg  = (const float*)d_in[3];
    const float* seb  = (const float*)d_in[4];
    const float* seW2 = (const float*)d_in[5];
    const float* seb2 = (const float*)d_in[6];
    const float* hpW1 = (const float*)d_in[7];
    const float* hpb1 = (const float*)d_in[8];
    const float* hpg  = (const float*)d_in[9];
    const float* hpb  = (const float*)d_in[10];
    const float* hpW2 = (const float*)d_in[11];
    const float* hpb2 = (const float*)d_in[12];
    const float* Wih  = (const float*)d_in[13];
    const float* Whh  = (const float*)d_in[14];
    const float* bih  = (const float*)d_in[15];
    const float* bhh  = (const float*)d_in[16];
    const void*  pxm  = d_in[17];
    const void*  pym  = d_in[18];

    int B = in_sizes[0] / (T_OBS * 2);
    int TB = T_OBS * B;
    int predLen = out_size / (2 * B);
    float* out = (float*)d_out;
    int nTiles = B / 64;

    cudaFuncSetAttribute(k_enc, cudaFuncAttributeMaxDynamicSharedMemorySize, LSTM_SMEM);
    cudaFuncSetAttribute(k_dec, cudaFuncAttributeMaxDynamicSharedMemorySize, LSTM_SMEM);

    k_prep<<<1, 256>>>(Wih, Whh, bih, bhh, seW2, seb2);
    k_moments<<<512, 256>>>(obs, pxm, pym, TB, B);
    k_enc<<<148, 512, LSTM_SMEM>>>(obs, B, nTiles, seW1, seb1, seg, seb,
                                   pxm, pym, 1.0f / (float)TB);

    for (int s = 0; s < predLen; s++) {
        k_hp<<<512, 256>>>(hpW1, hpb1, B);
        k_pos<<<B / 256, 256>>>(hpW2, hpb2, hpg, hpb, out + (size_t)s * B * 2,
                                pxm, pym, 1.0f / (float)B, B);
        if (s + 1 < predLen)
            k_dec<<<148, 512, LSTM_SMEM>>>(B, nTiles, seW1, seb1, seg, seb,
                                           1.0f / (float)B);
    }
}

// round 12
// speedup vs baseline: 1.0696x; 1.0696x over previous
#include <cuda_runtime.h>
#include <cuda_bf16.h>
#include <math.h>

#define T_OBS 8
#define EPSBN 1e-5f

typedef unsigned int u32;
typedef unsigned long long u64;

#define MAXB 131072
#define WSTR 88   // padded k-stride (bf16): 176B rows, conflict-free ldmatrix

// ---------------- static device scratch ------------------------------------
__device__ float  g_h[MAXB * 64];
__device__ float  g_c[MAXB * 64];
__device__ float  g_z[MAXB * 16];
__device__ float  g_last[MAXB * 2];
__device__ __align__(16) __nv_bfloat16 g_Wh[256 * WSTR];
__device__ __align__(16) __nv_bfloat16 g_Wl[256 * WSTR];
__device__ float  g_bias[256];
__device__ double g_enc_stats[5];
__device__ double g_se_stats[5];
__device__ double g_hp_stats[32];

// ---------------- helpers ----------------------------------------------------
__device__ __forceinline__ float scalar_f(const void* p) {
    int iv = *(const int*)p;
    float fv = __int_as_float(iv);
    if (fv >= 1e-3f && fv <= 1e7f) return fv;
    return (float)iv;
}
__device__ __forceinline__ float fast_sig(float x) {
    float t; asm("ex2.approx.f32 %0, %1;" : "=f"(t) : "f"(-1.4426950408889634f * x));
    float r; asm("rcp.approx.f32 %0, %1;" : "=f"(r) : "f"(1.0f + t));
    return r;
}
// fused LSTM pointwise: 8 MUFU per cell
__device__ __forceinline__ void lstm_cell(float iv, float fv, float gv, float ov,
                                          float cold, float& cnew, float& hnew) {
    gv = fminf(fmaxf(gv, -30.f), 30.f);
    float tf; asm("ex2.approx.f32 %0, %1;" : "=f"(tf) : "f"(-1.4426950408889634f * fv));
    float sf; asm("rcp.approx.f32 %0, %1;" : "=f"(sf) : "f"(1.0f + tf));
    float ei; asm("ex2.approx.f32 %0, %1;" : "=f"(ei) : "f"(-1.4426950408889634f * iv));
    float eg; asm("ex2.approx.f32 %0, %1;" : "=f"(eg) : "f"(2.8853900817779268f * gv));
    float dig = (1.0f + ei) * (eg + 1.0f);
    float rig; asm("rcp.approx.f32 %0, %1;" : "=f"(rig) : "f"(dig));
    float c2 = sf * cold + (eg - 1.0f) * rig;
    cnew = c2;
    float eo; asm("ex2.approx.f32 %0, %1;" : "=f"(eo) : "f"(-1.4426950408889634f * ov));
    float ec; asm("ex2.approx.f32 %0, %1;" : "=f"(ec) : "f"(2.8853900817779268f * c2));
    float doc = (1.0f + eo) * (ec + 1.0f);
    float roc; asm("rcp.approx.f32 %0, %1;" : "=f"(roc) : "f"(doc));
    hnew = (ec - 1.0f) * roc;
}
__device__ __forceinline__ float wred(float v) {
#pragma unroll
    for (int o = 16; o > 0; o >>= 1) v += __shfl_down_sync(0xffffffffu, v, o);
    return v;
}
__device__ __forceinline__ u32 smem_u32(const void* p) {
    u32 a;
    asm("{ .reg .u64 t; cvta.to.shared.u64 t, %1; cvt.u32.u64 %0, t; }" : "=r"(a) : "l"(p));
    return a;
}
__device__ __forceinline__ void ldsm4(u32* r, u32 addr) {
    asm volatile("ldmatrix.sync.aligned.m8n8.x4.shared.b16 {%0,%1,%2,%3}, [%4];"
        : "=r"(r[0]), "=r"(r[1]), "=r"(r[2]), "=r"(r[3]) : "r"(addr));
}
__device__ __forceinline__ void mma16816(float* d, const u32* a, const u32* b) {
    asm volatile(
        "mma.sync.aligned.m16n8k16.row.col.f32.bf16.bf16.f32 "
        "{%0,%1,%2,%3},{%4,%5,%6,%7},{%8,%9},{%0,%1,%2,%3};"
        : "+f"(d[0]), "+f"(d[1]), "+f"(d[2]), "+f"(d[3])
        : "r"(a[0]), "r"(a[1]), "r"(a[2]), "r"(a[3]), "r"(b[0]), "r"(b[1]));
}
__device__ __forceinline__ u32 pack_bf16_hi(float a0, float a1) {
    __nv_bfloat16 h0 = __float2bfloat16(a0), h1 = __float2bfloat16(a1);
    return ((u32)__bfloat16_as_ushort(h1) << 16) | __bfloat16_as_ushort(h0);
}
__device__ __forceinline__ u32 pack_bf16_lo(float a0, float a1) {
    __nv_bfloat16 h0 = __float2bfloat16(a0), h1 = __float2bfloat16(a1);
    __nv_bfloat16 l0 = __float2bfloat16(a0 - __bfloat162float(h0));
    __nv_bfloat16 l1 = __float2bfloat16(a1 - __bfloat162float(h1));
    return ((u32)__bfloat16_as_ushort(l1) << 16) | __bfloat16_as_ushort(l0);
}

// ---------------- smem layout (double-buffered A) ----------------------------
#define O_WH   0                    // 45056
#define O_WL   45056                // 45056
#define O_AB0  90112                // AH0; AL0=+11264; AH1=+22528; AL1=+33792
#define O_BIAS 135168               // 1024
#define O_FOLD 136192               // 192
#define LSTM_SMEM 136448

// ---------------- prep: fold se_W2/se_b2 into Wih; bf16-split ---------------
__global__ void k_prep(const float* __restrict__ Wih, const float* __restrict__ Whh,
                       const float* __restrict__ bih, const float* __restrict__ bhh,
                       const float* __restrict__ seW2, const float* __restrict__ seb2) {
    int gc = threadIdx.x;
    if (gc < 5) g_enc_stats[gc] = 0.0;
    float wr[64];
#pragma unroll 8
    for (int m = 0; m < 64; m++) wr[m] = Wih[gc * 64 + m];
    float be = bih[gc] + bhh[gc];
#pragma unroll 8
    for (int m = 0; m < 64; m++) be += wr[m] * seb2[m];
    g_bias[gc] = be;
    for (int k = 0; k < WSTR; k++) {
        float w = 0.f;
        if (k < 16) {
#pragma unroll 8
            for (int m = 0; m < 64; m++) w += wr[m] * seW2[m * 16 + k];
        } else if (k < 80) {
            w = Whh[gc * 64 + (k - 16)];
        }
        __nv_bfloat16 hi = __float2bfloat16(w);
        __nv_bfloat16 lo = __float2bfloat16(w - __bfloat162float(hi));
        g_Wh[gc * WSTR + k] = hi;
        g_Wl[gc * WSTR + k] = lo;
    }
}

// ---------------- moments of normalized obs + init last_pos -----------------
__global__ void k_moments(const float* __restrict__ obs, const void* pxm, const void* pym,
                          int TB, int B) {
    __shared__ float red[8][5];
    float invx = 1.0f / scalar_f(pxm), invy = 1.0f / scalar_f(pym);
    int idx = blockIdx.x * blockDim.x + threadIdx.x;
    int stride = gridDim.x * blockDim.x;
    float s[5] = {0, 0, 0, 0, 0};
    for (int i = idx; i < TB; i += stride) {
        float x = obs[2 * i] * invx, y = obs[2 * i + 1] * invy;
        s[0] += x; s[1] += y; s[2] += x * x; s[3] += y * y; s[4] += x * y;
    }
    int wid = threadIdx.x >> 5, lane = threadIdx.x & 31;
#pragma unroll
    for (int k = 0; k < 5; k++) s[k] = wred(s[k]);
    if (lane == 0) {
#pragma unroll
        for (int k = 0; k < 5; k++) red[wid][k] = s[k];
    }
    __syncthreads();
    if (wid == 0 && lane < 5) {
        float t = 0.f;
#pragma unroll
        for (int w = 0; w < 8; w++) t += red[w][lane];
        atomicAdd(&g_enc_stats[lane], (double)t);
    }
    int off = TB - B;
    for (int i = idx; i < B; i += stride) {
        g_last[2 * i]     = obs[2 * (off + i)]     * invx;
        g_last[2 * i + 1] = obs[2 * (off + i) + 1] * invy;
    }
}

// ======================= fused 8-step encoder ================================
__global__ void __launch_bounds__(512, 1)
k_enc(const float* __restrict__ obs, int B, int nTiles,
      const float* __restrict__ seW1, const float* __restrict__ seb1,
      const float* __restrict__ seg_, const float* __restrict__ seb_,
      const void* pxm, const void* pym, float Ninv) {
    extern __shared__ char sm[];
    float* bs = (float*)(sm + O_BIAS);
    float* fold = (float*)(sm + O_FOLD);
    u32 smb = smem_u32(sm);
    int tid = threadIdx.x, wid = tid >> 5, lane = tid & 31;

    {
        const float4* s1 = (const float4*)g_Wh;
        const float4* s2 = (const float4*)g_Wl;
        float4* d1 = (float4*)(sm + O_WH);
        float4* d2 = (float4*)(sm + O_WL);
        for (int i = tid; i < 2816; i += 512) { d1[i] = s1[i]; d2[i] = s2[i]; }
    }
    if (tid < 256) bs[tid] = g_bias[tid];
    if (blockIdx.x == 0 && tid < 32) g_hp_stats[tid] = 0.0;
    if (tid < 16) {   // encode BN fold (analytic, from 5 moments)
        const double* st = g_enc_stats;
        double mx = st[0] * Ninv, my = st[1] * Ninv;
        double vxx = st[2] * Ninv - mx * mx;
        double vyy = st[3] * Ninv - my * my;
        double cxy = st[4] * Ninv - mx * my;
        float w0 = seW1[2 * tid], w1 = seW1[2 * tid + 1];
        float mu = (float)(w0 * mx + w1 * my) + seb1[tid];
        float var = (float)((double)w0 * w0 * vxx + (double)w1 * w1 * vyy +
                            2.0 * (double)w0 * w1 * cxy);
        float sc = seg_[tid] * rsqrtf(var + EPSBN);
        float ix = 1.f / scalar_f(pxm), iy = 1.f / scalar_f(pym);
        fold[tid]      = w0 * sc * ix;
        fold[16 + tid] = w1 * sc * iy;
        fold[32 + tid] = (seb1[tid] - mu) * sc + seb_[tid];
    }
    __syncthreads();

    int wm = wid & 1, wn = wid >> 1;
    int j0 = wn * 8 + (lane & 3) * 2;
    float bj[4][2];
#pragma unroll
    for (int g = 0; g < 4; g++) { bj[g][0] = bs[g * 64 + j0]; bj[g][1] = bs[g * 64 + j0 + 1]; }

    u32 bh[3][4][2];
    {
        u32 nrow = (u32)(wn * 8 + (lane & 7));
        u32 gsel = (u32)(((lane >> 4) & 1) * 64);
        u32 ksel = (u32)(((lane >> 3) & 1) * 16);
#pragma unroll
        for (int kt = 0; kt < 3; kt++) {
#pragma unroll
            for (int p = 0; p < 2; p++) {
                u32 r4[4];
                ldsm4(r4, smb + O_WH +
                      ((u32)(p * 2) * 64 + gsel + nrow) * (WSTR * 2) + ksel + (u32)(kt * 32));
                bh[kt][2 * p][0] = r4[0]; bh[kt][2 * p][1] = r4[1];
                bh[kt][2 * p + 1][0] = r4[2]; bh[kt][2 * p + 1][1] = r4[3];
            }
        }
    }

    u32 aRowOff = (u32)((wm * 32 + (lane & 15)) * (WSTR * 2));
    u32 aColSel = (u32)(((lane >> 4) & 1) * 16);
    u32 bRow = (u32)(wn * 8 + (lane & 7));
    u32 bGsel = (u32)(((lane >> 4) & 1) * 64);
    u32 bKsel = (u32)(((lane >> 3) & 1) * 16);
    int srow = tid >> 3, seg8 = tid & 7, j2 = seg8 * 2;
    float fa0 = fold[j2], fb0 = fold[16 + j2], fc0 = fold[32 + j2];
    float fa1 = fold[j2 + 1], fb1 = fold[16 + j2 + 1], fc1 = fold[32 + j2 + 1];

    {   // prologue: stage feats t0 of first tile into buf0
        int r = blockIdx.x * 64 + srow;
        float2 xy0 = *(const float2*)(obs + 2 * (size_t)r);
        float f0 = fmaxf(fa0 * xy0.x + fb0 * xy0.y + fc0, 0.f);
        float f1 = fmaxf(fa1 * xy0.x + fb1 * xy0.y + fc1, 0.f);
        int off = srow * (WSTR * 2) + j2 * 2;
        *(u32*)(sm + O_AB0 + off) = pack_bf16_hi(f0, f1);
        *(u32*)(sm + O_AB0 + 11264 + off) = pack_bf16_lo(f0, f1);
    }

    for (int tile = blockIdx.x; tile < nTiles; tile += gridDim.x) {
        int row0 = tile * 64;
        int nxt = tile + gridDim.x;
        float creg[2][2][2];

        for (int t = 0; t < T_OBS; t++) {
            u32 ahb = smb + O_AB0 + (u32)((t & 1) * 22528);
            u32 alb = ahb + 11264;
            float2 nxy = make_float2(0.f, 0.f);
            if (t < T_OBS - 1) {
                nxy = *(const float2*)(obs + (size_t)(t + 1) * B * 2 + 2 * (size_t)(row0 + srow));
            } else if (nxt < nTiles) {
                nxy = *(const float2*)(obs + 2 * (size_t)(nxt * 64 + srow));
            }
            __syncthreads();

            float acc[2][4][4];
#pragma unroll
            for (int mt = 0; mt < 2; mt++)
#pragma unroll
                for (int g = 0; g < 4; g++)
#pragma unroll
                    for (int e = 0; e < 4; e++) acc[mt][g][e] = 0.f;
            int nkt = t ? 5 : 1;
#pragma unroll
            for (int kt = 0; kt < 5; kt++) {
                if (kt >= nkt) break;
                u32 kOff = (u32)(kt * 32);
                u32 ah0[4], ah1[4], al0[4], al1[4];
                u32 aAddr = ahb + aRowOff + aColSel + kOff;
                ldsm4(ah0, aAddr);
                ldsm4(ah1, aAddr + 16 * (WSTR * 2));
                u32 aAddrL = alb + aRowOff + aColSel + kOff;
                ldsm4(al0, aAddrL);
                ldsm4(al1, aAddrL + 16 * (WSTR * 2));
                u32 bl[4][2];
#pragma unroll
                for (int p = 0; p < 2; p++) {
                    u32 r4[4];
                    ldsm4(r4, smb + O_WL +
                          ((u32)(p * 2) * 64 + bGsel + bRow) * (WSTR * 2) + bKsel + kOff);
                    bl[2 * p][0] = r4[0]; bl[2 * p][1] = r4[1];
                    bl[2 * p + 1][0] = r4[2]; bl[2 * p + 1][1] = r4[3];
                }
                if (kt < 3) {
#pragma unroll
                    for (int g = 0; g < 4; g++) {
                        mma16816(acc[0][g], ah0, bh[kt][g]);
                        mma16816(acc[1][g], ah1, bh[kt][g]);
                        mma16816(acc[0][g], al0, bh[kt][g]);
                        mma16816(acc[1][g], al1, bh[kt][g]);
                        mma16816(acc[0][g], ah0, bl[g]);
                        mma16816(acc[1][g], ah1, bl[g]);
                    }
                } else {
                    u32 bhd[4][2];
#pragma unroll
                    for (int p = 0; p < 2; p++) {
                        u32 r4[4];
                        ldsm4(r4, smb + O_WH +
                              ((u32)(p * 2) * 64 + bGsel + bRow) * (WSTR * 2) + bKsel + kOff);
                        bhd[2 * p][0] = r4[0]; bhd[2 * p][1] = r4[1];
                        bhd[2 * p + 1][0] = r4[2]; bhd[2 * p + 1][1] = r4[3];
                    }
#pragma unroll
                    for (int g = 0; g < 4; g++) {
                        mma16816(acc[0][g], ah0, bhd[g]);
                        mma16816(acc[1][g], ah1, bhd[g]);
                        mma16816(acc[0][g], al0, bhd[g]);
                        mma16816(acc[1][g], al1, bhd[g]);
                        mma16816(acc[0][g], ah0, bl[g]);
                        mma16816(acc[1][g], ah1, bl[g]);
                    }
                }
            }

            float hn[2][2][2];
#pragma unroll
            for (int mt = 0; mt < 2; mt++)
#pragma unroll
                for (int rr = 0; rr < 2; rr++)
#pragma unroll
                    for (int cc = 0; cc < 2; cc++) {
                        int e = rr * 2 + cc;
                        float iv = acc[mt][0][e] + bj[0][cc];
                        float fv = acc[mt][1][e] + bj[1][cc];
                        float gv = acc[mt][2][e] + bj[2][cc];
                        float ov = acc[mt][3][e] + bj[3][cc];
                        float cold = t ? creg[mt][rr][cc] : 0.f;
                        lstm_cell(iv, fv, gv, ov, cold, creg[mt][rr][cc], hn[mt][rr][cc]);
                    }

            if (t < T_OBS - 1) {
                u32 ahn = smb + O_AB0 + (u32)(((t + 1) & 1) * 22528);
                u32 aln = ahn + 11264;
#pragma unroll
                for (int mt = 0; mt < 2; mt++)
#pragma unroll
                    for (int rr = 0; rr < 2; rr++) {
                        int lrow = wm * 32 + mt * 16 + rr * 8 + (lane >> 2);
                        int off = lrow * (WSTR * 2) + (16 + j0) * 2;
                        *(u32*)(ahn - smb + sm + off) = pack_bf16_hi(hn[mt][rr][0], hn[mt][rr][1]);
                        *(u32*)(aln - smb + sm + off) = pack_bf16_lo(hn[mt][rr][0], hn[mt][rr][1]);
                    }
                float f0 = fmaxf(fa0 * nxy.x + fb0 * nxy.y + fc0, 0.f);
                float f1 = fmaxf(fa1 * nxy.x + fb1 * nxy.y + fc1, 0.f);
                int off = srow * (WSTR * 2) + j2 * 2;
                *(u32*)(ahn - smb + sm + off) = pack_bf16_hi(f0, f1);
                *(u32*)(aln - smb + sm + off) = pack_bf16_lo(f0, f1);
            } else {
#pragma unroll
                for (int mt = 0; mt < 2; mt++)
#pragma unroll
                    for (int rr = 0; rr < 2; rr++) {
                        int r = row0 + wm * 32 + mt * 16 + rr * 8 + (lane >> 2);
                        *(float2*)(g_h + (size_t)r * 64 + j0) =
                            make_float2(hn[mt][rr][0], hn[mt][rr][1]);
                        *(float2*)(g_c + (size_t)r * 64 + j0) =
                            make_float2(creg[mt][rr][0], creg[mt][rr][1]);
                    }
                if (nxt < nTiles) {
                    float f0 = fmaxf(fa0 * nxy.x + fb0 * nxy.y + fc0, 0.f);
                    float f1 = fmaxf(fa1 * nxy.x + fb1 * nxy.y + fc1, 0.f);
                    int off = srow * (WSTR * 2) + j2 * 2;
                    *(u32*)(sm + O_AB0 + off) = pack_bf16_hi(f0, f1);
                    *(u32*)(sm + O_AB0 + 11264 + off) = pack_bf16_lo(f0, f1);
                }
            }
        }
    }
}

// ======================= decode LSTM step (double-buffered A) ================
__global__ void __launch_bounds__(512, 1)
k_dec(int B, int nTiles,
      const float* __restrict__ seW1, const float* __restrict__ seb1,
      const float* __restrict__ seg_, const float* __restrict__ seb_, float Ninv) {
    extern __shared__ char sm[];
    float* bs = (float*)(sm + O_BIAS);
    float* fold = (float*)(sm + O_FOLD);
    u32 smb = smem_u32(sm);
    int tid = threadIdx.x, wid = tid >> 5, lane = tid & 31;

    {
        const float4* s1 = (const float4*)g_Wh;
        const float4* s2 = (const float4*)g_Wl;
        float4* d1 = (float4*)(sm + O_WH);
        float4* d2 = (float4*)(sm + O_WL);
        for (int i = tid; i < 2816; i += 512) { d1[i] = s1[i]; d2[i] = s2[i]; }
    }
    if (tid < 256) bs[tid] = g_bias[tid];
    if (blockIdx.x == 0 && tid < 32) g_hp_stats[tid] = 0.0;
    if (tid < 16) {   // decode BN fold from se stats (inputs already in [0,1])
        const double* st = g_se_stats;
        double mx = st[0] * Ninv, my = st[1] * Ninv;
        double vxx = st[2] * Ninv - mx * mx;
        double vyy = st[3] * Ninv - my * my;
        double cxy = st[4] * Ninv - mx * my;
        float w0 = seW1[2 * tid], w1 = seW1[2 * tid + 1];
        float mu = (float)(w0 * mx + w1 * my) + seb1[tid];
        float var = (float)((double)w0 * w0 * vxx + (double)w1 * w1 * vyy +
                            2.0 * (double)w0 * w1 * cxy);
        float sc = seg_[tid] * rsqrtf(var + EPSBN);
        fold[tid]      = w0 * sc;
        fold[16 + tid] = w1 * sc;
        fold[32 + tid] = (seb1[tid] - mu) * sc + seb_[tid];
    }
    __syncthreads();

    int wm = wid & 1, wn = wid >> 1;
    int j0 = wn * 8 + (lane & 3) * 2;
    float bj[4][2];
#pragma unroll
    for (int g = 0; g < 4; g++) { bj[g][0] = bs[g * 64 + j0]; bj[g][1] = bs[g * 64 + j0 + 1]; }

    u32 bh[3][4][2];
    {
        u32 nrow = (u32)(wn * 8 + (lane & 7));
        u32 gsel = (u32)(((lane >> 4) & 1) * 64);
        u32 ksel = (u32)(((lane >> 3) & 1) * 16);
#pragma unroll
        for (int kt = 0; kt < 3; kt++) {
#pragma unroll
            for (int p = 0; p < 2; p++) {
                u32 r4[4];
                ldsm4(r4, smb + O_WH +
                      ((u32)(p * 2) * 64 + gsel + nrow) * (WSTR * 2) + ksel + (u32)(kt * 32));
                bh[kt][2 * p][0] = r4[0]; bh[kt][2 * p][1] = r4[1];
                bh[kt][2 * p + 1][0] = r4[2]; bh[kt][2 * p + 1][1] = r4[3];
            }
        }
    }

    u32 aRowOff = (u32)((wm * 32 + (lane & 15)) * (WSTR * 2));
    u32 aColSel = (u32)(((lane >> 4) & 1) * 16);
    u32 bRow = (u32)(wn * 8 + (lane & 7));
    u32 bGsel = (u32)(((lane >> 4) & 1) * 64);
    u32 bKsel = (u32)(((lane >> 3) & 1) * 16);
    int srow = tid >> 3, seg8 = tid & 7, j2 = seg8 * 2;
    float fa0 = fold[j2], fb0 = fold[16 + j2], fc0 = fold[32 + j2];
    float fa1 = fold[j2 + 1], fb1 = fold[16 + j2 + 1], fc1 = fold[32 + j2 + 1];

    {   // prologue: stage first tile into buf0
        int r = blockIdx.x * 64 + srow;
        const float4* hp = (const float4*)(g_h + (size_t)r * 64 + seg8 * 8);
        float4 h0 = hp[0], h1 = hp[1];
        float2 lp = *(const float2*)(g_last + 2 * (size_t)r);
        uint4 hi, lo;
        hi.x = pack_bf16_hi(h0.x, h0.y); lo.x = pack_bf16_lo(h0.x, h0.y);
        hi.y = pack_bf16_hi(h0.z, h0.w); lo.y = pack_bf16_lo(h0.z, h0.w);
        hi.z = pack_bf16_hi(h1.x, h1.y); lo.z = pack_bf16_lo(h1.x, h1.y);
        hi.w = pack_bf16_hi(h1.z, h1.w); lo.w = pack_bf16_lo(h1.z, h1.w);
        int off = srow * (WSTR * 2) + 32 + seg8 * 16;
        *(uint4*)(sm + O_AB0 + off) = hi;
        *(uint4*)(sm + O_AB0 + 11264 + off) = lo;
        float f0 = fmaxf(fa0 * lp.x + fb0 * lp.y + fc0, 0.f);
        float f1 = fmaxf(fa1 * lp.x + fb1 * lp.y + fc1, 0.f);
        int offf = srow * (WSTR * 2) + j2 * 2;
        *(u32*)(sm + O_AB0 + offf) = pack_bf16_hi(f0, f1);
        *(u32*)(sm + O_AB0 + 11264 + offf) = pack_bf16_lo(f0, f1);
    }

    int pbuf = 0;
    for (int tile = blockIdx.x; tile < nTiles; tile += gridDim.x) {
        int row0 = tile * 64;
        int nxt = tile + gridDim.x;
        u32 ahb = smb + O_AB0 + (u32)(pbuf * 22528);
        u32 alb = ahb + 11264;

        float4 nh0, nh1; float2 nlp;
        bool hasNext = (nxt < nTiles);
        if (hasNext) {
            int r = nxt * 64 + srow;
            const float4* hp = (const float4*)(g_h + (size_t)r * 64 + seg8 * 8);
            nh0 = hp[0]; nh1 = hp[1];
            nlp = *(const float2*)(g_last + 2 * (size_t)r);
        }
        __syncthreads();

        float acc[2][4][4];
#pragma unroll
        for (int mt = 0; mt < 2; mt++)
#pragma unroll
            for (int g = 0; g < 4; g++)
#pragma unroll
                for (int e = 0; e < 4; e++) acc[mt][g][e] = 0.f;

#pragma unroll
        for (int kt = 0; kt < 5; kt++) {
            u32 kOff = (u32)(kt * 32);
            u32 ah0[4], ah1[4], al0[4], al1[4];
            u32 aAddr = ahb + aRowOff + aColSel + kOff;
            ldsm4(ah0, aAddr);
            ldsm4(ah1, aAddr + 16 * (WSTR * 2));
            u32 aAddrL = alb + aRowOff + aColSel + kOff;
            ldsm4(al0, aAddrL);
            ldsm4(al1, aAddrL + 16 * (WSTR * 2));
            u32 bl[4][2];
#pragma unroll
            for (int p = 0; p < 2; p++) {
                u32 r4[4];
                ldsm4(r4, smb + O_WL +
                      ((u32)(p * 2) * 64 + bGsel + bRow) * (WSTR * 2) + bKsel + kOff);
                bl[2 * p][0] = r4[0]; bl[2 * p][1] = r4[1];
                bl[2 * p + 1][0] = r4[2]; bl[2 * p + 1][1] = r4[3];
            }
            if (kt < 3) {
#pragma unroll
                for (int g = 0; g < 4; g++) {
                    mma16816(acc[0][g], ah0, bh[kt][g]);
                    mma16816(acc[1][g], ah1, bh[kt][g]);
                    mma16816(acc[0][g], al0, bh[kt][g]);
                    mma16816(acc[1][g], al1, bh[kt][g]);
                    mma16816(acc[0][g], ah0, bl[g]);
                    mma16816(acc[1][g], ah1, bl[g]);
                }
            } else {
                u32 bhd[4][2];
#pragma unroll
                for (int p = 0; p < 2; p++) {
                    u32 r4[4];
                    ldsm4(r4, smb + O_WH +
                          ((u32)(p * 2) * 64 + bGsel + bRow) * (WSTR * 2) + bKsel + kOff);
                    bhd[2 * p][0] = r4[0]; bhd[2 * p][1] = r4[1];
                    bhd[2 * p + 1][0] = r4[2]; bhd[2 * p + 1][1] = r4[3];
                }
#pragma unroll
                for (int g = 0; g < 4; g++) {
                    mma16816(acc[0][g], ah0, bhd[g]);
                    mma16816(acc[1][g], ah1, bhd[g]);
                    mma16816(acc[0][g], al0, bhd[g]);
                    mma16816(acc[1][g], al1, bhd[g]);
                    mma16816(acc[0][g], ah0, bl[g]);
                    mma16816(acc[1][g], ah1, bl[g]);
                }
            }
        }

        // epilogue: pointwise -> global h, c
#pragma unroll
        for (int mt = 0; mt < 2; mt++)
#pragma unroll
            for (int rr = 0; rr < 2; rr++) {
                int rw = row0 + wm * 32 + mt * 16 + rr * 8 + (lane >> 2);
                float2 c2 = *(float2*)(g_c + (size_t)rw * 64 + j0);
                float cn[2], hn[2];
#pragma unroll
                for (int cc = 0; cc < 2; cc++) {
                    int e = rr * 2 + cc;
                    float iv = acc[mt][0][e] + bj[0][cc];
                    float fv = acc[mt][1][e] + bj[1][cc];
                    float gv = acc[mt][2][e] + bj[2][cc];
                    float ov = acc[mt][3][e] + bj[3][cc];
                    lstm_cell(iv, fv, gv, ov, cc ? c2.y : c2.x, cn[cc], hn[cc]);
                }
                *(float2*)(g_c + (size_t)rw * 64 + j0) = make_float2(cn[0], cn[1]);
                *(float2*)(g_h + (size_t)rw * 64 + j0) = make_float2(hn[0], hn[1]);
            }

        // stage next tile into the other buffer
        if (hasNext) {
            u32 off1 = (u32)(O_AB0 + (pbuf ^ 1) * 22528);
            uint4 hi, lo;
            hi.x = pack_bf16_hi(nh0.x, nh0.y); lo.x = pack_bf16_lo(nh0.x, nh0.y);
            hi.y = pack_bf16_hi(nh0.z, nh0.w); lo.y = pack_bf16_lo(nh0.z, nh0.w);
            hi.z = pack_bf16_hi(nh1.x, nh1.y); lo.z = pack_bf16_lo(nh1.x, nh1.y);
            hi.w = pack_bf16_hi(nh1.z, nh1.w); lo.w = pack_bf16_lo(nh1.z, nh1.w);
            int off = srow * (WSTR * 2) + 32 + seg8 * 16;
            *(uint4*)(sm + off1 + off) = hi;
            *(uint4*)(sm + off1 + 11264 + off) = lo;
            float f0 = fmaxf(fa0 * nlp.x + fb0 * nlp.y + fc0, 0.f);
            float f1 = fmaxf(fa1 * nlp.x + fb1 * nlp.y + fc1, 0.f);
            int offf = srow * (WSTR * 2) + j2 * 2;
            *(u32*)(sm + off1 + offf) = pack_bf16_hi(f0, f1);
            *(u32*)(sm + off1 + 11264 + offf) = pack_bf16_lo(f0, f1);
        }
        pbuf ^= 1;
    }
}

// ---------------- hidden2pos proj + stats (2 rows/thread, R6 variant) -------
__global__ void k_hp(const float* __restrict__ hpW1, const float* __restrict__ hpb1, int B) {
    __shared__ float Ws[1024];
    __shared__ float red[8][32];
    for (int i = threadIdx.x; i < 1024; i += 256) Ws[i] = hpW1[i];
    if (blockIdx.x == 0 && threadIdx.x < 5) g_se_stats[threadIdx.x] = 0.0;
    __syncthreads();
    int r0 = (blockIdx.x * 256 + threadIdx.x) * 2;
    float z0[16], z1[16];
#pragma unroll
    for (int jj = 0; jj < 16; jj++) { float b = hpb1[jj]; z0[jj] = b; z1[jj] = b; }
    const float4* ha = (const float4*)(g_h + (size_t)r0 * 64);
    const float4* hb = (const float4*)(g_h + (size_t)(r0 + 1) * 64);
#pragma unroll 4
    for (int kk = 0; kk < 16; kk++) {
        float4 a = ha[kk], b = hb[kk];
#pragma unroll
        for (int jj = 0; jj < 16; jj++) {
            const float* w = &Ws[jj * 64 + 4 * kk];
            z0[jj] += a.x * w[0] + a.y * w[1] + a.z * w[2] + a.w * w[3];
            z1[jj] += b.x * w[0] + b.y * w[1] + b.z * w[2] + b.w * w[3];
        }
    }
    float4* zo = (float4*)(g_z + (size_t)r0 * 16);
    zo[0] = make_float4(z0[0], z0[1], z0[2], z0[3]);
    zo[1] = make_float4(z0[4], z0[5], z0[6], z0[7]);
    zo[2] = make_float4(z0[8], z0[9], z0[10], z0[11]);
    zo[3] = make_float4(z0[12], z0[13], z0[14], z0[15]);
    zo[4] = make_float4(z1[0], z1[1], z1[2], z1[3]);
    zo[5] = make_float4(z1[4], z1[5], z1[6], z1[7]);
    zo[6] = make_float4(z1[8], z1[9], z1[10], z1[11]);
    zo[7] = make_float4(z1[12], z1[13], z1[14], z1[15]);
    float sv[16], qv[16];
#pragma unroll
    for (int jj = 0; jj < 16; jj++) {
        sv[jj] = z0[jj] + z1[jj];
        qv[jj] = z0[jj] * z0[jj] + z1[jj] * z1[jj];
    }
    int wid = threadIdx.x >> 5, lane = threadIdx.x & 31;
#pragma unroll
    for (int jj = 0; jj < 16; jj++) { sv[jj] = wred(sv[jj]); qv[jj] = wred(qv[jj]); }
    if (lane == 0) {
#pragma unroll
        for (int jj = 0; jj < 16; jj++) { red[wid][jj] = sv[jj]; red[wid][16 + jj] = qv[jj]; }
    }
    __syncthreads();
    if (wid == 0) {
        float t = 0.f;
#pragma unroll
        for (int w = 0; w < 8; w++) t += red[w][lane];
        atomicAdd(&g_hp_stats[lane], (double)t);
    }
}

// ---------------- positions: BN(inline)+relu+W2, sigmoid, out, se moments ---
__global__ void k_pos(const float* __restrict__ hpW2, const float* __restrict__ hpb2,
                      const float* __restrict__ gamma, const float* __restrict__ beta,
                      float* __restrict__ out, const void* pxm, const void* pym,
                      float Binv, int B) {
    __shared__ float sc[16], sh[16];
    __shared__ float red[8][5];
    if (threadIdx.x < 16) {
        int j = threadIdx.x;
        double mu = g_hp_stats[j] * Binv;
        double var = g_hp_stats[16 + j] * Binv - mu * mu;
        float s = gamma[j] * rsqrtf((float)var + EPSBN);
        sc[j] = s;
        sh[j] = beta[j] - (float)mu * s;
    }
    __syncthreads();
    int row = blockIdx.x * 256 + threadIdx.x;
    const float4* zr = (const float4*)(g_z + (size_t)row * 16);
    float px = hpb2[0], py = hpb2[1];
#pragma unroll
    for (int q4 = 0; q4 < 4; q4++) {
        float4 v = zr[q4];
        float vv[4] = {v.x, v.y, v.z, v.w};
#pragma unroll
        for (int e = 0; e < 4; e++) {
            int j = q4 * 4 + e;
            float t = fmaxf(vv[e] * sc[j] + sh[j], 0.f);
            px += t * hpW2[j];
            py += t * hpW2[16 + j];
        }
    }
    float lx = fast_sig(px + g_last[2 * row]);
    float ly = fast_sig(py + g_last[2 * row + 1]);
    g_last[2 * row] = lx;
    g_last[2 * row + 1] = ly;
    out[2 * row]     = lx * scalar_f(pxm);
    out[2 * row + 1] = ly * scalar_f(pym);
    float s[5] = {lx, ly, lx * lx, ly * ly, lx * ly};
    int wid = threadIdx.x >> 5, lane = threadIdx.x & 31;
#pragma unroll
    for (int k = 0; k < 5; k++) s[k] = wred(s[k]);
    if (lane == 0) {
#pragma unroll
        for (int k = 0; k < 5; k++) red[wid][k] = s[k];
    }
    __syncthreads();
    if (wid == 0 && lane < 5) {
        float t = 0.f;
#pragma unroll
        for (int w = 0; w < 8; w++) t += red[w][lane];
        atomicAdd(&g_se_stats[lane], (double)t);
    }
}

// ---------------- launch ------------------------------------------------------
extern "C" void kernel_launch(void* const* d_in, const int* in_sizes, int n_in,
                              void* d_out, int out_size) {
    const float* obs  = (const float*)d_in[0];
    const float* seW1 = (const float*)d_in[1];
    const float* seb1 = (const float*)d_in[2];
    const float* seg  = (const float*)d_in[3];
    const float* seb  = (const float*)d_in[4];
    const float* seW2 = (const float*)d_in[5];
    const float* seb2 = (const float*)d_in[6];
    const float* hpW1 = (const float*)d_in[7];
    const float* hpb1 = (const float*)d_in[8];
    const float* hpg  = (const float*)d_in[9];
    const float* hpb  = (const float*)d_in[10];
    const float* hpW2 = (const float*)d_in[11];
    const float* hpb2 = (const float*)d_in[12];
    const float* Wih  = (const float*)d_in[13];
    const float* Whh  = (const float*)d_in[14];
    const float* bih  = (const float*)d_in[15];
    const float* bhh  = (const float*)d_in[16];
    const void*  pxm  = d_in[17];
    const void*  pym  = d_in[18];

    int B = in_sizes[0] / (T_OBS * 2);
    int TB = T_OBS * B;
    int predLen = out_size / (2 * B);
    float* out = (float*)d_out;
    int nTiles = B / 64;

    cudaFuncSetAttribute(k_enc, cudaFuncAttributeMaxDynamicSharedMemorySize, LSTM_SMEM);
    cudaFuncSetAttribute(k_dec, cudaFuncAttributeMaxDynamicSharedMemorySize, LSTM_SMEM);

    k_prep<<<1, 256>>>(Wih, Whh, bih, bhh, seW2, seb2);
    k_moments<<<512, 256>>>(obs, pxm, pym, TB, B);
    k_enc<<<148, 512, LSTM_SMEM>>>(obs, B, nTiles, seW1, seb1, seg, seb,
                                   pxm, pym, 1.0f / (float)TB);

    for (int s = 0; s < predLen; s++) {
        k_hp<<<B / 512, 256>>>(hpW1, hpb1, B);
        k_pos<<<B / 256, 256>>>(hpW2, hpb2, hpg, hpb, out + (size_t)s * B * 2,
                                pxm, pym, 1.0f / (float)B, B);
        if (s + 1 < predLen)
            k_dec<<<148, 512, LSTM_SMEM>>>(B, nTiles, seW1, seb1, seg, seb,
                                           1.0f / (float)B);
    }
}

// round 13
// speedup vs baseline: 1.1195x; 1.0467x over previous
#include <cuda_runtime.h>
#include <cuda_bf16.h>
#include <math.h>

#define T_OBS 8
#define EPSBN 1e-5f

typedef unsigned int u32;
typedef unsigned long long u64;

#define MAXB 131072
#define WSTR 88   // padded k-stride (bf16): 176B rows, conflict-free ldmatrix

// ---------------- static device scratch ------------------------------------
__device__ float  g_h[MAXB * 64];
__device__ float  g_c[MAXB * 64];
__device__ float  g_z[MAXB * 16];
__device__ float  g_last[MAXB * 2];
__device__ __align__(16) __nv_bfloat16 g_Wh[256 * WSTR];
__device__ __align__(16) __nv_bfloat16 g_Wl[256 * WSTR];
__device__ float  g_bias[256];
__device__ double g_enc_stats[5];
__device__ double g_se_stats[5];
__device__ double g_hp_stats[32];

// ---------------- helpers ----------------------------------------------------
__device__ __forceinline__ float scalar_f(const void* p) {
    int iv = *(const int*)p;
    float fv = __int_as_float(iv);
    if (fv >= 1e-3f && fv <= 1e7f) return fv;
    return (float)iv;
}
__device__ __forceinline__ float fast_sig(float x) {
    float t; asm("ex2.approx.f32 %0, %1;" : "=f"(t) : "f"(-1.4426950408889634f * x));
    float r; asm("rcp.approx.f32 %0, %1;" : "=f"(r) : "f"(1.0f + t));
    return r;
}
// fused LSTM pointwise: 8 MUFU per cell
__device__ __forceinline__ void lstm_cell(float iv, float fv, float gv, float ov,
                                          float cold, float& cnew, float& hnew) {
    gv = fminf(fmaxf(gv, -30.f), 30.f);
    float tf; asm("ex2.approx.f32 %0, %1;" : "=f"(tf) : "f"(-1.4426950408889634f * fv));
    float sf; asm("rcp.approx.f32 %0, %1;" : "=f"(sf) : "f"(1.0f + tf));
    float ei; asm("ex2.approx.f32 %0, %1;" : "=f"(ei) : "f"(-1.4426950408889634f * iv));
    float eg; asm("ex2.approx.f32 %0, %1;" : "=f"(eg) : "f"(2.8853900817779268f * gv));
    float dig = (1.0f + ei) * (eg + 1.0f);
    float rig; asm("rcp.approx.f32 %0, %1;" : "=f"(rig) : "f"(dig));
    float c2 = sf * cold + (eg - 1.0f) * rig;
    cnew = c2;
    float eo; asm("ex2.approx.f32 %0, %1;" : "=f"(eo) : "f"(-1.4426950408889634f * ov));
    float ec; asm("ex2.approx.f32 %0, %1;" : "=f"(ec) : "f"(2.8853900817779268f * c2));
    float doc = (1.0f + eo) * (ec + 1.0f);
    float roc; asm("rcp.approx.f32 %0, %1;" : "=f"(roc) : "f"(doc));
    hnew = (ec - 1.0f) * roc;
}
__device__ __forceinline__ float wred(float v) {
#pragma unroll
    for (int o = 16; o > 0; o >>= 1) v += __shfl_down_sync(0xffffffffu, v, o);
    return v;
}
__device__ __forceinline__ u32 smem_u32(const void* p) {
    u32 a;
    asm("{ .reg .u64 t; cvta.to.shared.u64 t, %1; cvt.u32.u64 %0, t; }" : "=r"(a) : "l"(p));
    return a;
}
__device__ __forceinline__ void ldsm4(u32* r, u32 addr) {
    asm volatile("ldmatrix.sync.aligned.m8n8.x4.shared.b16 {%0,%1,%2,%3}, [%4];"
        : "=r"(r[0]), "=r"(r[1]), "=r"(r[2]), "=r"(r[3]) : "r"(addr));
}
__device__ __forceinline__ void mma16816(float* d, const u32* a, const u32* b) {
    asm volatile(
        "mma.sync.aligned.m16n8k16.row.col.f32.bf16.bf16.f32 "
        "{%0,%1,%2,%3},{%4,%5,%6,%7},{%8,%9},{%0,%1,%2,%3};"
        : "+f"(d[0]), "+f"(d[1]), "+f"(d[2]), "+f"(d[3])
        : "r"(a[0]), "r"(a[1]), "r"(a[2]), "r"(a[3]), "r"(b[0]), "r"(b[1]));
}
__device__ __forceinline__ u32 pack_bf16_hi(float a0, float a1) {
    __nv_bfloat16 h0 = __float2bfloat16(a0), h1 = __float2bfloat16(a1);
    return ((u32)__bfloat16_as_ushort(h1) << 16) | __bfloat16_as_ushort(h0);
}
__device__ __forceinline__ u32 pack_bf16_lo(float a0, float a1) {
    __nv_bfloat16 h0 = __float2bfloat16(a0), h1 = __float2bfloat16(a1);
    __nv_bfloat16 l0 = __float2bfloat16(a0 - __bfloat162float(h0));
    __nv_bfloat16 l1 = __float2bfloat16(a1 - __bfloat162float(h1));
    return ((u32)__bfloat16_as_ushort(l1) << 16) | __bfloat16_as_ushort(l0);
}

// ---------------- smem layouts ------------------------------------------------
// k_enc (512 thr, 1 CTA/SM, 64-row tiles, double-buffered A)
#define O_WH   0                    // 45056
#define O_WL   45056                // 45056
#define O_AB0  90112                // AH0; AL0=+11264; AH1=+22528; AL1=+33792
#define O_BIAS 135168               // 1024
#define O_FOLD 136192               // 192
#define ENC_SMEM 136448
// k_dec (256 thr, 2 CTA/SM, 32-row tiles, single A)
#define D_AH   90112                // 5632
#define D_AL   95744                // 5632
#define D_BIAS 101376               // 1024
#define D_FOLD 102400               // 192
#define DEC_SMEM 102592

// ---------------- prep: fold se_W2/se_b2 into Wih; bf16-split ---------------
__global__ void k_prep(const float* __restrict__ Wih, const float* __restrict__ Whh,
                       const float* __restrict__ bih, const float* __restrict__ bhh,
                       const float* __restrict__ seW2, const float* __restrict__ seb2) {
    int gc = threadIdx.x;
    if (gc < 5) g_enc_stats[gc] = 0.0;
    float wr[64];
#pragma unroll 8
    for (int m = 0; m < 64; m++) wr[m] = Wih[gc * 64 + m];
    float be = bih[gc] + bhh[gc];
#pragma unroll 8
    for (int m = 0; m < 64; m++) be += wr[m] * seb2[m];
    g_bias[gc] = be;
    for (int k = 0; k < WSTR; k++) {
        float w = 0.f;
        if (k < 16) {
#pragma unroll 8
            for (int m = 0; m < 64; m++) w += wr[m] * seW2[m * 16 + k];
        } else if (k < 80) {
            w = Whh[gc * 64 + (k - 16)];
        }
        __nv_bfloat16 hi = __float2bfloat16(w);
        __nv_bfloat16 lo = __float2bfloat16(w - __bfloat162float(hi));
        g_Wh[gc * WSTR + k] = hi;
        g_Wl[gc * WSTR + k] = lo;
    }
}

// ---------------- moments of normalized obs + init last_pos -----------------
__global__ void k_moments(const float* __restrict__ obs, const void* pxm, const void* pym,
                          int TB, int B) {
    __shared__ float red[8][5];
    float invx = 1.0f / scalar_f(pxm), invy = 1.0f / scalar_f(pym);
    int idx = blockIdx.x * blockDim.x + threadIdx.x;
    int stride = gridDim.x * blockDim.x;
    float s[5] = {0, 0, 0, 0, 0};
    for (int i = idx; i < TB; i += stride) {
        float x = obs[2 * i] * invx, y = obs[2 * i + 1] * invy;
        s[0] += x; s[1] += y; s[2] += x * x; s[3] += y * y; s[4] += x * y;
    }
    int wid = threadIdx.x >> 5, lane = threadIdx.x & 31;
#pragma unroll
    for (int k = 0; k < 5; k++) s[k] = wred(s[k]);
    if (lane == 0) {
#pragma unroll
        for (int k = 0; k < 5; k++) red[wid][k] = s[k];
    }
    __syncthreads();
    if (wid == 0 && lane < 5) {
        float t = 0.f;
#pragma unroll
        for (int w = 0; w < 8; w++) t += red[w][lane];
        atomicAdd(&g_enc_stats[lane], (double)t);
    }
    int off = TB - B;
    for (int i = idx; i < B; i += stride) {
        g_last[2 * i]     = obs[2 * (off + i)]     * invx;
        g_last[2 * i + 1] = obs[2 * (off + i) + 1] * invy;
    }
}

// ======================= fused 8-step encoder (unchanged) ====================
__global__ void __launch_bounds__(512, 1)
k_enc(const float* __restrict__ obs, int B, int nTiles,
      const float* __restrict__ seW1, const float* __restrict__ seb1,
      const float* __restrict__ seg_, const float* __restrict__ seb_,
      const void* pxm, const void* pym, float Ninv) {
    extern __shared__ char sm[];
    float* bs = (float*)(sm + O_BIAS);
    float* fold = (float*)(sm + O_FOLD);
    u32 smb = smem_u32(sm);
    int tid = threadIdx.x, wid = tid >> 5, lane = tid & 31;

    {
        const float4* s1 = (const float4*)g_Wh;
        const float4* s2 = (const float4*)g_Wl;
        float4* d1 = (float4*)(sm + O_WH);
        float4* d2 = (float4*)(sm + O_WL);
        for (int i = tid; i < 2816; i += 512) { d1[i] = s1[i]; d2[i] = s2[i]; }
    }
    if (tid < 256) bs[tid] = g_bias[tid];
    if (blockIdx.x == 0 && tid < 32) g_hp_stats[tid] = 0.0;
    if (tid < 16) {
        const double* st = g_enc_stats;
        double mx = st[0] * Ninv, my = st[1] * Ninv;
        double vxx = st[2] * Ninv - mx * mx;
        double vyy = st[3] * Ninv - my * my;
        double cxy = st[4] * Ninv - mx * my;
        float w0 = seW1[2 * tid], w1 = seW1[2 * tid + 1];
        float mu = (float)(w0 * mx + w1 * my) + seb1[tid];
        float var = (float)((double)w0 * w0 * vxx + (double)w1 * w1 * vyy +
                            2.0 * (double)w0 * w1 * cxy);
        float sc = seg_[tid] * rsqrtf(var + EPSBN);
        float ix = 1.f / scalar_f(pxm), iy = 1.f / scalar_f(pym);
        fold[tid]      = w0 * sc * ix;
        fold[16 + tid] = w1 * sc * iy;
        fold[32 + tid] = (seb1[tid] - mu) * sc + seb_[tid];
    }
    __syncthreads();

    int wm = wid & 1, wn = wid >> 1;
    int j0 = wn * 8 + (lane & 3) * 2;
    float bj[4][2];
#pragma unroll
    for (int g = 0; g < 4; g++) { bj[g][0] = bs[g * 64 + j0]; bj[g][1] = bs[g * 64 + j0 + 1]; }

    u32 bh[3][4][2];
    {
        u32 nrow = (u32)(wn * 8 + (lane & 7));
        u32 gsel = (u32)(((lane >> 4) & 1) * 64);
        u32 ksel = (u32)(((lane >> 3) & 1) * 16);
#pragma unroll
        for (int kt = 0; kt < 3; kt++) {
#pragma unroll
            for (int p = 0; p < 2; p++) {
                u32 r4[4];
                ldsm4(r4, smb + O_WH +
                      ((u32)(p * 2) * 64 + gsel + nrow) * (WSTR * 2) + ksel + (u32)(kt * 32));
                bh[kt][2 * p][0] = r4[0]; bh[kt][2 * p][1] = r4[1];
                bh[kt][2 * p + 1][0] = r4[2]; bh[kt][2 * p + 1][1] = r4[3];
            }
        }
    }

    u32 aRowOff = (u32)((wm * 32 + (lane & 15)) * (WSTR * 2));
    u32 aColSel = (u32)(((lane >> 4) & 1) * 16);
    u32 bRow = (u32)(wn * 8 + (lane & 7));
    u32 bGsel = (u32)(((lane >> 4) & 1) * 64);
    u32 bKsel = (u32)(((lane >> 3) & 1) * 16);
    int srow = tid >> 3, seg8 = tid & 7, j2 = seg8 * 2;
    float fa0 = fold[j2], fb0 = fold[16 + j2], fc0 = fold[32 + j2];
    float fa1 = fold[j2 + 1], fb1 = fold[16 + j2 + 1], fc1 = fold[32 + j2 + 1];

    {
        int r = blockIdx.x * 64 + srow;
        float2 xy0 = *(const float2*)(obs + 2 * (size_t)r);
        float f0 = fmaxf(fa0 * xy0.x + fb0 * xy0.y + fc0, 0.f);
        float f1 = fmaxf(fa1 * xy0.x + fb1 * xy0.y + fc1, 0.f);
        int off = srow * (WSTR * 2) + j2 * 2;
        *(u32*)(sm + O_AB0 + off) = pack_bf16_hi(f0, f1);
        *(u32*)(sm + O_AB0 + 11264 + off) = pack_bf16_lo(f0, f1);
    }

    for (int tile = blockIdx.x; tile < nTiles; tile += gridDim.x) {
        int row0 = tile * 64;
        int nxt = tile + gridDim.x;
        float creg[2][2][2];

        for (int t = 0; t < T_OBS; t++) {
            u32 ahb = smb + O_AB0 + (u32)((t & 1) * 22528);
            u32 alb = ahb + 11264;
            float2 nxy = make_float2(0.f, 0.f);
            if (t < T_OBS - 1) {
                nxy = *(const float2*)(obs + (size_t)(t + 1) * B * 2 + 2 * (size_t)(row0 + srow));
            } else if (nxt < nTiles) {
                nxy = *(const float2*)(obs + 2 * (size_t)(nxt * 64 + srow));
            }
            __syncthreads();

            float acc[2][4][4];
#pragma unroll
            for (int mt = 0; mt < 2; mt++)
#pragma unroll
                for (int g = 0; g < 4; g++)
#pragma unroll
                    for (int e = 0; e < 4; e++) acc[mt][g][e] = 0.f;
            int nkt = t ? 5 : 1;
#pragma unroll
            for (int kt = 0; kt < 5; kt++) {
                if (kt >= nkt) break;
                u32 kOff = (u32)(kt * 32);
                u32 ah0[4], ah1[4], al0[4], al1[4];
                u32 aAddr = ahb + aRowOff + aColSel + kOff;
                ldsm4(ah0, aAddr);
                ldsm4(ah1, aAddr + 16 * (WSTR * 2));
                u32 aAddrL = alb + aRowOff + aColSel + kOff;
                ldsm4(al0, aAddrL);
                ldsm4(al1, aAddrL + 16 * (WSTR * 2));
                u32 bl[4][2];
#pragma unroll
                for (int p = 0; p < 2; p++) {
                    u32 r4[4];
                    ldsm4(r4, smb + O_WL +
                          ((u32)(p * 2) * 64 + bGsel + bRow) * (WSTR * 2) + bKsel + kOff);
                    bl[2 * p][0] = r4[0]; bl[2 * p][1] = r4[1];
                    bl[2 * p + 1][0] = r4[2]; bl[2 * p + 1][1] = r4[3];
                }
                if (kt < 3) {
#pragma unroll
                    for (int g = 0; g < 4; g++) {
                        mma16816(acc[0][g], ah0, bh[kt][g]);
                        mma16816(acc[1][g], ah1, bh[kt][g]);
                        mma16816(acc[0][g], al0, bh[kt][g]);
                        mma16816(acc[1][g], al1, bh[kt][g]);
                        mma16816(acc[0][g], ah0, bl[g]);
                        mma16816(acc[1][g], ah1, bl[g]);
                    }
                } else {
                    u32 bhd[4][2];
#pragma unroll
                    for (int p = 0; p < 2; p++) {
                        u32 r4[4];
                        ldsm4(r4, smb + O_WH +
                              ((u32)(p * 2) * 64 + bGsel + bRow) * (WSTR * 2) + bKsel + kOff);
                        bhd[2 * p][0] = r4[0]; bhd[2 * p][1] = r4[1];
                        bhd[2 * p + 1][0] = r4[2]; bhd[2 * p + 1][1] = r4[3];
                    }
#pragma unroll
                    for (int g = 0; g < 4; g++) {
                        mma16816(acc[0][g], ah0, bhd[g]);
                        mma16816(acc[1][g], ah1, bhd[g]);
                        mma16816(acc[0][g], al0, bhd[g]);
                        mma16816(acc[1][g], al1, bhd[g]);
                        mma16816(acc[0][g], ah0, bl[g]);
                        mma16816(acc[1][g], ah1, bl[g]);
                    }
                }
            }

            float hn[2][2][2];
#pragma unroll
            for (int mt = 0; mt < 2; mt++)
#pragma unroll
                for (int rr = 0; rr < 2; rr++)
#pragma unroll
                    for (int cc = 0; cc < 2; cc++) {
                        int e = rr * 2 + cc;
                        float iv = acc[mt][0][e] + bj[0][cc];
                        float fv = acc[mt][1][e] + bj[1][cc];
                        float gv = acc[mt][2][e] + bj[2][cc];
                        float ov = acc[mt][3][e] + bj[3][cc];
                        float cold = t ? creg[mt][rr][cc] : 0.f;
                        lstm_cell(iv, fv, gv, ov, cold, creg[mt][rr][cc], hn[mt][rr][cc]);
                    }

            if (t < T_OBS - 1) {
                u32 ahn = smb + O_AB0 + (u32)(((t + 1) & 1) * 22528);
                u32 aln = ahn + 11264;
#pragma unroll
                for (int mt = 0; mt < 2; mt++)
#pragma unroll
                    for (int rr = 0; rr < 2; rr++) {
                        int lrow = wm * 32 + mt * 16 + rr * 8 + (lane >> 2);
                        int off = lrow * (WSTR * 2) + (16 + j0) * 2;
                        *(u32*)(ahn - smb + sm + off) = pack_bf16_hi(hn[mt][rr][0], hn[mt][rr][1]);
                        *(u32*)(aln - smb + sm + off) = pack_bf16_lo(hn[mt][rr][0], hn[mt][rr][1]);
                    }
                float f0 = fmaxf(fa0 * nxy.x + fb0 * nxy.y + fc0, 0.f);
                float f1 = fmaxf(fa1 * nxy.x + fb1 * nxy.y + fc1, 0.f);
                int off = srow * (WSTR * 2) + j2 * 2;
                *(u32*)(ahn - smb + sm + off) = pack_bf16_hi(f0, f1);
                *(u32*)(aln - smb + sm + off) = pack_bf16_lo(f0, f1);
            } else {
#pragma unroll
                for (int mt = 0; mt < 2; mt++)
#pragma unroll
                    for (int rr = 0; rr < 2; rr++) {
                        int r = row0 + wm * 32 + mt * 16 + rr * 8 + (lane >> 2);
                        *(float2*)(g_h + (size_t)r * 64 + j0) =
                            make_float2(hn[mt][rr][0], hn[mt][rr][1]);
                        *(float2*)(g_c + (size_t)r * 64 + j0) =
                            make_float2(creg[mt][rr][0], creg[mt][rr][1]);
                    }
                if (nxt < nTiles) {
                    float f0 = fmaxf(fa0 * nxy.x + fb0 * nxy.y + fc0, 0.f);
                    float f1 = fmaxf(fa1 * nxy.x + fb1 * nxy.y + fc1, 0.f);
                    int off = srow * (WSTR * 2) + j2 * 2;
                    *(u32*)(sm + O_AB0 + off) = pack_bf16_hi(f0, f1);
                    *(u32*)(sm + O_AB0 + 11264 + off) = pack_bf16_lo(f0, f1);
                }
            }
        }
    }
}

// ======== decode LSTM step: 256 thr, 32-row tiles, 2 CTAs/SM ================
__global__ void __launch_bounds__(256, 2)
k_dec(int B, int nTiles,
      const float* __restrict__ seW1, const float* __restrict__ seb1,
      const float* __restrict__ seg_, const float* __restrict__ seb_, float Ninv) {
    extern __shared__ char sm[];
    float* bs = (float*)(sm + D_BIAS);
    float* fold = (float*)(sm + D_FOLD);
    u32 smb = smem_u32(sm);
    int tid = threadIdx.x, wid = tid >> 5, lane = tid & 31;

    {
        const float4* s1 = (const float4*)g_Wh;
        const float4* s2 = (const float4*)g_Wl;
        float4* d1 = (float4*)(sm + O_WH);
        float4* d2 = (float4*)(sm + O_WL);
        for (int i = tid; i < 2816; i += 256) { d1[i] = s1[i]; d2[i] = s2[i]; }
    }
    if (tid < 256) bs[tid] = g_bias[tid];
    if (blockIdx.x == 0 && tid < 32) g_hp_stats[tid] = 0.0;
    if (tid < 16) {   // decode BN fold from se stats
        const double* st = g_se_stats;
        double mx = st[0] * Ninv, my = st[1] * Ninv;
        double vxx = st[2] * Ninv - mx * mx;
        double vyy = st[3] * Ninv - my * my;
        double cxy = st[4] * Ninv - mx * my;
        float w0 = seW1[2 * tid], w1 = seW1[2 * tid + 1];
        float mu = (float)(w0 * mx + w1 * my) + seb1[tid];
        float var = (float)((double)w0 * w0 * vxx + (double)w1 * w1 * vyy +
                            2.0 * (double)w0 * w1 * cxy);
        float sc = seg_[tid] * rsqrtf(var + EPSBN);
        fold[tid]      = w0 * sc;
        fold[16 + tid] = w1 * sc;
        fold[32 + tid] = (seb1[tid] - mu) * sc + seb_[tid];
    }
    __syncthreads();

    int wn = wid;                       // 8 warps = 8 n-slices
    int j0 = wn * 8 + (lane & 3) * 2;
    float bj[4][2];
#pragma unroll
    for (int g = 0; g < 4; g++) { bj[g][0] = bs[g * 64 + j0]; bj[g][1] = bs[g * 64 + j0 + 1]; }

    u32 bh[3][4][2];
    {
        u32 nrow = (u32)(wn * 8 + (lane & 7));
        u32 gsel = (u32)(((lane >> 4) & 1) * 64);
        u32 ksel = (u32)(((lane >> 3) & 1) * 16);
#pragma unroll
        for (int kt = 0; kt < 3; kt++) {
#pragma unroll
            for (int p = 0; p < 2; p++) {
                u32 r4[4];
                ldsm4(r4, smb + O_WH +
                      ((u32)(p * 2) * 64 + gsel + nrow) * (WSTR * 2) + ksel + (u32)(kt * 32));
                bh[kt][2 * p][0] = r4[0]; bh[kt][2 * p][1] = r4[1];
                bh[kt][2 * p + 1][0] = r4[2]; bh[kt][2 * p + 1][1] = r4[3];
            }
        }
    }

    u32 aRowOff = (u32)((lane & 15) * (WSTR * 2));
    u32 aColSel = (u32)(((lane >> 4) & 1) * 16);
    u32 bRow = (u32)(wn * 8 + (lane & 7));
    u32 bGsel = (u32)(((lane >> 4) & 1) * 64);
    u32 bKsel = (u32)(((lane >> 3) & 1) * 16);
    int srow = tid >> 3, seg8 = tid & 7, j2 = seg8 * 2;
    float fa0 = fold[j2], fb0 = fold[16 + j2], fc0 = fold[32 + j2];
    float fa1 = fold[j2 + 1], fb1 = fold[16 + j2 + 1], fc1 = fold[32 + j2 + 1];

    {   // prologue: stage first 32-row tile
        int r = blockIdx.x * 32 + srow;
        const float4* hp = (const float4*)(g_h + (size_t)r * 64 + seg8 * 8);
        float4 h0 = hp[0], h1 = hp[1];
        float2 lp = *(const float2*)(g_last + 2 * (size_t)r);
        uint4 hi, lo;
        hi.x = pack_bf16_hi(h0.x, h0.y); lo.x = pack_bf16_lo(h0.x, h0.y);
        hi.y = pack_bf16_hi(h0.z, h0.w); lo.y = pack_bf16_lo(h0.z, h0.w);
        hi.z = pack_bf16_hi(h1.x, h1.y); lo.z = pack_bf16_lo(h1.x, h1.y);
        hi.w = pack_bf16_hi(h1.z, h1.w); lo.w = pack_bf16_lo(h1.z, h1.w);
        int off = srow * (WSTR * 2) + 32 + seg8 * 16;
        *(uint4*)(sm + D_AH + off) = hi;
        *(uint4*)(sm + D_AL + off) = lo;
        float f0 = fmaxf(fa0 * lp.x + fb0 * lp.y + fc0, 0.f);
        float f1 = fmaxf(fa1 * lp.x + fb1 * lp.y + fc1, 0.f);
        int offf = srow * (WSTR * 2) + j2 * 2;
        *(u32*)(sm + D_AH + offf) = pack_bf16_hi(f0, f1);
        *(u32*)(sm + D_AL + offf) = pack_bf16_lo(f0, f1);
    }

    for (int tile = blockIdx.x; tile < nTiles; tile += gridDim.x) {
        int row0 = tile * 32;
        int nxt = tile + gridDim.x;

        // prefetch next tile (hide LDG under MMA) + current c
        float4 nh0, nh1; float2 nlp;
        bool hasNext = (nxt < nTiles);
        if (hasNext) {
            int r = nxt * 32 + srow;
            const float4* hp = (const float4*)(g_h + (size_t)r * 64 + seg8 * 8);
            nh0 = hp[0]; nh1 = hp[1];
            nlp = *(const float2*)(g_last + 2 * (size_t)r);
        }
        float2 cpre[2][2];
#pragma unroll
        for (int mt = 0; mt < 2; mt++)
#pragma unroll
            for (int rr = 0; rr < 2; rr++) {
                int rw = row0 + mt * 16 + rr * 8 + (lane >> 2);
                cpre[mt][rr] = *(const float2*)(g_c + (size_t)rw * 64 + j0);
            }
        __syncthreads();   // A staged (prologue or previous epilogue STS)

        float acc[2][4][4];
#pragma unroll
        for (int mt = 0; mt < 2; mt++)
#pragma unroll
            for (int g = 0; g < 4; g++)
#pragma unroll
                for (int e = 0; e < 4; e++) acc[mt][g][e] = 0.f;

#pragma unroll
        for (int kt = 0; kt < 5; kt++) {
            u32 kOff = (u32)(kt * 32);
            u32 ah0[4], ah1[4], al0[4], al1[4];
            u32 aAddr = smb + D_AH + aRowOff + aColSel + kOff;
            ldsm4(ah0, aAddr);
            ldsm4(ah1, aAddr + 16 * (WSTR * 2));
            u32 aAddrL = smb + D_AL + aRowOff + aColSel + kOff;
            ldsm4(al0, aAddrL);
            ldsm4(al1, aAddrL + 16 * (WSTR * 2));
            u32 bl[4][2];
#pragma unroll
            for (int p = 0; p < 2; p++) {
                u32 r4[4];
                ldsm4(r4, smb + O_WL +
                      ((u32)(p * 2) * 64 + bGsel + bRow) * (WSTR * 2) + bKsel + kOff);
                bl[2 * p][0] = r4[0]; bl[2 * p][1] = r4[1];
                bl[2 * p + 1][0] = r4[2]; bl[2 * p + 1][1] = r4[3];
            }
            if (kt < 3) {
#pragma unroll
                for (int g = 0; g < 4; g++) {
                    mma16816(acc[0][g], ah0, bh[kt][g]);
                    mma16816(acc[1][g], ah1, bh[kt][g]);
                    mma16816(acc[0][g], al0, bh[kt][g]);
                    mma16816(acc[1][g], al1, bh[kt][g]);
                    mma16816(acc[0][g], ah0, bl[g]);
                    mma16816(acc[1][g], ah1, bl[g]);
                }
            } else {
                u32 bhd[4][2];
#pragma unroll
                for (int p = 0; p < 2; p++) {
                    u32 r4[4];
                    ldsm4(r4, smb + O_WH +
                          ((u32)(p * 2) * 64 + bGsel + bRow) * (WSTR * 2) + bKsel + kOff);
                    bhd[2 * p][0] = r4[0]; bhd[2 * p][1] = r4[1];
                    bhd[2 * p + 1][0] = r4[2]; bhd[2 * p + 1][1] = r4[3];
                }
#pragma unroll
                for (int g = 0; g < 4; g++) {
                    mma16816(acc[0][g], ah0, bhd[g]);
                    mma16816(acc[1][g], ah1, bhd[g]);
                    mma16816(acc[0][g], al0, bhd[g]);
                    mma16816(acc[1][g], al1, bhd[g]);
                    mma16816(acc[0][g], ah0, bl[g]);
                    mma16816(acc[1][g], ah1, bl[g]);
                }
            }
        }

        // epilogue: pointwise -> global h, c (c was prefetched)
#pragma unroll
        for (int mt = 0; mt < 2; mt++)
#pragma unroll
            for (int rr = 0; rr < 2; rr++) {
                int rw = row0 + mt * 16 + rr * 8 + (lane >> 2);
                float2 c2 = cpre[mt][rr];
                float cn[2], hn[2];
#pragma unroll
                for (int cc = 0; cc < 2; cc++) {
                    int e = rr * 2 + cc;
                    float iv = acc[mt][0][e] + bj[0][cc];
                    float fv = acc[mt][1][e] + bj[1][cc];
                    float gv = acc[mt][2][e] + bj[2][cc];
                    float ov = acc[mt][3][e] + bj[3][cc];
                    lstm_cell(iv, fv, gv, ov, cc ? c2.y : c2.x, cn[cc], hn[cc]);
                }
                *(float2*)(g_c + (size_t)rw * 64 + j0) = make_float2(cn[0], cn[1]);
                *(float2*)(g_h + (size_t)rw * 64 + j0) = make_float2(hn[0], hn[1]);
            }

        __syncthreads();   // all ldsm reads of the A buffer done
        if (hasNext) {     // stage next tile into the (single) A buffer
            uint4 hi, lo;
            hi.x = pack_bf16_hi(nh0.x, nh0.y); lo.x = pack_bf16_lo(nh0.x, nh0.y);
            hi.y = pack_bf16_hi(nh0.z, nh0.w); lo.y = pack_bf16_lo(nh0.z, nh0.w);
            hi.z = pack_bf16_hi(nh1.x, nh1.y); lo.z = pack_bf16_lo(nh1.x, nh1.y);
            hi.w = pack_bf16_hi(nh1.z, nh1.w); lo.w = pack_bf16_lo(nh1.z, nh1.w);
            int off = srow * (WSTR * 2) + 32 + seg8 * 16;
            *(uint4*)(sm + D_AH + off) = hi;
            *(uint4*)(sm + D_AL + off) = lo;
            float f0 = fmaxf(fa0 * nlp.x + fb0 * nlp.y + fc0, 0.f);
            float f1 = fmaxf(fa1 * nlp.x + fb1 * nlp.y + fc1, 0.f);
            int offf = srow * (WSTR * 2) + j2 * 2;
            *(u32*)(sm + D_AH + offf) = pack_bf16_hi(f0, f1);
            *(u32*)(sm + D_AL + offf) = pack_bf16_lo(f0, f1);
        }
    }
}

// ---------------- hidden2pos proj + stats (2 rows/thread) --------------------
__global__ void k_hp(const float* __restrict__ hpW1, const float* __restrict__ hpb1, int B) {
    __shared__ float Ws[1024];
    __shared__ float red[8][32];
    for (int i = threadIdx.x; i < 1024; i += 256) Ws[i] = hpW1[i];
    if (blockIdx.x == 0 && threadIdx.x < 5) g_se_stats[threadIdx.x] = 0.0;
    __syncthreads();
    int r0 = (blockIdx.x * 256 + threadIdx.x) * 2;
    float z0[16], z1[16];
#pragma unroll
    for (int jj = 0; jj < 16; jj++) { float b = hpb1[jj]; z0[jj] = b; z1[jj] = b; }
    const float4* ha = (const float4*)(g_h + (size_t)r0 * 64);
    const float4* hb = (const float4*)(g_h + (size_t)(r0 + 1) * 64);
#pragma unroll 4
    for (int kk = 0; kk < 16; kk++) {
        float4 a = ha[kk], b = hb[kk];
#pragma unroll
        for (int jj = 0; jj < 16; jj++) {
            const float* w = &Ws[jj * 64 + 4 * kk];
            z0[jj] += a.x * w[0] + a.y * w[1] + a.z * w[2] + a.w * w[3];
            z1[jj] += b.x * w[0] + b.y * w[1] + b.z * w[2] + b.w * w[3];
        }
    }
    float4* zo = (float4*)(g_z + (size_t)r0 * 16);
    zo[0] = make_float4(z0[0], z0[1], z0[2], z0[3]);
    zo[1] = make_float4(z0[4], z0[5], z0[6], z0[7]);
    zo[2] = make_float4(z0[8], z0[9], z0[10], z0[11]);
    zo[3] = make_float4(z0[12], z0[13], z0[14], z0[15]);
    zo[4] = make_float4(z1[0], z1[1], z1[2], z1[3]);
    zo[5] = make_float4(z1[4], z1[5], z1[6], z1[7]);
    zo[6] = make_float4(z1[8], z1[9], z1[10], z1[11]);
    zo[7] = make_float4(z1[12], z1[13], z1[14], z1[15]);
    float sv[16], qv[16];
#pragma unroll
    for (int jj = 0; jj < 16; jj++) {
        sv[jj] = z0[jj] + z1[jj];
        qv[jj] = z0[jj] * z0[jj] + z1[jj] * z1[jj];
    }
    int wid = threadIdx.x >> 5, lane = threadIdx.x & 31;
#pragma unroll
    for (int jj = 0; jj < 16; jj++) { sv[jj] = wred(sv[jj]); qv[jj] = wred(qv[jj]); }
    if (lane == 0) {
#pragma unroll
        for (int jj = 0; jj < 16; jj++) { red[wid][jj] = sv[jj]; red[wid][16 + jj] = qv[jj]; }
    }
    __syncthreads();
    if (wid == 0) {
        float t = 0.f;
#pragma unroll
        for (int w = 0; w < 8; w++) t += red[w][lane];
        atomicAdd(&g_hp_stats[lane], (double)t);
    }
}

// ---------------- positions: BN(inline)+relu+W2, sigmoid, out, se moments ---
__global__ void k_pos(const float* __restrict__ hpW2, const float* __restrict__ hpb2,
                      const float* __restrict__ gamma, const float* __restrict__ beta,
                      float* __restrict__ out, const void* pxm, const void* pym,
                      float Binv, int B) {
    __shared__ float sc[16], sh[16];
    __shared__ float red[8][5];
    if (threadIdx.x < 16) {
        int j = threadIdx.x;
        double mu = g_hp_stats[j] * Binv;
        double var = g_hp_stats[16 + j] * Binv - mu * mu;
        float s = gamma[j] * rsqrtf((float)var + EPSBN);
        sc[j] = s;
        sh[j] = beta[j] - (float)mu * s;
    }
    __syncthreads();
    int row = blockIdx.x * 256 + threadIdx.x;
    const float4* zr = (const float4*)(g_z + (size_t)row * 16);
    float px = hpb2[0], py = hpb2[1];
#pragma unroll
    for (int q4 = 0; q4 < 4; q4++) {
        float4 v = zr[q4];
        float vv[4] = {v.x, v.y, v.z, v.w};
#pragma unroll
        for (int e = 0; e < 4; e++) {
            int j = q4 * 4 + e;
            float t = fmaxf(vv[e] * sc[j] + sh[j], 0.f);
            px += t * hpW2[j];
            py += t * hpW2[16 + j];
        }
    }
    float lx = fast_sig(px + g_last[2 * row]);
    float ly = fast_sig(py + g_last[2 * row + 1]);
    g_last[2 * row] = lx;
    g_last[2 * row + 1] = ly;
    out[2 * row]     = lx * scalar_f(pxm);
    out[2 * row + 1] = ly * scalar_f(pym);
    float s[5] = {lx, ly, lx * lx, ly * ly, lx * ly};
    int wid = threadIdx.x >> 5, lane = threadIdx.x & 31;
#pragma unroll
    for (int k = 0; k < 5; k++) s[k] = wred(s[k]);
    if (lane == 0) {
#pragma unroll
        for (int k = 0; k < 5; k++) red[wid][k] = s[k];
    }
    __syncthreads();
    if (wid == 0 && lane < 5) {
        float t = 0.f;
#pragma unroll
        for (int w = 0; w < 8; w++) t += red[w][lane];
        atomicAdd(&g_se_stats[lane], (double)t);
    }
}

// ---------------- launch ------------------------------------------------------
extern "C" void kernel_launch(void* const* d_in, const int* in_sizes, int n_in,
                              void* d_out, int out_size) {
    const float* obs  = (const float*)d_in[0];
    const float* seW1 = (const float*)d_in[1];
    const float* seb1 = (const float*)d_in[2];
    const float* seg  = (const float*)d_in[3];
    const float* seb  = (const float*)d_in[4];
    const float* seW2 = (const float*)d_in[5];
    const float* seb2 = (const float*)d_in[6];
    const float* hpW1 = (const float*)d_in[7];
    const float* hpb1 = (const float*)d_in[8];
    const float* hpg  = (const float*)d_in[9];
    const float* hpb  = (const float*)d_in[10];
    const float* hpW2 = (const float*)d_in[11];
    const float* hpb2 = (const float*)d_in[12];
    const float* Wih  = (const float*)d_in[13];
    const float* Whh  = (const float*)d_in[14];
    const float* bih  = (const float*)d_in[15];
    const float* bhh  = (const float*)d_in[16];
    const void*  pxm  = d_in[17];
    const void*  pym  = d_in[18];

    int B = in_sizes[0] / (T_OBS * 2);
    int TB = T_OBS * B;
    int predLen = out_size / (2 * B);
    float* out = (float*)d_out;

    cudaFuncSetAttribute(k_enc, cudaFuncAttributeMaxDynamicSharedMemorySize, ENC_SMEM);
    cudaFuncSetAttribute(k_dec, cudaFuncAttributeMaxDynamicSharedMemorySize, DEC_SMEM);

    k_prep<<<1, 256>>>(Wih, Whh, bih, bhh, seW2, seb2);
    k_moments<<<512, 256>>>(obs, pxm, pym, TB, B);
    k_enc<<<148, 512, ENC_SMEM>>>(obs, B, B / 64, seW1, seb1, seg, seb,
                                  pxm, pym, 1.0f / (float)TB);

    for (int s = 0; s < predLen; s++) {
        k_hp<<<B / 512, 256>>>(hpW1, hpb1, B);
        k_pos<<<B / 256, 256>>>(hpW2, hpb2, hpg, hpb, out + (size_t)s * B * 2,
                                pxm, pym, 1.0f / (float)B, B);
        if (s + 1 < predLen)
            k_dec<<<296, 256, DEC_SMEM>>>(B, B / 32, seW1, seb1, seg, seb,
                                          1.0f / (float)B);
    }
}

// round 14
// speedup vs baseline: 1.1272x; 1.0069x over previous
#include <cuda_runtime.h>
#include <cuda_bf16.h>
#include <math.h>

#define T_OBS 8
#define EPSBN 1e-5f

typedef unsigned int u32;
typedef unsigned long long u64;

#define MAXB 131072
#define WSTR 88   // padded k-stride (bf16): 176B rows, conflict-free ldmatrix

// ---------------- static device scratch ------------------------------------
__device__ float  g_h[MAXB * 64];
__device__ float  g_c[MAXB * 64];
__device__ float  g_z[MAXB * 16];
__device__ float  g_last[MAXB * 2];
__device__ __align__(16) __nv_bfloat16 g_Wh[256 * WSTR];
__device__ __align__(16) __nv_bfloat16 g_Wl[256 * WSTR];
__device__ float  g_bias[256];
__device__ double g_enc_stats[5];
__device__ double g_se_stats[5];
__device__ double g_hp_stats[32];

// ---------------- helpers ----------------------------------------------------
__device__ __forceinline__ float scalar_f(const void* p) {
    int iv = *(const int*)p;
    float fv = __int_as_float(iv);
    if (fv >= 1e-3f && fv <= 1e7f) return fv;
    return (float)iv;
}
__device__ __forceinline__ float fast_sig(float x) {
    float t; asm("ex2.approx.f32 %0, %1;" : "=f"(t) : "f"(-1.4426950408889634f * x));
    float r; asm("rcp.approx.f32 %0, %1;" : "=f"(r) : "f"(1.0f + t));
    return r;
}
// fused LSTM pointwise: 8 MUFU per cell
__device__ __forceinline__ void lstm_cell(float iv, float fv, float gv, float ov,
                                          float cold, float& cnew, float& hnew) {
    gv = fminf(fmaxf(gv, -30.f), 30.f);
    float tf; asm("ex2.approx.f32 %0, %1;" : "=f"(tf) : "f"(-1.4426950408889634f * fv));
    float sf; asm("rcp.approx.f32 %0, %1;" : "=f"(sf) : "f"(1.0f + tf));
    float ei; asm("ex2.approx.f32 %0, %1;" : "=f"(ei) : "f"(-1.4426950408889634f * iv));
    float eg; asm("ex2.approx.f32 %0, %1;" : "=f"(eg) : "f"(2.8853900817779268f * gv));
    float dig = (1.0f + ei) * (eg + 1.0f);
    float rig; asm("rcp.approx.f32 %0, %1;" : "=f"(rig) : "f"(dig));
    float c2 = sf * cold + (eg - 1.0f) * rig;
    cnew = c2;
    float eo; asm("ex2.approx.f32 %0, %1;" : "=f"(eo) : "f"(-1.4426950408889634f * ov));
    float ec; asm("ex2.approx.f32 %0, %1;" : "=f"(ec) : "f"(2.8853900817779268f * c2));
    float doc = (1.0f + eo) * (ec + 1.0f);
    float roc; asm("rcp.approx.f32 %0, %1;" : "=f"(roc) : "f"(doc));
    hnew = (ec - 1.0f) * roc;
}
__device__ __forceinline__ float wred(float v) {
#pragma unroll
    for (int o = 16; o > 0; o >>= 1) v += __shfl_down_sync(0xffffffffu, v, o);
    return v;
}
__device__ __forceinline__ u32 smem_u32(const void* p) {
    u32 a;
    asm("{ .reg .u64 t; cvta.to.shared.u64 t, %1; cvt.u32.u64 %0, t; }" : "=r"(a) : "l"(p));
    return a;
}
__device__ __forceinline__ void ldsm4(u32* r, u32 addr) {
    asm volatile("ldmatrix.sync.aligned.m8n8.x4.shared.b16 {%0,%1,%2,%3}, [%4];"
        : "=r"(r[0]), "=r"(r[1]), "=r"(r[2]), "=r"(r[3]) : "r"(addr));
}
__device__ __forceinline__ void mma16816(float* d, const u32* a, const u32* b) {
    asm volatile(
        "mma.sync.aligned.m16n8k16.row.col.f32.bf16.bf16.f32 "
        "{%0,%1,%2,%3},{%4,%5,%6,%7},{%8,%9},{%0,%1,%2,%3};"
        : "+f"(d[0]), "+f"(d[1]), "+f"(d[2]), "+f"(d[3])
        : "r"(a[0]), "r"(a[1]), "r"(a[2]), "r"(a[3]), "r"(b[0]), "r"(b[1]));
}
__device__ __forceinline__ u32 pack_bf16_hi(float a0, float a1) {
    __nv_bfloat16 h0 = __float2bfloat16(a0), h1 = __float2bfloat16(a1);
    return ((u32)__bfloat16_as_ushort(h1) << 16) | __bfloat16_as_ushort(h0);
}
__device__ __forceinline__ u32 pack_bf16_lo(float a0, float a1) {
    __nv_bfloat16 h0 = __float2bfloat16(a0), h1 = __float2bfloat16(a1);
    __nv_bfloat16 l0 = __float2bfloat16(a0 - __bfloat162float(h0));
    __nv_bfloat16 l1 = __float2bfloat16(a1 - __bfloat162float(h1));
    return ((u32)__bfloat16_as_ushort(l1) << 16) | __bfloat16_as_ushort(l0);
}

// ---------------- smem layouts ------------------------------------------------
#define O_WH   0                    // 45056
#define O_WL   45056                // 45056
// k_enc (256 thr, 2 CTA/SM, 32-row tiles, double-buffered A)
#define E_AB0  90112                // AH0; AL0=+5632; AH1=+11264; AL1=+16896
#define E_BIAS 112640               // 1024
#define E_FOLD 113664               // 192
#define ENC_SMEM 113856
// k_dec (256 thr, 2 CTA/SM, 32-row tiles, single A)
#define D_AH   90112                // 5632
#define D_AL   95744                // 5632
#define D_BIAS 101376               // 1024
#define D_FOLD 102400               // 192
#define DEC_SMEM 102592

// ---------------- prep: fold se_W2/se_b2 into Wih; bf16-split ---------------
__global__ void k_prep(const float* __restrict__ Wih, const float* __restrict__ Whh,
                       const float* __restrict__ bih, const float* __restrict__ bhh,
                       const float* __restrict__ seW2, const float* __restrict__ seb2) {
    int gc = threadIdx.x;
    if (gc < 5) g_enc_stats[gc] = 0.0;
    float wr[64];
#pragma unroll 8
    for (int m = 0; m < 64; m++) wr[m] = Wih[gc * 64 + m];
    float be = bih[gc] + bhh[gc];
#pragma unroll 8
    for (int m = 0; m < 64; m++) be += wr[m] * seb2[m];
    g_bias[gc] = be;
    for (int k = 0; k < WSTR; k++) {
        float w = 0.f;
        if (k < 16) {
#pragma unroll 8
            for (int m = 0; m < 64; m++) w += wr[m] * seW2[m * 16 + k];
        } else if (k < 80) {
            w = Whh[gc * 64 + (k - 16)];
        }
        __nv_bfloat16 hi = __float2bfloat16(w);
        __nv_bfloat16 lo = __float2bfloat16(w - __bfloat162float(hi));
        g_Wh[gc * WSTR + k] = hi;
        g_Wl[gc * WSTR + k] = lo;
    }
}

// ---------------- moments of normalized obs + init last_pos -----------------
__global__ void k_moments(const float* __restrict__ obs, const void* pxm, const void* pym,
                          int TB, int B) {
    __shared__ float red[8][5];
    float invx = 1.0f / scalar_f(pxm), invy = 1.0f / scalar_f(pym);
    int idx = blockIdx.x * blockDim.x + threadIdx.x;
    int stride = gridDim.x * blockDim.x;
    float s[5] = {0, 0, 0, 0, 0};
    for (int i = idx; i < TB; i += stride) {
        float x = obs[2 * i] * invx, y = obs[2 * i + 1] * invy;
        s[0] += x; s[1] += y; s[2] += x * x; s[3] += y * y; s[4] += x * y;
    }
    int wid = threadIdx.x >> 5, lane = threadIdx.x & 31;
#pragma unroll
    for (int k = 0; k < 5; k++) s[k] = wred(s[k]);
    if (lane == 0) {
#pragma unroll
        for (int k = 0; k < 5; k++) red[wid][k] = s[k];
    }
    __syncthreads();
    if (wid == 0 && lane < 5) {
        float t = 0.f;
#pragma unroll
        for (int w = 0; w < 8; w++) t += red[w][lane];
        atomicAdd(&g_enc_stats[lane], (double)t);
    }
    int off = TB - B;
    for (int i = idx; i < B; i += stride) {
        g_last[2 * i]     = obs[2 * (off + i)]     * invx;
        g_last[2 * i + 1] = obs[2 * (off + i) + 1] * invy;
    }
}

// ===== fused 8-step encoder: 256 thr, 32-row tiles, 2 CTAs/SM, dbl-buf A ====
__global__ void __launch_bounds__(256, 2)
k_enc(const float* __restrict__ obs, int B, int nTiles,
      const float* __restrict__ seW1, const float* __restrict__ seb1,
      const float* __restrict__ seg_, const float* __restrict__ seb_,
      const void* pxm, const void* pym, float Ninv) {
    extern __shared__ char sm[];
    float* bs = (float*)(sm + E_BIAS);
    float* fold = (float*)(sm + E_FOLD);
    u32 smb = smem_u32(sm);
    int tid = threadIdx.x, wid = tid >> 5, lane = tid & 31;

    {
        const float4* s1 = (const float4*)g_Wh;
        const float4* s2 = (const float4*)g_Wl;
        float4* d1 = (float4*)(sm + O_WH);
        float4* d2 = (float4*)(sm + O_WL);
        for (int i = tid; i < 2816; i += 256) { d1[i] = s1[i]; d2[i] = s2[i]; }
    }
    bs[tid] = g_bias[tid];
    if (blockIdx.x == 0 && tid < 32) g_hp_stats[tid] = 0.0;
    if (tid < 16) {   // encode BN fold (analytic, from 5 moments)
        const double* st = g_enc_stats;
        double mx = st[0] * Ninv, my = st[1] * Ninv;
        double vxx = st[2] * Ninv - mx * mx;
        double vyy = st[3] * Ninv - my * my;
        double cxy = st[4] * Ninv - mx * my;
        float w0 = seW1[2 * tid], w1 = seW1[2 * tid + 1];
        float mu = (float)(w0 * mx + w1 * my) + seb1[tid];
        float var = (float)((double)w0 * w0 * vxx + (double)w1 * w1 * vyy +
                            2.0 * (double)w0 * w1 * cxy);
        float sc = seg_[tid] * rsqrtf(var + EPSBN);
        float ix = 1.f / scalar_f(pxm), iy = 1.f / scalar_f(pym);
        fold[tid]      = w0 * sc * ix;
        fold[16 + tid] = w1 * sc * iy;
        fold[32 + tid] = (seb1[tid] - mu) * sc + seb_[tid];
    }
    __syncthreads();

    int wn = wid;
    int j0 = wn * 8 + (lane & 3) * 2;
    float bj[4][2];
#pragma unroll
    for (int g = 0; g < 4; g++) { bj[g][0] = bs[g * 64 + j0]; bj[g][1] = bs[g * 64 + j0 + 1]; }

    u32 bh[3][4][2];
    {
        u32 nrow = (u32)(wn * 8 + (lane & 7));
        u32 gsel = (u32)(((lane >> 4) & 1) * 64);
        u32 ksel = (u32)(((lane >> 3) & 1) * 16);
#pragma unroll
        for (int kt = 0; kt < 3; kt++) {
#pragma unroll
            for (int p = 0; p < 2; p++) {
                u32 r4[4];
                ldsm4(r4, smb + O_WH +
                      ((u32)(p * 2) * 64 + gsel + nrow) * (WSTR * 2) + ksel + (u32)(kt * 32));
                bh[kt][2 * p][0] = r4[0]; bh[kt][2 * p][1] = r4[1];
                bh[kt][2 * p + 1][0] = r4[2]; bh[kt][2 * p + 1][1] = r4[3];
            }
        }
    }

    u32 aRowOff = (u32)((lane & 15) * (WSTR * 2));
    u32 aColSel = (u32)(((lane >> 4) & 1) * 16);
    u32 bRow = (u32)(wn * 8 + (lane & 7));
    u32 bGsel = (u32)(((lane >> 4) & 1) * 64);
    u32 bKsel = (u32)(((lane >> 3) & 1) * 16);
    int srow = tid >> 3, seg8 = tid & 7, j2 = seg8 * 2;
    float fa0 = fold[j2], fb0 = fold[16 + j2], fc0 = fold[32 + j2];
    float fa1 = fold[j2 + 1], fb1 = fold[16 + j2 + 1], fc1 = fold[32 + j2 + 1];

    {   // prologue: stage feats t0 of first tile into buf0
        int r = blockIdx.x * 32 + srow;
        float2 xy0 = *(const float2*)(obs + 2 * (size_t)r);
        float f0 = fmaxf(fa0 * xy0.x + fb0 * xy0.y + fc0, 0.f);
        float f1 = fmaxf(fa1 * xy0.x + fb1 * xy0.y + fc1, 0.f);
        int off = srow * (WSTR * 2) + j2 * 2;
        *(u32*)(sm + E_AB0 + off) = pack_bf16_hi(f0, f1);
        *(u32*)(sm + E_AB0 + 5632 + off) = pack_bf16_lo(f0, f1);
    }

    for (int tile = blockIdx.x; tile < nTiles; tile += gridDim.x) {
        int row0 = tile * 32;
        int nxt = tile + gridDim.x;
        float creg[2][2][2];

        for (int t = 0; t < T_OBS; t++) {
            u32 ahb = smb + E_AB0 + (u32)((t & 1) * 11264);
            u32 alb = ahb + 5632;
            float2 nxy = make_float2(0.f, 0.f);
            if (t < T_OBS - 1) {
                nxy = *(const float2*)(obs + (size_t)(t + 1) * B * 2 + 2 * (size_t)(row0 + srow));
            } else if (nxt < nTiles) {
                nxy = *(const float2*)(obs + 2 * (size_t)(nxt * 32 + srow));
            }
            __syncthreads();

            float acc[2][4][4];
#pragma unroll
            for (int mt = 0; mt < 2; mt++)
#pragma unroll
                for (int g = 0; g < 4; g++)
#pragma unroll
                    for (int e = 0; e < 4; e++) acc[mt][g][e] = 0.f;
            int nkt = t ? 5 : 1;
#pragma unroll
            for (int kt = 0; kt < 5; kt++) {
                if (kt >= nkt) break;
                u32 kOff = (u32)(kt * 32);
                u32 ah0[4], ah1[4], al0[4], al1[4];
                u32 aAddr = ahb + aRowOff + aColSel + kOff;
                ldsm4(ah0, aAddr);
                ldsm4(ah1, aAddr + 16 * (WSTR * 2));
                u32 aAddrL = alb + aRowOff + aColSel + kOff;
                ldsm4(al0, aAddrL);
                ldsm4(al1, aAddrL + 16 * (WSTR * 2));
                u32 bl[4][2];
#pragma unroll
                for (int p = 0; p < 2; p++) {
                    u32 r4[4];
                    ldsm4(r4, smb + O_WL +
                          ((u32)(p * 2) * 64 + bGsel + bRow) * (WSTR * 2) + bKsel + kOff);
                    bl[2 * p][0] = r4[0]; bl[2 * p][1] = r4[1];
                    bl[2 * p + 1][0] = r4[2]; bl[2 * p + 1][1] = r4[3];
                }
                if (kt < 3) {
#pragma unroll
                    for (int g = 0; g < 4; g++) {
                        mma16816(acc[0][g], ah0, bh[kt][g]);
                        mma16816(acc[1][g], ah1, bh[kt][g]);
                        mma16816(acc[0][g], al0, bh[kt][g]);
                        mma16816(acc[1][g], al1, bh[kt][g]);
                        mma16816(acc[0][g], ah0, bl[g]);
                        mma16816(acc[1][g], ah1, bl[g]);
                    }
                } else {
                    u32 bhd[4][2];
#pragma unroll
                    for (int p = 0; p < 2; p++) {
                        u32 r4[4];
                        ldsm4(r4, smb + O_WH +
                              ((u32)(p * 2) * 64 + bGsel + bRow) * (WSTR * 2) + bKsel + kOff);
                        bhd[2 * p][0] = r4[0]; bhd[2 * p][1] = r4[1];
                        bhd[2 * p + 1][0] = r4[2]; bhd[2 * p + 1][1] = r4[3];
                    }
#pragma unroll
                    for (int g = 0; g < 4; g++) {
                        mma16816(acc[0][g], ah0, bhd[g]);
                        mma16816(acc[1][g], ah1, bhd[g]);
                        mma16816(acc[0][g], al0, bhd[g]);
                        mma16816(acc[1][g], al1, bhd[g]);
                        mma16816(acc[0][g], ah0, bl[g]);
                        mma16816(acc[1][g], ah1, bl[g]);
                    }
                }
            }

            float hn[2][2][2];
#pragma unroll
            for (int mt = 0; mt < 2; mt++)
#pragma unroll
                for (int rr = 0; rr < 2; rr++)
#pragma unroll
                    for (int cc = 0; cc < 2; cc++) {
                        int e = rr * 2 + cc;
                        float iv = acc[mt][0][e] + bj[0][cc];
                        float fv = acc[mt][1][e] + bj[1][cc];
                        float gv = acc[mt][2][e] + bj[2][cc];
                        float ov = acc[mt][3][e] + bj[3][cc];
                        float cold = t ? creg[mt][rr][cc] : 0.f;
                        lstm_cell(iv, fv, gv, ov, cold, creg[mt][rr][cc], hn[mt][rr][cc]);
                    }

            if (t < T_OBS - 1) {
                // write h + feats(t+1) into the OTHER buffer (its readers
                // finished before the sync at the top of this step)
                u32 ahn = smb + E_AB0 + (u32)(((t + 1) & 1) * 11264);
#pragma unroll
                for (int mt = 0; mt < 2; mt++)
#pragma unroll
                    for (int rr = 0; rr < 2; rr++) {
                        int lrow = mt * 16 + rr * 8 + (lane >> 2);
                        int off = lrow * (WSTR * 2) + (16 + j0) * 2;
                        *(u32*)(ahn - smb + sm + off) = pack_bf16_hi(hn[mt][rr][0], hn[mt][rr][1]);
                        *(u32*)(ahn + 5632 - smb + sm + off) = pack_bf16_lo(hn[mt][rr][0], hn[mt][rr][1]);
                    }
                float f0 = fmaxf(fa0 * nxy.x + fb0 * nxy.y + fc0, 0.f);
                float f1 = fmaxf(fa1 * nxy.x + fb1 * nxy.y + fc1, 0.f);
                int off = srow * (WSTR * 2) + j2 * 2;
                *(u32*)(ahn - smb + sm + off) = pack_bf16_hi(f0, f1);
                *(u32*)(ahn + 5632 - smb + sm + off) = pack_bf16_lo(f0, f1);
            } else {
#pragma unroll
                for (int mt = 0; mt < 2; mt++)
#pragma unroll
                    for (int rr = 0; rr < 2; rr++) {
                        int r = row0 + mt * 16 + rr * 8 + (lane >> 2);
                        *(float2*)(g_h + (size_t)r * 64 + j0) =
                            make_float2(hn[mt][rr][0], hn[mt][rr][1]);
                        *(float2*)(g_c + (size_t)r * 64 + j0) =
                            make_float2(creg[mt][rr][0], creg[mt][rr][1]);
                    }
                if (nxt < nTiles) {   // stage t0 feats of next tile into buf0
                    float f0 = fmaxf(fa0 * nxy.x + fb0 * nxy.y + fc0, 0.f);
                    float f1 = fmaxf(fa1 * nxy.x + fb1 * nxy.y + fc1, 0.f);
                    int off = srow * (WSTR * 2) + j2 * 2;
                    *(u32*)(sm + E_AB0 + off) = pack_bf16_hi(f0, f1);
                    *(u32*)(sm + E_AB0 + 5632 + off) = pack_bf16_lo(f0, f1);
                }
            }
        }
    }
}

// ======== decode LSTM step: 256 thr, 32-row tiles, 2 CTAs/SM ================
__global__ void __launch_bounds__(256, 2)
k_dec(int B, int nTiles,
      const float* __restrict__ seW1, const float* __restrict__ seb1,
      const float* __restrict__ seg_, const float* __restrict__ seb_, float Ninv) {
    extern __shared__ char sm[];
    float* bs = (float*)(sm + D_BIAS);
    float* fold = (float*)(sm + D_FOLD);
    u32 smb = smem_u32(sm);
    int tid = threadIdx.x, wid = tid >> 5, lane = tid & 31;

    {
        const float4* s1 = (const float4*)g_Wh;
        const float4* s2 = (const float4*)g_Wl;
        float4* d1 = (float4*)(sm + O_WH);
        float4* d2 = (float4*)(sm + O_WL);
        for (int i = tid; i < 2816; i += 256) { d1[i] = s1[i]; d2[i] = s2[i]; }
    }
    bs[tid] = g_bias[tid];
    if (blockIdx.x == 0 && tid < 32) g_hp_stats[tid] = 0.0;
    if (tid < 16) {   // decode BN fold from se stats
        const double* st = g_se_stats;
        double mx = st[0] * Ninv, my = st[1] * Ninv;
        double vxx = st[2] * Ninv - mx * mx;
        double vyy = st[3] * Ninv - my * my;
        double cxy = st[4] * Ninv - mx * my;
        float w0 = seW1[2 * tid], w1 = seW1[2 * tid + 1];
        float mu = (float)(w0 * mx + w1 * my) + seb1[tid];
        float var = (float)((double)w0 * w0 * vxx + (double)w1 * w1 * vyy +
                            2.0 * (double)w0 * w1 * cxy);
        float sc = seg_[tid] * rsqrtf(var + EPSBN);
        fold[tid]      = w0 * sc;
        fold[16 + tid] = w1 * sc;
        fold[32 + tid] = (seb1[tid] - mu) * sc + seb_[tid];
    }
    __syncthreads();

    int wn = wid;
    int j0 = wn * 8 + (lane & 3) * 2;
    float bj[4][2];
#pragma unroll
    for (int g = 0; g < 4; g++) { bj[g][0] = bs[g * 64 + j0]; bj[g][1] = bs[g * 64 + j0 + 1]; }

    u32 bh[3][4][2];
    {
        u32 nrow = (u32)(wn * 8 + (lane & 7));
        u32 gsel = (u32)(((lane >> 4) & 1) * 64);
        u32 ksel = (u32)(((lane >> 3) & 1) * 16);
#pragma unroll
        for (int kt = 0; kt < 3; kt++) {
#pragma unroll
            for (int p = 0; p < 2; p++) {
                u32 r4[4];
                ldsm4(r4, smb + O_WH +
                      ((u32)(p * 2) * 64 + gsel + nrow) * (WSTR * 2) + ksel + (u32)(kt * 32));
                bh[kt][2 * p][0] = r4[0]; bh[kt][2 * p][1] = r4[1];
                bh[kt][2 * p + 1][0] = r4[2]; bh[kt][2 * p + 1][1] = r4[3];
            }
        }
    }

    u32 aRowOff = (u32)((lane & 15) * (WSTR * 2));
    u32 aColSel = (u32)(((lane >> 4) & 1) * 16);
    u32 bRow = (u32)(wn * 8 + (lane & 7));
    u32 bGsel = (u32)(((lane >> 4) & 1) * 64);
    u32 bKsel = (u32)(((lane >> 3) & 1) * 16);
    int srow = tid >> 3, seg8 = tid & 7, j2 = seg8 * 2;
    float fa0 = fold[j2], fb0 = fold[16 + j2], fc0 = fold[32 + j2];
    float fa1 = fold[j2 + 1], fb1 = fold[16 + j2 + 1], fc1 = fold[32 + j2 + 1];

    {   // prologue: stage first 32-row tile
        int r = blockIdx.x * 32 + srow;
        const float4* hp = (const float4*)(g_h + (size_t)r * 64 + seg8 * 8);
        float4 h0 = hp[0], h1 = hp[1];
        float2 lp = *(const float2*)(g_last + 2 * (size_t)r);
        uint4 hi, lo;
        hi.x = pack_bf16_hi(h0.x, h0.y); lo.x = pack_bf16_lo(h0.x, h0.y);
        hi.y = pack_bf16_hi(h0.z, h0.w); lo.y = pack_bf16_lo(h0.z, h0.w);
        hi.z = pack_bf16_hi(h1.x, h1.y); lo.z = pack_bf16_lo(h1.x, h1.y);
        hi.w = pack_bf16_hi(h1.z, h1.w); lo.w = pack_bf16_lo(h1.z, h1.w);
        int off = srow * (WSTR * 2) + 32 + seg8 * 16;
        *(uint4*)(sm + D_AH + off) = hi;
        *(uint4*)(sm + D_AL + off) = lo;
        float f0 = fmaxf(fa0 * lp.x + fb0 * lp.y + fc0, 0.f);
        float f1 = fmaxf(fa1 * lp.x + fb1 * lp.y + fc1, 0.f);
        int offf = srow * (WSTR * 2) + j2 * 2;
        *(u32*)(sm + D_AH + offf) = pack_bf16_hi(f0, f1);
        *(u32*)(sm + D_AL + offf) = pack_bf16_lo(f0, f1);
    }

    for (int tile = blockIdx.x; tile < nTiles; tile += gridDim.x) {
        int row0 = tile * 32;
        int nxt = tile + gridDim.x;

        float4 nh0, nh1; float2 nlp;
        bool hasNext = (nxt < nTiles);
        if (hasNext) {
            int r = nxt * 32 + srow;
            const float4* hp = (const float4*)(g_h + (size_t)r * 64 + seg8 * 8);
            nh0 = hp[0]; nh1 = hp[1];
            nlp = *(const float2*)(g_last + 2 * (size_t)r);
        }
        float2 cpre[2][2];
#pragma unroll
        for (int mt = 0; mt < 2; mt++)
#pragma unroll
            for (int rr = 0; rr < 2; rr++) {
                int rw = row0 + mt * 16 + rr * 8 + (lane >> 2);
                cpre[mt][rr] = *(const float2*)(g_c + (size_t)rw * 64 + j0);
            }
        __syncthreads();

        float acc[2][4][4];
#pragma unroll
        for (int mt = 0; mt < 2; mt++)
#pragma unroll
            for (int g = 0; g < 4; g++)
#pragma unroll
                for (int e = 0; e < 4; e++) acc[mt][g][e] = 0.f;

#pragma unroll
        for (int kt = 0; kt < 5; kt++) {
            u32 kOff = (u32)(kt * 32);
            u32 ah0[4], ah1[4], al0[4], al1[4];
            u32 aAddr = smb + D_AH + aRowOff + aColSel + kOff;
            ldsm4(ah0, aAddr);
            ldsm4(ah1, aAddr + 16 * (WSTR * 2));
            u32 aAddrL = smb + D_AL + aRowOff + aColSel + kOff;
            ldsm4(al0, aAddrL);
            ldsm4(al1, aAddrL + 16 * (WSTR * 2));
            u32 bl[4][2];
#pragma unroll
            for (int p = 0; p < 2; p++) {
                u32 r4[4];
                ldsm4(r4, smb + O_WL +
                      ((u32)(p * 2) * 64 + bGsel + bRow) * (WSTR * 2) + bKsel + kOff);
                bl[2 * p][0] = r4[0]; bl[2 * p][1] = r4[1];
                bl[2 * p + 1][0] = r4[2]; bl[2 * p + 1][1] = r4[3];
            }
            if (kt < 3) {
#pragma unroll
                for (int g = 0; g < 4; g++) {
                    mma16816(acc[0][g], ah0, bh[kt][g]);
                    mma16816(acc[1][g], ah1, bh[kt][g]);
                    mma16816(acc[0][g], al0, bh[kt][g]);
                    mma16816(acc[1][g], al1, bh[kt][g]);
                    mma16816(acc[0][g], ah0, bl[g]);
                    mma16816(acc[1][g], ah1, bl[g]);
                }
            } else {
                u32 bhd[4][2];
#pragma unroll
                for (int p = 0; p < 2; p++) {
                    u32 r4[4];
                    ldsm4(r4, smb + O_WH +
                          ((u32)(p * 2) * 64 + bGsel + bRow) * (WSTR * 2) + bKsel + kOff);
                    bhd[2 * p][0] = r4[0]; bhd[2 * p][1] = r4[1];
                    bhd[2 * p + 1][0] = r4[2]; bhd[2 * p + 1][1] = r4[3];
                }
#pragma unroll
                for (int g = 0; g < 4; g++) {
                    mma16816(acc[0][g], ah0, bhd[g]);
                    mma16816(acc[1][g], ah1, bhd[g]);
                    mma16816(acc[0][g], al0, bhd[g]);
                    mma16816(acc[1][g], al1, bhd[g]);
                    mma16816(acc[0][g], ah0, bl[g]);
                    mma16816(acc[1][g], ah1, bl[g]);
                }
            }
        }

        // epilogue: pointwise -> global h, c (c was prefetched)
#pragma unroll
        for (int mt = 0; mt < 2; mt++)
#pragma unroll
            for (int rr = 0; rr < 2; rr++) {
                int rw = row0 + mt * 16 + rr * 8 + (lane >> 2);
                float2 c2 = cpre[mt][rr];
                float cn[2], hn[2];
#pragma unroll
                for (int cc = 0; cc < 2; cc++) {
                    int e = rr * 2 + cc;
                    float iv = acc[mt][0][e] + bj[0][cc];
                    float fv = acc[mt][1][e] + bj[1][cc];
                    float gv = acc[mt][2][e] + bj[2][cc];
                    float ov = acc[mt][3][e] + bj[3][cc];
                    lstm_cell(iv, fv, gv, ov, cc ? c2.y : c2.x, cn[cc], hn[cc]);
                }
                *(float2*)(g_c + (size_t)rw * 64 + j0) = make_float2(cn[0], cn[1]);
                *(float2*)(g_h + (size_t)rw * 64 + j0) = make_float2(hn[0], hn[1]);
            }

        __syncthreads();
        if (hasNext) {
            uint4 hi, lo;
            hi.x = pack_bf16_hi(nh0.x, nh0.y); lo.x = pack_bf16_lo(nh0.x, nh0.y);
            hi.y = pack_bf16_hi(nh0.z, nh0.w); lo.y = pack_bf16_lo(nh0.z, nh0.w);
            hi.z = pack_bf16_hi(nh1.x, nh1.y); lo.z = pack_bf16_lo(nh1.x, nh1.y);
            hi.w = pack_bf16_hi(nh1.z, nh1.w); lo.w = pack_bf16_lo(nh1.z, nh1.w);
            int off = srow * (WSTR * 2) + 32 + seg8 * 16;
            *(uint4*)(sm + D_AH + off) = hi;
            *(uint4*)(sm + D_AL + off) = lo;
            float f0 = fmaxf(fa0 * nlp.x + fb0 * nlp.y + fc0, 0.f);
            float f1 = fmaxf(fa1 * nlp.x + fb1 * nlp.y + fc1, 0.f);
            int offf = srow * (WSTR * 2) + j2 * 2;
            *(u32*)(sm + D_AH + offf) = pack_bf16_hi(f0, f1);
            *(u32*)(sm + D_AL + offf) = pack_bf16_lo(f0, f1);
        }
    }
}

// ---------------- hidden2pos proj + stats (2 rows/thread) --------------------
__global__ void k_hp(const float* __restrict__ hpW1, const float* __restrict__ hpb1, int B) {
    __shared__ float Ws[1024];
    __shared__ float red[8][32];
    for (int i = threadIdx.x; i < 1024; i += 256) Ws[i] = hpW1[i];
    if (blockIdx.x == 0 && threadIdx.x < 5) g_se_stats[threadIdx.x] = 0.0;
    __syncthreads();
    int r0 = (blockIdx.x * 256 + threadIdx.x) * 2;
    float z0[16], z1[16];
#pragma unroll
    for (int jj = 0; jj < 16; jj++) { float b = hpb1[jj]; z0[jj] = b; z1[jj] = b; }
    const float4* ha = (const float4*)(g_h + (size_t)r0 * 64);
    const float4* hb = (const float4*)(g_h + (size_t)(r0 + 1) * 64);
#pragma unroll 4
    for (int kk = 0; kk < 16; kk++) {
        float4 a = ha[kk], b = hb[kk];
#pragma unroll
        for (int jj = 0; jj < 16; jj++) {
            const float* w = &Ws[jj * 64 + 4 * kk];
            z0[jj] += a.x * w[0] + a.y * w[1] + a.z * w[2] + a.w * w[3];
            z1[jj] += b.x * w[0] + b.y * w[1] + b.z * w[2] + b.w * w[3];
        }
    }
    float4* zo = (float4*)(g_z + (size_t)r0 * 16);
    zo[0] = make_float4(z0[0], z0[1], z0[2], z0[3]);
    zo[1] = make_float4(z0[4], z0[5], z0[6], z0[7]);
    zo[2] = make_float4(z0[8], z0[9], z0[10], z0[11]);
    zo[3] = make_float4(z0[12], z0[13], z0[14], z0[15]);
    zo[4] = make_float4(z1[0], z1[1], z1[2], z1[3]);
    zo[5] = make_float4(z1[4], z1[5], z1[6], z1[7]);
    zo[6] = make_float4(z1[8], z1[9], z1[10], z1[11]);
    zo[7] = make_float4(z1[12], z1[13], z1[14], z1[15]);
    float sv[16], qv[16];
#pragma unroll
    for (int jj = 0; jj < 16; jj++) {
        sv[jj] = z0[jj] + z1[jj];
        qv[jj] = z0[jj] * z0[jj] + z1[jj] * z1[jj];
    }
    int wid = threadIdx.x >> 5, lane = threadIdx.x & 31;
#pragma unroll
    for (int jj = 0; jj < 16; jj++) { sv[jj] = wred(sv[jj]); qv[jj] = wred(qv[jj]); }
    if (lane == 0) {
#pragma unroll
        for (int jj = 0; jj < 16; jj++) { red[wid][jj] = sv[jj]; red[wid][16 + jj] = qv[jj]; }
    }
    __syncthreads();
    if (wid == 0) {
        float t = 0.f;
#pragma unroll
        for (int w = 0; w < 8; w++) t += red[w][lane];
        atomicAdd(&g_hp_stats[lane], (double)t);
    }
}

// ---------------- positions: BN(inline)+relu+W2, sigmoid, out, se moments ---
__global__ void k_pos(const float* __restrict__ hpW2, const float* __restrict__ hpb2,
                      const float* __restrict__ gamma, const float* __restrict__ beta,
                      float* __restrict__ out, const void* pxm, const void* pym,
                      float Binv, int B) {
    __shared__ float sc[16], sh[16];
    __shared__ float red[8][5];
    if (threadIdx.x < 16) {
        int j = threadIdx.x;
        double mu = g_hp_stats[j] * Binv;
        double var = g_hp_stats[16 + j] * Binv - mu * mu;
        float s = gamma[j] * rsqrtf((float)var + EPSBN);
        sc[j] = s;
        sh[j] = beta[j] - (float)mu * s;
    }
    __syncthreads();
    int row = blockIdx.x * 256 + threadIdx.x;
    const float4* zr = (const float4*)(g_z + (size_t)row * 16);
    float px = hpb2[0], py = hpb2[1];
#pragma unroll
    for (int q4 = 0; q4 < 4; q4++) {
        float4 v = zr[q4];
        float vv[4] = {v.x, v.y, v.z, v.w};
#pragma unroll
        for (int e = 0; e < 4; e++) {
            int j = q4 * 4 + e;
            float t = fmaxf(vv[e] * sc[j] + sh[j], 0.f);
            px += t * hpW2[j];
            py += t * hpW2[16 + j];
        }
    }
    float lx = fast_sig(px + g_last[2 * row]);
    float ly = fast_sig(py + g_last[2 * row + 1]);
    g_last[2 * row] = lx;
    g_last[2 * row + 1] = ly;
    out[2 * row]     = lx * scalar_f(pxm);
    out[2 * row + 1] = ly * scalar_f(pym);
    float s[5] = {lx, ly, lx * lx, ly * ly, lx * ly};
    int wid = threadIdx.x >> 5, lane = threadIdx.x & 31;
#pragma unroll
    for (int k = 0; k < 5; k++) s[k] = wred(s[k]);
    if (lane == 0) {
#pragma unroll
        for (int k = 0; k < 5; k++) red[wid][k] = s[k];
    }
    __syncthreads();
    if (wid == 0 && lane < 5) {
        float t = 0.f;
#pragma unroll
        for (int w = 0; w < 8; w++) t += red[w][lane];
        atomicAdd(&g_se_stats[lane], (double)t);
    }
}

// ---------------- launch ------------------------------------------------------
extern "C" void kernel_launch(void* const* d_in, const int* in_sizes, int n_in,
                              void* d_out, int out_size) {
    const float* obs  = (const float*)d_in[0];
    const float* seW1 = (const float*)d_in[1];
    const float* seb1 = (const float*)d_in[2];
    const float* seg  = (const float*)d_in[3];
    const float* seb  = (const float*)d_in[4];
    const float* seW2 = (const float*)d_in[5];
    const float* seb2 = (const float*)d_in[6];
    const float* hpW1 = (const float*)d_in[7];
    const float* hpb1 = (const float*)d_in[8];
    const float* hpg  = (const float*)d_in[9];
    const float* hpb  = (const float*)d_in[10];
    const float* hpW2 = (const float*)d_in[11];
    const float* hpb2 = (const float*)d_in[12];
    const float* Wih  = (const float*)d_in[13];
    const float* Whh  = (const float*)d_in[14];
    const float* bih  = (const float*)d_in[15];
    const float* bhh  = (const float*)d_in[16];
    const void*  pxm  = d_in[17];
    const void*  pym  = d_in[18];

    int B = in_sizes[0] / (T_OBS * 2);
    int TB = T_OBS * B;
    int predLen = out_size / (2 * B);
    float* out = (float*)d_out;

    cudaFuncSetAttribute(k_enc, cudaFuncAttributeMaxDynamicSharedMemorySize, ENC_SMEM);
    cudaFuncSetAttribute(k_dec, cudaFuncAttributeMaxDynamicSharedMemorySize, DEC_SMEM);

    k_prep<<<1, 256>>>(Wih, Whh, bih, bhh, seW2, seb2);
    k_moments<<<512, 256>>>(obs, pxm, pym, TB, B);
    k_enc<<<296, 256, ENC_SMEM>>>(obs, B, B / 32, seW1, seb1, seg, seb,
                                  pxm, pym, 1.0f / (float)TB);

    for (int s = 0; s < predLen; s++) {
        k_hp<<<B / 512, 256>>>(hpW1, hpb1, B);
        k_pos<<<B / 256, 256>>>(hpW2, hpb2, hpg, hpb, out + (size_t)s * B * 2,
                                pxm, pym, 1.0f / (float)B, B);
        if (s + 1 < predLen)
            k_dec<<<296, 256, DEC_SMEM>>>(B, B / 32, seW1, seb1, seg, seb,
                                          1.0f / (float)B);
    }
}

// round 15
// speedup vs baseline: 1.1414x; 1.0126x over previous
#include <cuda_runtime.h>
#include <cuda_bf16.h>
#include <math.h>

#define T_OBS 8
#define EPSBN 1e-5f

typedef unsigned int u32;
typedef unsigned long long u64;

#define MAXB 131072
#define WSTR 88   // padded k-stride (bf16): 176B rows, conflict-free ldmatrix

// ---------------- static device scratch ------------------------------------
__device__ float  g_h[MAXB * 64];
__device__ float  g_c[MAXB * 64];
__device__ float  g_last[MAXB * 2];
__device__ __align__(16) __nv_bfloat16 g_Wh[256 * WSTR];
__device__ __align__(16) __nv_bfloat16 g_Wl[256 * WSTR];
__device__ float  g_bias[256];
__device__ double g_enc_stats[5];
__device__ double g_se_stats[5];
__device__ double g_hp_stats[32];
__device__ u32    g_barc = 0;
__device__ u32    g_barg = 0;

// ---------------- helpers ----------------------------------------------------
__device__ __forceinline__ float scalar_f(const void* p) {
    int iv = *(const int*)p;
    float fv = __int_as_float(iv);
    if (fv >= 1e-3f && fv <= 1e7f) return fv;
    return (float)iv;
}
__device__ __forceinline__ float fast_sig(float x) {
    float t; asm("ex2.approx.f32 %0, %1;" : "=f"(t) : "f"(-1.4426950408889634f * x));
    float r; asm("rcp.approx.f32 %0, %1;" : "=f"(r) : "f"(1.0f + t));
    return r;
}
// fused LSTM pointwise: 8 MUFU per cell
__device__ __forceinline__ void lstm_cell(float iv, float fv, float gv, float ov,
                                          float cold, float& cnew, float& hnew) {
    gv = fminf(fmaxf(gv, -30.f), 30.f);
    float tf; asm("ex2.approx.f32 %0, %1;" : "=f"(tf) : "f"(-1.4426950408889634f * fv));
    float sf; asm("rcp.approx.f32 %0, %1;" : "=f"(sf) : "f"(1.0f + tf));
    float ei; asm("ex2.approx.f32 %0, %1;" : "=f"(ei) : "f"(-1.4426950408889634f * iv));
    float eg; asm("ex2.approx.f32 %0, %1;" : "=f"(eg) : "f"(2.8853900817779268f * gv));
    float dig = (1.0f + ei) * (eg + 1.0f);
    float rig; asm("rcp.approx.f32 %0, %1;" : "=f"(rig) : "f"(dig));
    float c2 = sf * cold + (eg - 1.0f) * rig;
    cnew = c2;
    float eo; asm("ex2.approx.f32 %0, %1;" : "=f"(eo) : "f"(-1.4426950408889634f * ov));
    float ec; asm("ex2.approx.f32 %0, %1;" : "=f"(ec) : "f"(2.8853900817779268f * c2));
    float doc = (1.0f + eo) * (ec + 1.0f);
    float roc; asm("rcp.approx.f32 %0, %1;" : "=f"(roc) : "f"(doc));
    hnew = (ec - 1.0f) * roc;
}
__device__ __forceinline__ float wred(float v) {
#pragma unroll
    for (int o = 16; o > 0; o >>= 1) v += __shfl_down_sync(0xffffffffu, v, o);
    return v;
}
__device__ __forceinline__ u32 smem_u32(const void* p) {
    u32 a;
    asm("{ .reg .u64 t; cvta.to.shared.u64 t, %1; cvt.u32.u64 %0, t; }" : "=r"(a) : "l"(p));
    return a;
}
__device__ __forceinline__ void ldsm4(u32* r, u32 addr) {
    asm volatile("ldmatrix.sync.aligned.m8n8.x4.shared.b16 {%0,%1,%2,%3}, [%4];"
        : "=r"(r[0]), "=r"(r[1]), "=r"(r[2]), "=r"(r[3]) : "r"(addr));
}
__device__ __forceinline__ void mma16816(float* d, const u32* a, const u32* b) {
    asm volatile(
        "mma.sync.aligned.m16n8k16.row.col.f32.bf16.bf16.f32 "
        "{%0,%1,%2,%3},{%4,%5,%6,%7},{%8,%9},{%0,%1,%2,%3};"
        : "+f"(d[0]), "+f"(d[1]), "+f"(d[2]), "+f"(d[3])
        : "r"(a[0]), "r"(a[1]), "r"(a[2]), "r"(a[3]), "r"(b[0]), "r"(b[1]));
}
__device__ __forceinline__ u32 pack_bf16_hi(float a0, float a1) {
    __nv_bfloat16 h0 = __float2bfloat16(a0), h1 = __float2bfloat16(a1);
    return ((u32)__bfloat16_as_ushort(h1) << 16) | __bfloat16_as_ushort(h0);
}
__device__ __forceinline__ u32 pack_bf16_lo(float a0, float a1) {
    __nv_bfloat16 h0 = __float2bfloat16(a0), h1 = __float2bfloat16(a1);
    __nv_bfloat16 l0 = __float2bfloat16(a0 - __bfloat162float(h0));
    __nv_bfloat16 l1 = __float2bfloat16(a1 - __bfloat162float(h1));
    return ((u32)__bfloat16_as_ushort(l1) << 16) | __bfloat16_as_ushort(l0);
}
__device__ __forceinline__ double vload(const double* p) {
    return *(volatile const double*)p;
}
__device__ __forceinline__ void grid_barrier() {
    __syncthreads();
    if (threadIdx.x == 0) {
        __threadfence();
        u32 gen = *(volatile u32*)&g_barg;
        u32 old = atomicAdd(&g_barc, 1);
        if (old == gridDim.x - 1) {
            atomicExch(&g_barc, 0);
            __threadfence();
            atomicExch(&g_barg, gen + 1);
        } else {
            while (*(volatile u32*)&g_barg == gen) { __nanosleep(64); }
        }
        __threadfence();
    }
    __syncthreads();
}

// ---------------- smem layouts ------------------------------------------------
#define O_WH   0                    // 45056
#define O_WL   45056                // 45056
// k_enc (256 thr, 2 CTA/SM, 32-row tiles, double-buffered A)
#define E_AB0  90112                // AH0; AL0=+5632; AH1=+11264; AL1=+16896
#define E_BIAS 112640               // 1024
#define E_FOLD 113664               // 192
#define ENC_SMEM 113856
// k_dec (256 thr, 2 CTA/SM, 32-row tiles, single A)
#define D_AH   90112                // 5632
#define D_AL   95744                // 5632
#define D_BIAS 101376               // 1024
#define D_FOLD 102400               // 192
#define DEC_SMEM 102592

// ---------------- prep: fold se_W2/se_b2 into Wih; bf16-split ---------------
__global__ void k_prep(const float* __restrict__ Wih, const float* __restrict__ Whh,
                       const float* __restrict__ bih, const float* __restrict__ bhh,
                       const float* __restrict__ seW2, const float* __restrict__ seb2) {
    int gc = threadIdx.x;
    if (gc < 5) g_enc_stats[gc] = 0.0;
    float wr[64];
#pragma unroll 8
    for (int m = 0; m < 64; m++) wr[m] = Wih[gc * 64 + m];
    float be = bih[gc] + bhh[gc];
#pragma unroll 8
    for (int m = 0; m < 64; m++) be += wr[m] * seb2[m];
    g_bias[gc] = be;
    for (int k = 0; k < WSTR; k++) {
        float w = 0.f;
        if (k < 16) {
#pragma unroll 8
            for (int m = 0; m < 64; m++) w += wr[m] * seW2[m * 16 + k];
        } else if (k < 80) {
            w = Whh[gc * 64 + (k - 16)];
        }
        __nv_bfloat16 hi = __float2bfloat16(w);
        __nv_bfloat16 lo = __float2bfloat16(w - __bfloat162float(hi));
        g_Wh[gc * WSTR + k] = hi;
        g_Wl[gc * WSTR + k] = lo;
    }
}

// ---------------- moments of normalized obs + init last_pos -----------------
__global__ void k_moments(const float* __restrict__ obs, const void* pxm, const void* pym,
                          int TB, int B) {
    __shared__ float red[8][5];
    float invx = 1.0f / scalar_f(pxm), invy = 1.0f / scalar_f(pym);
    int idx = blockIdx.x * blockDim.x + threadIdx.x;
    int stride = gridDim.x * blockDim.x;
    float s[5] = {0, 0, 0, 0, 0};
    for (int i = idx; i < TB; i += stride) {
        float x = obs[2 * i] * invx, y = obs[2 * i + 1] * invy;
        s[0] += x; s[1] += y; s[2] += x * x; s[3] += y * y; s[4] += x * y;
    }
    int wid = threadIdx.x >> 5, lane = threadIdx.x & 31;
#pragma unroll
    for (int k = 0; k < 5; k++) s[k] = wred(s[k]);
    if (lane == 0) {
#pragma unroll
        for (int k = 0; k < 5; k++) red[wid][k] = s[k];
    }
    __syncthreads();
    if (wid == 0 && lane < 5) {
        float t = 0.f;
#pragma unroll
        for (int w = 0; w < 8; w++) t += red[w][lane];
        atomicAdd(&g_enc_stats[lane], (double)t);
    }
    int off = TB - B;
    for (int i = idx; i < B; i += stride) {
        g_last[2 * i]     = obs[2 * (off + i)]     * invx;
        g_last[2 * i + 1] = obs[2 * (off + i) + 1] * invy;
    }
}

// ===== fused 8-step encoder: 256 thr, 32-row tiles, 2 CTAs/SM, dbl-buf A ====
__global__ void __launch_bounds__(256, 2)
k_enc(const float* __restrict__ obs, int B, int nTiles,
      const float* __restrict__ seW1, const float* __restrict__ seb1,
      const float* __restrict__ seg_, const float* __restrict__ seb_,
      const void* pxm, const void* pym, float Ninv) {
    extern __shared__ char sm[];
    float* bs = (float*)(sm + E_BIAS);
    float* fold = (float*)(sm + E_FOLD);
    u32 smb = smem_u32(sm);
    int tid = threadIdx.x, wid = tid >> 5, lane = tid & 31;

    {
        const float4* s1 = (const float4*)g_Wh;
        const float4* s2 = (const float4*)g_Wl;
        float4* d1 = (float4*)(sm + O_WH);
        float4* d2 = (float4*)(sm + O_WL);
        for (int i = tid; i < 2816; i += 256) { d1[i] = s1[i]; d2[i] = s2[i]; }
    }
    bs[tid] = g_bias[tid];
    if (blockIdx.x == 0 && tid < 32) g_hp_stats[tid] = 0.0;
    if (tid < 16) {   // encode BN fold (analytic, from 5 moments)
        const double* st = g_enc_stats;
        double mx = st[0] * Ninv, my = st[1] * Ninv;
        double vxx = st[2] * Ninv - mx * mx;
        double vyy = st[3] * Ninv - my * my;
        double cxy = st[4] * Ninv - mx * my;
        float w0 = seW1[2 * tid], w1 = seW1[2 * tid + 1];
        float mu = (float)(w0 * mx + w1 * my) + seb1[tid];
        float var = (float)((double)w0 * w0 * vxx + (double)w1 * w1 * vyy +
                            2.0 * (double)w0 * w1 * cxy);
        float sc = seg_[tid] * rsqrtf(var + EPSBN);
        float ix = 1.f / scalar_f(pxm), iy = 1.f / scalar_f(pym);
        fold[tid]      = w0 * sc * ix;
        fold[16 + tid] = w1 * sc * iy;
        fold[32 + tid] = (seb1[tid] - mu) * sc + seb_[tid];
    }
    __syncthreads();

    int wn = wid;
    int j0 = wn * 8 + (lane & 3) * 2;
    float bj[4][2];
#pragma unroll
    for (int g = 0; g < 4; g++) { bj[g][0] = bs[g * 64 + j0]; bj[g][1] = bs[g * 64 + j0 + 1]; }

    u32 bh[3][4][2];
    {
        u32 nrow = (u32)(wn * 8 + (lane & 7));
        u32 gsel = (u32)(((lane >> 4) & 1) * 64);
        u32 ksel = (u32)(((lane >> 3) & 1) * 16);
#pragma unroll
        for (int kt = 0; kt < 3; kt++) {
#pragma unroll
            for (int p = 0; p < 2; p++) {
                u32 r4[4];
                ldsm4(r4, smb + O_WH +
                      ((u32)(p * 2) * 64 + gsel + nrow) * (WSTR * 2) + ksel + (u32)(kt * 32));
                bh[kt][2 * p][0] = r4[0]; bh[kt][2 * p][1] = r4[1];
                bh[kt][2 * p + 1][0] = r4[2]; bh[kt][2 * p + 1][1] = r4[3];
            }
        }
    }

    u32 aRowOff = (u32)((lane & 15) * (WSTR * 2));
    u32 aColSel = (u32)(((lane >> 4) & 1) * 16);
    u32 bRow = (u32)(wn * 8 + (lane & 7));
    u32 bGsel = (u32)(((lane >> 4) & 1) * 64);
    u32 bKsel = (u32)(((lane >> 3) & 1) * 16);
    int srow = tid >> 3, seg8 = tid & 7, j2 = seg8 * 2;
    float fa0 = fold[j2], fb0 = fold[16 + j2], fc0 = fold[32 + j2];
    float fa1 = fold[j2 + 1], fb1 = fold[16 + j2 + 1], fc1 = fold[32 + j2 + 1];

    {   // prologue: stage feats t0 of first tile into buf0
        int r = blockIdx.x * 32 + srow;
        float2 xy0 = *(const float2*)(obs + 2 * (size_t)r);
        float f0 = fmaxf(fa0 * xy0.x + fb0 * xy0.y + fc0, 0.f);
        float f1 = fmaxf(fa1 * xy0.x + fb1 * xy0.y + fc1, 0.f);
        int off = srow * (WSTR * 2) + j2 * 2;
        *(u32*)(sm + E_AB0 + off) = pack_bf16_hi(f0, f1);
        *(u32*)(sm + E_AB0 + 5632 + off) = pack_bf16_lo(f0, f1);
    }

    for (int tile = blockIdx.x; tile < nTiles; tile += gridDim.x) {
        int row0 = tile * 32;
        int nxt = tile + gridDim.x;
        float creg[2][2][2];

        for (int t = 0; t < T_OBS; t++) {
            u32 ahb = smb + E_AB0 + (u32)((t & 1) * 11264);
            u32 alb = ahb + 5632;
            float2 nxy = make_float2(0.f, 0.f);
            if (t < T_OBS - 1) {
                nxy = *(const float2*)(obs + (size_t)(t + 1) * B * 2 + 2 * (size_t)(row0 + srow));
            } else if (nxt < nTiles) {
                nxy = *(const float2*)(obs + 2 * (size_t)(nxt * 32 + srow));
            }
            __syncthreads();

            float acc[2][4][4];
#pragma unroll
            for (int mt = 0; mt < 2; mt++)
#pragma unroll
                for (int g = 0; g < 4; g++)
#pragma unroll
                    for (int e = 0; e < 4; e++) acc[mt][g][e] = 0.f;
            int nkt = t ? 5 : 1;
#pragma unroll
            for (int kt = 0; kt < 5; kt++) {
                if (kt >= nkt) break;
                u32 kOff = (u32)(kt * 32);
                u32 ah0[4], ah1[4], al0[4], al1[4];
                u32 aAddr = ahb + aRowOff + aColSel + kOff;
                ldsm4(ah0, aAddr);
                ldsm4(ah1, aAddr + 16 * (WSTR * 2));
                u32 aAddrL = alb + aRowOff + aColSel + kOff;
                ldsm4(al0, aAddrL);
                ldsm4(al1, aAddrL + 16 * (WSTR * 2));
                u32 bl[4][2];
#pragma unroll
                for (int p = 0; p < 2; p++) {
                    u32 r4[4];
                    ldsm4(r4, smb + O_WL +
                          ((u32)(p * 2) * 64 + bGsel + bRow) * (WSTR * 2) + bKsel + kOff);
                    bl[2 * p][0] = r4[0]; bl[2 * p][1] = r4[1];
                    bl[2 * p + 1][0] = r4[2]; bl[2 * p + 1][1] = r4[3];
                }
                if (kt < 3) {
#pragma unroll
                    for (int g = 0; g < 4; g++) {
                        mma16816(acc[0][g], ah0, bh[kt][g]);
                        mma16816(acc[1][g], ah1, bh[kt][g]);
                        mma16816(acc[0][g], al0, bh[kt][g]);
                        mma16816(acc[1][g], al1, bh[kt][g]);
                        mma16816(acc[0][g], ah0, bl[g]);
                        mma16816(acc[1][g], ah1, bl[g]);
                    }
                } else {
                    u32 bhd[4][2];
#pragma unroll
                    for (int p = 0; p < 2; p++) {
                        u32 r4[4];
                        ldsm4(r4, smb + O_WH +
                              ((u32)(p * 2) * 64 + bGsel + bRow) * (WSTR * 2) + bKsel + kOff);
                        bhd[2 * p][0] = r4[0]; bhd[2 * p][1] = r4[1];
                        bhd[2 * p + 1][0] = r4[2]; bhd[2 * p + 1][1] = r4[3];
                    }
#pragma unroll
                    for (int g = 0; g < 4; g++) {
                        mma16816(acc[0][g], ah0, bhd[g]);
                        mma16816(acc[1][g], ah1, bhd[g]);
                        mma16816(acc[0][g], al0, bhd[g]);
                        mma16816(acc[1][g], al1, bhd[g]);
                        mma16816(acc[0][g], ah0, bl[g]);
                        mma16816(acc[1][g], ah1, bl[g]);
                    }
                }
            }

            float hn[2][2][2];
#pragma unroll
            for (int mt = 0; mt < 2; mt++)
#pragma unroll
                for (int rr = 0; rr < 2; rr++)
#pragma unroll
                    for (int cc = 0; cc < 2; cc++) {
                        int e = rr * 2 + cc;
                        float iv = acc[mt][0][e] + bj[0][cc];
                        float fv = acc[mt][1][e] + bj[1][cc];
                        float gv = acc[mt][2][e] + bj[2][cc];
                        float ov = acc[mt][3][e] + bj[3][cc];
                        float cold = t ? creg[mt][rr][cc] : 0.f;
                        lstm_cell(iv, fv, gv, ov, cold, creg[mt][rr][cc], hn[mt][rr][cc]);
                    }

            if (t < T_OBS - 1) {
                u32 ahn = smb + E_AB0 + (u32)(((t + 1) & 1) * 11264);
#pragma unroll
                for (int mt = 0; mt < 2; mt++)
#pragma unroll
                    for (int rr = 0; rr < 2; rr++) {
                        int lrow = mt * 16 + rr * 8 + (lane >> 2);
                        int off = lrow * (WSTR * 2) + (16 + j0) * 2;
                        *(u32*)(ahn - smb + sm + off) = pack_bf16_hi(hn[mt][rr][0], hn[mt][rr][1]);
                        *(u32*)(ahn + 5632 - smb + sm + off) = pack_bf16_lo(hn[mt][rr][0], hn[mt][rr][1]);
                    }
                float f0 = fmaxf(fa0 * nxy.x + fb0 * nxy.y + fc0, 0.f);
                float f1 = fmaxf(fa1 * nxy.x + fb1 * nxy.y + fc1, 0.f);
                int off = srow * (WSTR * 2) + j2 * 2;
                *(u32*)(ahn - smb + sm + off) = pack_bf16_hi(f0, f1);
                *(u32*)(ahn + 5632 - smb + sm + off) = pack_bf16_lo(f0, f1);
            } else {
#pragma unroll
                for (int mt = 0; mt < 2; mt++)
#pragma unroll
                    for (int rr = 0; rr < 2; rr++) {
                        int r = row0 + mt * 16 + rr * 8 + (lane >> 2);
                        *(float2*)(g_h + (size_t)r * 64 + j0) =
                            make_float2(hn[mt][rr][0], hn[mt][rr][1]);
                        *(float2*)(g_c + (size_t)r * 64 + j0) =
                            make_float2(creg[mt][rr][0], creg[mt][rr][1]);
                    }
                if (nxt < nTiles) {
                    float f0 = fmaxf(fa0 * nxy.x + fb0 * nxy.y + fc0, 0.f);
                    float f1 = fmaxf(fa1 * nxy.x + fb1 * nxy.y + fc1, 0.f);
                    int off = srow * (WSTR * 2) + j2 * 2;
                    *(u32*)(sm + E_AB0 + off) = pack_bf16_hi(f0, f1);
                    *(u32*)(sm + E_AB0 + 5632 + off) = pack_bf16_lo(f0, f1);
                }
            }
        }
    }
}

// ======== decode LSTM step: 256 thr, 32-row tiles, 2 CTAs/SM ================
__global__ void __launch_bounds__(256, 2)
k_dec(int B, int nTiles,
      const float* __restrict__ seW1, const float* __restrict__ seb1,
      const float* __restrict__ seg_, const float* __restrict__ seb_, float Ninv) {
    extern __shared__ char sm[];
    float* bs = (float*)(sm + D_BIAS);
    float* fold = (float*)(sm + D_FOLD);
    u32 smb = smem_u32(sm);
    int tid = threadIdx.x, wid = tid >> 5, lane = tid & 31;

    {
        const float4* s1 = (const float4*)g_Wh;
        const float4* s2 = (const float4*)g_Wl;
        float4* d1 = (float4*)(sm + O_WH);
        float4* d2 = (float4*)(sm + O_WL);
        for (int i = tid; i < 2816; i += 256) { d1[i] = s1[i]; d2[i] = s2[i]; }
    }
    bs[tid] = g_bias[tid];
    if (blockIdx.x == 0 && tid < 32) g_hp_stats[tid] = 0.0;
    if (tid < 16) {   // decode BN fold from se stats
        const double* st = g_se_stats;
        double mx = st[0] * Ninv, my = st[1] * Ninv;
        double vxx = st[2] * Ninv - mx * mx;
        double vyy = st[3] * Ninv - my * my;
        double cxy = st[4] * Ninv - mx * my;
        float w0 = seW1[2 * tid], w1 = seW1[2 * tid + 1];
        float mu = (float)(w0 * mx + w1 * my) + seb1[tid];
        float var = (float)((double)w0 * w0 * vxx + (double)w1 * w1 * vyy +
                            2.0 * (double)w0 * w1 * cxy);
        float sc = seg_[tid] * rsqrtf(var + EPSBN);
        fold[tid]      = w0 * sc;
        fold[16 + tid] = w1 * sc;
        fold[32 + tid] = (seb1[tid] - mu) * sc + seb_[tid];
    }
    __syncthreads();

    int wn = wid;
    int j0 = wn * 8 + (lane & 3) * 2;
    float bj[4][2];
#pragma unroll
    for (int g = 0; g < 4; g++) { bj[g][0] = bs[g * 64 + j0]; bj[g][1] = bs[g * 64 + j0 + 1]; }

    u32 bh[3][4][2];
    {
        u32 nrow = (u32)(wn * 8 + (lane & 7));
        u32 gsel = (u32)(((lane >> 4) & 1) * 64);
        u32 ksel = (u32)(((lane >> 3) & 1) * 16);
#pragma unroll
        for (int kt = 0; kt < 3; kt++) {
#pragma unroll
            for (int p = 0; p < 2; p++) {
                u32 r4[4];
                ldsm4(r4, smb + O_WH +
                      ((u32)(p * 2) * 64 + gsel + nrow) * (WSTR * 2) + ksel + (u32)(kt * 32));
                bh[kt][2 * p][0] = r4[0]; bh[kt][2 * p][1] = r4[1];
                bh[kt][2 * p + 1][0] = r4[2]; bh[kt][2 * p + 1][1] = r4[3];
            }
        }
    }

    u32 aRowOff = (u32)((lane & 15) * (WSTR * 2));
    u32 aColSel = (u32)(((lane >> 4) & 1) * 16);
    u32 bRow = (u32)(wn * 8 + (lane & 7));
    u32 bGsel = (u32)(((lane >> 4) & 1) * 64);
    u32 bKsel = (u32)(((lane >> 3) & 1) * 16);
    int srow = tid >> 3, seg8 = tid & 7, j2 = seg8 * 2;
    float fa0 = fold[j2], fb0 = fold[16 + j2], fc0 = fold[32 + j2];
    float fa1 = fold[j2 + 1], fb1 = fold[16 + j2 + 1], fc1 = fold[32 + j2 + 1];

    {   // prologue: stage first 32-row tile
        int r = blockIdx.x * 32 + srow;
        const float4* hp = (const float4*)(g_h + (size_t)r * 64 + seg8 * 8);
        float4 h0 = hp[0], h1 = hp[1];
        float2 lp = *(const float2*)(g_last + 2 * (size_t)r);
        uint4 hi, lo;
        hi.x = pack_bf16_hi(h0.x, h0.y); lo.x = pack_bf16_lo(h0.x, h0.y);
        hi.y = pack_bf16_hi(h0.z, h0.w); lo.y = pack_bf16_lo(h0.z, h0.w);
        hi.z = pack_bf16_hi(h1.x, h1.y); lo.z = pack_bf16_lo(h1.x, h1.y);
        hi.w = pack_bf16_hi(h1.z, h1.w); lo.w = pack_bf16_lo(h1.z, h1.w);
        int off = srow * (WSTR * 2) + 32 + seg8 * 16;
        *(uint4*)(sm + D_AH + off) = hi;
        *(uint4*)(sm + D_AL + off) = lo;
        float f0 = fmaxf(fa0 * lp.x + fb0 * lp.y + fc0, 0.f);
        float f1 = fmaxf(fa1 * lp.x + fb1 * lp.y + fc1, 0.f);
        int offf = srow * (WSTR * 2) + j2 * 2;
        *(u32*)(sm + D_AH + offf) = pack_bf16_hi(f0, f1);
        *(u32*)(sm + D_AL + offf) = pack_bf16_lo(f0, f1);
    }

    for (int tile = blockIdx.x; tile < nTiles; tile += gridDim.x) {
        int row0 = tile * 32;
        int nxt = tile + gridDim.x;

        float4 nh0, nh1; float2 nlp;
        bool hasNext = (nxt < nTiles);
        if (hasNext) {
            int r = nxt * 32 + srow;
            const float4* hp = (const float4*)(g_h + (size_t)r * 64 + seg8 * 8);
            nh0 = hp[0]; nh1 = hp[1];
            nlp = *(const float2*)(g_last + 2 * (size_t)r);
        }
        float2 cpre[2][2];
#pragma unroll
        for (int mt = 0; mt < 2; mt++)
#pragma unroll
            for (int rr = 0; rr < 2; rr++) {
                int rw = row0 + mt * 16 + rr * 8 + (lane >> 2);
                cpre[mt][rr] = *(const float2*)(g_c + (size_t)rw * 64 + j0);
            }
        __syncthreads();

        float acc[2][4][4];
#pragma unroll
        for (int mt = 0; mt < 2; mt++)
#pragma unroll
            for (int g = 0; g < 4; g++)
#pragma unroll
                for (int e = 0; e < 4; e++) acc[mt][g][e] = 0.f;

#pragma unroll
        for (int kt = 0; kt < 5; kt++) {
            u32 kOff = (u32)(kt * 32);
            u32 ah0[4], ah1[4], al0[4], al1[4];
            u32 aAddr = smb + D_AH + aRowOff + aColSel + kOff;
            ldsm4(ah0, aAddr);
            ldsm4(ah1, aAddr + 16 * (WSTR * 2));
            u32 aAddrL = smb + D_AL + aRowOff + aColSel + kOff;
            ldsm4(al0, aAddrL);
            ldsm4(al1, aAddrL + 16 * (WSTR * 2));
            u32 bl[4][2];
#pragma unroll
            for (int p = 0; p < 2; p++) {
                u32 r4[4];
                ldsm4(r4, smb + O_WL +
                      ((u32)(p * 2) * 64 + bGsel + bRow) * (WSTR * 2) + bKsel + kOff);
                bl[2 * p][0] = r4[0]; bl[2 * p][1] = r4[1];
                bl[2 * p + 1][0] = r4[2]; bl[2 * p + 1][1] = r4[3];
            }
            if (kt < 3) {
#pragma unroll
                for (int g = 0; g < 4; g++) {
                    mma16816(acc[0][g], ah0, bh[kt][g]);
                    mma16816(acc[1][g], ah1, bh[kt][g]);
                    mma16816(acc[0][g], al0, bh[kt][g]);
                    mma16816(acc[1][g], al1, bh[kt][g]);
                    mma16816(acc[0][g], ah0, bl[g]);
                    mma16816(acc[1][g], ah1, bl[g]);
                }
            } else {
                u32 bhd[4][2];
#pragma unroll
                for (int p = 0; p < 2; p++) {
                    u32 r4[4];
                    ldsm4(r4, smb + O_WH +
                          ((u32)(p * 2) * 64 + bGsel + bRow) * (WSTR * 2) + bKsel + kOff);
                    bhd[2 * p][0] = r4[0]; bhd[2 * p][1] = r4[1];
                    bhd[2 * p + 1][0] = r4[2]; bhd[2 * p + 1][1] = r4[3];
                }
#pragma unroll
                for (int g = 0; g < 4; g++) {
                    mma16816(acc[0][g], ah0, bhd[g]);
                    mma16816(acc[1][g], ah1, bhd[g]);
                    mma16816(acc[0][g], al0, bhd[g]);
                    mma16816(acc[1][g], al1, bhd[g]);
                    mma16816(acc[0][g], ah0, bl[g]);
                    mma16816(acc[1][g], ah1, bl[g]);
                }
            }
        }

        // epilogue: pointwise -> global h, c (c was prefetched)
#pragma unroll
        for (int mt = 0; mt < 2; mt++)
#pragma unroll
            for (int rr = 0; rr < 2; rr++) {
                int rw = row0 + mt * 16 + rr * 8 + (lane >> 2);
                float2 c2 = cpre[mt][rr];
                float cn[2], hn[2];
#pragma unroll
                for (int cc = 0; cc < 2; cc++) {
                    int e = rr * 2 + cc;
                    float iv = acc[mt][0][e] + bj[0][cc];
                    float fv = acc[mt][1][e] + bj[1][cc];
                    float gv = acc[mt][2][e] + bj[2][cc];
                    float ov = acc[mt][3][e] + bj[3][cc];
                    lstm_cell(iv, fv, gv, ov, cc ? c2.y : c2.x, cn[cc], hn[cc]);
                }
                *(float2*)(g_c + (size_t)rw * 64 + j0) = make_float2(cn[0], cn[1]);
                *(float2*)(g_h + (size_t)rw * 64 + j0) = make_float2(hn[0], hn[1]);
            }

        __syncthreads();
        if (hasNext) {
            uint4 hi, lo;
            hi.x = pack_bf16_hi(nh0.x, nh0.y); lo.x = pack_bf16_lo(nh0.x, nh0.y);
            hi.y = pack_bf16_hi(nh0.z, nh0.w); lo.y = pack_bf16_lo(nh0.z, nh0.w);
            hi.z = pack_bf16_hi(nh1.x, nh1.y); lo.z = pack_bf16_lo(nh1.x, nh1.y);
            hi.w = pack_bf16_hi(nh1.z, nh1.w); lo.w = pack_bf16_lo(nh1.z, nh1.w);
            int off = srow * (WSTR * 2) + 32 + seg8 * 16;
            *(uint4*)(sm + D_AH + off) = hi;
            *(uint4*)(sm + D_AL + off) = lo;
            float f0 = fmaxf(fa0 * nlp.x + fb0 * nlp.y + fc0, 0.f);
            float f1 = fmaxf(fa1 * nlp.x + fb1 * nlp.y + fc1, 0.f);
            int offf = srow * (WSTR * 2) + j2 * 2;
            *(u32*)(sm + D_AH + offf) = pack_bf16_hi(f0, f1);
            *(u32*)(sm + D_AL + offf) = pack_bf16_lo(f0, f1);
        }
    }
}

// ===== fused hidden2pos: z-proj + stats -> grid barrier -> positions ========
__global__ void __launch_bounds__(256, 2)
k_hppos(const float* __restrict__ hpW1, const float* __restrict__ hpb1,
        const float* __restrict__ hpW2, const float* __restrict__ hpb2,
        const float* __restrict__ gamma, const float* __restrict__ beta,
        float* __restrict__ out, const void* pxm, const void* pym,
        float Binv, int B) {
    __shared__ float Ws[1024];
    __shared__ float red[8][32];
    __shared__ float scp[34];   // sc[16], sh[16], b2x, b2y
    for (int i = threadIdx.x; i < 1024; i += 256) Ws[i] = hpW1[i];
    if (blockIdx.x == 0 && threadIdx.x < 5) g_se_stats[threadIdx.x] = 0.0;
    __syncthreads();
    int tid = threadIdx.x;
    int r0 = (blockIdx.x * 256 + tid) * 2;

    // ---- phase 1: z projection (z stays in registers) + hp stats ----
    float z0[16], z1[16];
#pragma unroll
    for (int jj = 0; jj < 16; jj++) { float b = hpb1[jj]; z0[jj] = b; z1[jj] = b; }
    const float4* ha = (const float4*)(g_h + (size_t)r0 * 64);
    const float4* hb = (const float4*)(g_h + (size_t)(r0 + 1) * 64);
#pragma unroll 4
    for (int kk = 0; kk < 16; kk++) {
        float4 a = ha[kk], b = hb[kk];
#pragma unroll
        for (int jj = 0; jj < 16; jj++) {
            const float* w = &Ws[jj * 64 + 4 * kk];
            z0[jj] += a.x * w[0] + a.y * w[1] + a.z * w[2] + a.w * w[3];
            z1[jj] += b.x * w[0] + b.y * w[1] + b.z * w[2] + b.w * w[3];
        }
    }
    float sv[16], qv[16];
#pragma unroll
    for (int jj = 0; jj < 16; jj++) {
        sv[jj] = z0[jj] + z1[jj];
        qv[jj] = z0[jj] * z0[jj] + z1[jj] * z1[jj];
    }
    int wid = tid >> 5, lane = tid & 31;
#pragma unroll
    for (int jj = 0; jj < 16; jj++) { sv[jj] = wred(sv[jj]); qv[jj] = wred(qv[jj]); }
    if (lane == 0) {
#pragma unroll
        for (int jj = 0; jj < 16; jj++) { red[wid][jj] = sv[jj]; red[wid][16 + jj] = qv[jj]; }
    }
    __syncthreads();
    if (wid == 0) {
        float t = 0.f;
#pragma unroll
        for (int w = 0; w < 8; w++) t += red[w][lane];
        atomicAdd(&g_hp_stats[lane], (double)t);
    }

    grid_barrier();

    // ---- phase 2: BN fold + positions + se moments ----
    if (tid < 16) {
        int j = tid;
        double mu = vload(&g_hp_stats[j]) * Binv;
        double var = vload(&g_hp_stats[16 + j]) * Binv - mu * mu;
        float s = gamma[j] * rsqrtf((float)var + EPSBN);
        scp[j] = s;
        scp[16 + j] = beta[j] - (float)mu * s;
    }
    if (tid == 16) { scp[32] = hpb2[0]; scp[33] = hpb2[1]; }
    __syncthreads();

    float px0 = scp[32], py0 = scp[33], px1 = scp[32], py1 = scp[33];
#pragma unroll
    for (int j = 0; j < 16; j++) {
        float w2x = __ldg(hpW2 + j), w2y = __ldg(hpW2 + 16 + j);
        float t0 = fmaxf(z0[j] * scp[j] + scp[16 + j], 0.f);
        float t1 = fmaxf(z1[j] * scp[j] + scp[16 + j], 0.f);
        px0 += t0 * w2x; py0 += t0 * w2y;
        px1 += t1 * w2x; py1 += t1 * w2y;
    }
    float xmax = scalar_f(pxm), ymax = scalar_f(pym);
    float2 lp0 = *(const float2*)(g_last + 2 * (size_t)r0);
    float2 lp1 = *(const float2*)(g_last + 2 * (size_t)(r0 + 1));
    float lx0 = fast_sig(px0 + lp0.x), ly0 = fast_sig(py0 + lp0.y);
    float lx1 = fast_sig(px1 + lp1.x), ly1 = fast_sig(py1 + lp1.y);
    *(float2*)(g_last + 2 * (size_t)r0) = make_float2(lx0, ly0);
    *(float2*)(g_last + 2 * (size_t)(r0 + 1)) = make_float2(lx1, ly1);
    float4 ov = make_float4(lx0 * xmax, ly0 * ymax, lx1 * xmax, ly1 * ymax);
    *(float4*)(out + 2 * (size_t)r0) = ov;

    float s[5] = {lx0 + lx1, ly0 + ly1, lx0 * lx0 + lx1 * lx1,
                  ly0 * ly0 + ly1 * ly1, lx0 * ly0 + lx1 * ly1};
#pragma unroll
    for (int k = 0; k < 5; k++) s[k] = wred(s[k]);
    __syncthreads();
    if (lane == 0) {
#pragma unroll
        for (int k = 0; k < 5; k++) red[wid][k] = s[k];
    }
    __syncthreads();
    if (wid == 0 && lane < 5) {
        float t = 0.f;
#pragma unroll
        for (int w = 0; w < 8; w++) t += red[w][lane];
        atomicAdd(&g_se_stats[lane], (double)t);
    }
}

// ---------------- launch ------------------------------------------------------
extern "C" void kernel_launch(void* const* d_in, const int* in_sizes, int n_in,
                              void* d_out, int out_size) {
    const float* obs  = (const float*)d_in[0];
    const float* seW1 = (const float*)d_in[1];
    const float* seb1 = (const float*)d_in[2];
    const float* seg  = (const float*)d_in[3];
    const float* seb  = (const float*)d_in[4];
    const float* seW2 = (const float*)d_in[5];
    const float* seb2 = (const float*)d_in[6];
    const float* hpW1 = (const float*)d_in[7];
    const float* hpb1 = (const float*)d_in[8];
    const float* hpg  = (const float*)d_in[9];
    const float* hpb  = (const float*)d_in[10];
    const float* hpW2 = (const float*)d_in[11];
    const float* hpb2 = (const float*)d_in[12];
    const float* Wih  = (const float*)d_in[13];
    const float* Whh  = (const float*)d_in[14];
    const float* bih  = (const float*)d_in[15];
    const float* bhh  = (const float*)d_in[16];
    const void*  pxm  = d_in[17];
    const void*  pym  = d_in[18];

    int B = in_sizes[0] / (T_OBS * 2);
    int TB = T_OBS * B;
    int predLen = out_size / (2 * B);
    float* out = (float*)d_out;

    cudaFuncSetAttribute(k_enc, cudaFuncAttributeMaxDynamicSharedMemorySize, ENC_SMEM);
    cudaFuncSetAttribute(k_dec, cudaFuncAttributeMaxDynamicSharedMemorySize, DEC_SMEM);

    k_prep<<<1, 256>>>(Wih, Whh, bih, bhh, seW2, seb2);
    k_moments<<<512, 256>>>(obs, pxm, pym, TB, B);
    k_enc<<<296, 256, ENC_SMEM>>>(obs, B, B / 32, seW1, seb1, seg, seb,
                                  pxm, pym, 1.0f / (float)TB);

    for (int s = 0; s < predLen; s++) {
        k_hppos<<<B / 512, 256>>>(hpW1, hpb1, hpW2, hpb2, hpg, hpb,
                                  out + (size_t)s * B * 2, pxm, pym,
                                  1.0f / (float)B, B);
        if (s + 1 < predLen)
            k_dec<<<296, 256, DEC_SMEM>>>(B, B / 32, seW1, seb1, seg, seb,
                                          1.0f / (float)B);
    }
}

// round 16
// speedup vs baseline: 1.1509x; 1.0084x over previous
#include <cuda_runtime.h>
#include <cuda_bf16.h>
#include <math.h>

#define T_OBS 8
#define EPSBN 1e-5f

typedef unsigned int u32;
typedef unsigned long long u64;

#define MAXB 131072
#define WSTR 88   // padded k-stride (bf16): 176B rows, conflict-free ldmatrix

// ---------------- static device scratch ------------------------------------
__device__ float  g_h[MAXB * 64];
__device__ float  g_c[MAXB * 64];
__device__ float  g_last[MAXB * 2];
__device__ __align__(16) __nv_bfloat16 g_Wh[256 * WSTR];
__device__ __align__(16) __nv_bfloat16 g_Wl[256 * WSTR];
__device__ float  g_bias[256];
__device__ double g_enc_stats[5];
__device__ double g_se_stats[5];
__device__ double g_hp_stats[32];
__device__ u32    g_barc = 0;
__device__ u32    g_barg = 0;

// ---------------- helpers ----------------------------------------------------
__device__ __forceinline__ float scalar_f(const void* p) {
    int iv = *(const int*)p;
    float fv = __int_as_float(iv);
    if (fv >= 1e-3f && fv <= 1e7f) return fv;
    return (float)iv;
}
__device__ __forceinline__ float fast_sig(float x) {
    float t; asm("ex2.approx.f32 %0, %1;" : "=f"(t) : "f"(-1.4426950408889634f * x));
    float r; asm("rcp.approx.f32 %0, %1;" : "=f"(r) : "f"(1.0f + t));
    return r;
}
// fused LSTM pointwise: 8 MUFU per cell
__device__ __forceinline__ void lstm_cell(float iv, float fv, float gv, float ov,
                                          float cold, float& cnew, float& hnew) {
    gv = fminf(fmaxf(gv, -30.f), 30.f);
    float tf; asm("ex2.approx.f32 %0, %1;" : "=f"(tf) : "f"(-1.4426950408889634f * fv));
    float sf; asm("rcp.approx.f32 %0, %1;" : "=f"(sf) : "f"(1.0f + tf));
    float ei; asm("ex2.approx.f32 %0, %1;" : "=f"(ei) : "f"(-1.4426950408889634f * iv));
    float eg; asm("ex2.approx.f32 %0, %1;" : "=f"(eg) : "f"(2.8853900817779268f * gv));
    float dig = (1.0f + ei) * (eg + 1.0f);
    float rig; asm("rcp.approx.f32 %0, %1;" : "=f"(rig) : "f"(dig));
    float c2 = sf * cold + (eg - 1.0f) * rig;
    cnew = c2;
    float eo; asm("ex2.approx.f32 %0, %1;" : "=f"(eo) : "f"(-1.4426950408889634f * ov));
    float ec; asm("ex2.approx.f32 %0, %1;" : "=f"(ec) : "f"(2.8853900817779268f * c2));
    float doc = (1.0f + eo) * (ec + 1.0f);
    float roc; asm("rcp.approx.f32 %0, %1;" : "=f"(roc) : "f"(doc));
    hnew = (ec - 1.0f) * roc;
}
__device__ __forceinline__ float wred(float v) {
#pragma unroll
    for (int o = 16; o > 0; o >>= 1) v += __shfl_down_sync(0xffffffffu, v, o);
    return v;
}
__device__ __forceinline__ u32 smem_u32(const void* p) {
    u32 a;
    asm("{ .reg .u64 t; cvta.to.shared.u64 t, %1; cvt.u32.u64 %0, t; }" : "=r"(a) : "l"(p));
    return a;
}
__device__ __forceinline__ void ldsm4(u32* r, u32 addr) {
    asm volatile("ldmatrix.sync.aligned.m8n8.x4.shared.b16 {%0,%1,%2,%3}, [%4];"
        : "=r"(r[0]), "=r"(r[1]), "=r"(r[2]), "=r"(r[3]) : "r"(addr));
}
__device__ __forceinline__ void mma16816(float* d, const u32* a, const u32* b) {
    asm volatile(
        "mma.sync.aligned.m16n8k16.row.col.f32.bf16.bf16.f32 "
        "{%0,%1,%2,%3},{%4,%5,%6,%7},{%8,%9},{%0,%1,%2,%3};"
        : "+f"(d[0]), "+f"(d[1]), "+f"(d[2]), "+f"(d[3])
        : "r"(a[0]), "r"(a[1]), "r"(a[2]), "r"(a[3]), "r"(b[0]), "r"(b[1]));
}
__device__ __forceinline__ u32 pack_bf16_hi(float a0, float a1) {
    __nv_bfloat16 h0 = __float2bfloat16(a0), h1 = __float2bfloat16(a1);
    return ((u32)__bfloat16_as_ushort(h1) << 16) | __bfloat16_as_ushort(h0);
}
__device__ __forceinline__ u32 pack_bf16_lo(float a0, float a1) {
    __nv_bfloat16 h0 = __float2bfloat16(a0), h1 = __float2bfloat16(a1);
    __nv_bfloat16 l0 = __float2bfloat16(a0 - __bfloat162float(h0));
    __nv_bfloat16 l1 = __float2bfloat16(a1 - __bfloat162float(h1));
    return ((u32)__bfloat16_as_ushort(l1) << 16) | __bfloat16_as_ushort(l0);
}
__device__ __forceinline__ double vload(const double* p) {
    return *(volatile const double*)p;
}
__device__ __forceinline__ void grid_barrier() {
    __syncthreads();
    if (threadIdx.x == 0) {
        __threadfence();
        u32 gen = *(volatile u32*)&g_barg;
        u32 old = atomicAdd(&g_barc, 1);
        if (old == gridDim.x - 1) {
            atomicExch(&g_barc, 0);
            __threadfence();
            atomicExch(&g_barg, gen + 1);
        } else {
            while (*(volatile u32*)&g_barg == gen) { __nanosleep(64); }
        }
        __threadfence();
    }
    __syncthreads();
}

// ---------------- smem layouts ------------------------------------------------
#define O_WH   0                    // 45056
#define O_WL   45056                // 45056
// both LSTM kernels: 256 thr, 2 CTA/SM, 32-row tiles, double-buffered A
#define L_AB0  90112                // AH0; AL0=+5632; AH1=+11264; AL1=+16896
#define L_BIAS 112640               // 1024
#define L_FOLD 113664               // 192
#define LSTM_SMEM 113856

// ---------------- prep: fold se_W2/se_b2 into Wih; bf16-split ---------------
__global__ void k_prep(const float* __restrict__ Wih, const float* __restrict__ Whh,
                       const float* __restrict__ bih, const float* __restrict__ bhh,
                       const float* __restrict__ seW2, const float* __restrict__ seb2) {
    int gc = threadIdx.x;
    if (gc < 5) g_enc_stats[gc] = 0.0;
    float wr[64];
#pragma unroll 8
    for (int m = 0; m < 64; m++) wr[m] = Wih[gc * 64 + m];
    float be = bih[gc] + bhh[gc];
#pragma unroll 8
    for (int m = 0; m < 64; m++) be += wr[m] * seb2[m];
    g_bias[gc] = be;
    for (int k = 0; k < WSTR; k++) {
        float w = 0.f;
        if (k < 16) {
#pragma unroll 8
            for (int m = 0; m < 64; m++) w += wr[m] * seW2[m * 16 + k];
        } else if (k < 80) {
            w = Whh[gc * 64 + (k - 16)];
        }
        __nv_bfloat16 hi = __float2bfloat16(w);
        __nv_bfloat16 lo = __float2bfloat16(w - __bfloat162float(hi));
        g_Wh[gc * WSTR + k] = hi;
        g_Wl[gc * WSTR + k] = lo;
    }
}

// ---------------- moments of normalized obs + init last_pos -----------------
__global__ void k_moments(const float* __restrict__ obs, const void* pxm, const void* pym,
                          int TB, int B) {
    __shared__ float red[8][5];
    float invx = 1.0f / scalar_f(pxm), invy = 1.0f / scalar_f(pym);
    int idx = blockIdx.x * blockDim.x + threadIdx.x;
    int stride = gridDim.x * blockDim.x;
    float s[5] = {0, 0, 0, 0, 0};
    for (int i = idx; i < TB; i += stride) {
        float x = obs[2 * i] * invx, y = obs[2 * i + 1] * invy;
        s[0] += x; s[1] += y; s[2] += x * x; s[3] += y * y; s[4] += x * y;
    }
    int wid = threadIdx.x >> 5, lane = threadIdx.x & 31;
#pragma unroll
    for (int k = 0; k < 5; k++) s[k] = wred(s[k]);
    if (lane == 0) {
#pragma unroll
        for (int k = 0; k < 5; k++) red[wid][k] = s[k];
    }
    __syncthreads();
    if (wid == 0 && lane < 5) {
        float t = 0.f;
#pragma unroll
        for (int w = 0; w < 8; w++) t += red[w][lane];
        atomicAdd(&g_enc_stats[lane], (double)t);
    }
    int off = TB - B;
    for (int i = idx; i < B; i += stride) {
        g_last[2 * i]     = obs[2 * (off + i)]     * invx;
        g_last[2 * i + 1] = obs[2 * (off + i) + 1] * invy;
    }
}

// ===== fused 8-step encoder: 256 thr, 32-row tiles, 2 CTAs/SM, dbl-buf A ====
__global__ void __launch_bounds__(256, 2)
k_enc(const float* __restrict__ obs, int B, int nTiles,
      const float* __restrict__ seW1, const float* __restrict__ seb1,
      const float* __restrict__ seg_, const float* __restrict__ seb_,
      const void* pxm, const void* pym, float Ninv) {
    extern __shared__ char sm[];
    float* bs = (float*)(sm + L_BIAS);
    float* fold = (float*)(sm + L_FOLD);
    u32 smb = smem_u32(sm);
    int tid = threadIdx.x, wid = tid >> 5, lane = tid & 31;

    {
        const float4* s1 = (const float4*)g_Wh;
        const float4* s2 = (const float4*)g_Wl;
        float4* d1 = (float4*)(sm + O_WH);
        float4* d2 = (float4*)(sm + O_WL);
        for (int i = tid; i < 2816; i += 256) { d1[i] = s1[i]; d2[i] = s2[i]; }
    }
    bs[tid] = g_bias[tid];
    if (blockIdx.x == 0 && tid < 32) g_hp_stats[tid] = 0.0;
    if (tid < 16) {   // encode BN fold (analytic, from 5 moments)
        const double* st = g_enc_stats;
        double mx = st[0] * Ninv, my = st[1] * Ninv;
        double vxx = st[2] * Ninv - mx * mx;
        double vyy = st[3] * Ninv - my * my;
        double cxy = st[4] * Ninv - mx * my;
        float w0 = seW1[2 * tid], w1 = seW1[2 * tid + 1];
        float mu = (float)(w0 * mx + w1 * my) + seb1[tid];
        float var = (float)((double)w0 * w0 * vxx + (double)w1 * w1 * vyy +
                            2.0 * (double)w0 * w1 * cxy);
        float sc = seg_[tid] * rsqrtf(var + EPSBN);
        float ix = 1.f / scalar_f(pxm), iy = 1.f / scalar_f(pym);
        fold[tid]      = w0 * sc * ix;
        fold[16 + tid] = w1 * sc * iy;
        fold[32 + tid] = (seb1[tid] - mu) * sc + seb_[tid];
    }
    __syncthreads();

    int wn = wid;
    int j0 = wn * 8 + (lane & 3) * 2;
    float bj[4][2];
#pragma unroll
    for (int g = 0; g < 4; g++) { bj[g][0] = bs[g * 64 + j0]; bj[g][1] = bs[g * 64 + j0 + 1]; }

    u32 bh[3][4][2];
    {
        u32 nrow = (u32)(wn * 8 + (lane & 7));
        u32 gsel = (u32)(((lane >> 4) & 1) * 64);
        u32 ksel = (u32)(((lane >> 3) & 1) * 16);
#pragma unroll
        for (int kt = 0; kt < 3; kt++) {
#pragma unroll
            for (int p = 0; p < 2; p++) {
                u32 r4[4];
                ldsm4(r4, smb + O_WH +
                      ((u32)(p * 2) * 64 + gsel + nrow) * (WSTR * 2) + ksel + (u32)(kt * 32));
                bh[kt][2 * p][0] = r4[0]; bh[kt][2 * p][1] = r4[1];
                bh[kt][2 * p + 1][0] = r4[2]; bh[kt][2 * p + 1][1] = r4[3];
            }
        }
    }

    u32 aRowOff = (u32)((lane & 15) * (WSTR * 2));
    u32 aColSel = (u32)(((lane >> 4) & 1) * 16);
    u32 bRow = (u32)(wn * 8 + (lane & 7));
    u32 bGsel = (u32)(((lane >> 4) & 1) * 64);
    u32 bKsel = (u32)(((lane >> 3) & 1) * 16);
    int srow = tid >> 3, seg8 = tid & 7, j2 = seg8 * 2;
    float fa0 = fold[j2], fb0 = fold[16 + j2], fc0 = fold[32 + j2];
    float fa1 = fold[j2 + 1], fb1 = fold[16 + j2 + 1], fc1 = fold[32 + j2 + 1];

    {   // prologue: stage feats t0 of first tile into buf0
        int r = blockIdx.x * 32 + srow;
        float2 xy0 = *(const float2*)(obs + 2 * (size_t)r);
        float f0 = fmaxf(fa0 * xy0.x + fb0 * xy0.y + fc0, 0.f);
        float f1 = fmaxf(fa1 * xy0.x + fb1 * xy0.y + fc1, 0.f);
        int off = srow * (WSTR * 2) + j2 * 2;
        *(u32*)(sm + L_AB0 + off) = pack_bf16_hi(f0, f1);
        *(u32*)(sm + L_AB0 + 5632 + off) = pack_bf16_lo(f0, f1);
    }

    for (int tile = blockIdx.x; tile < nTiles; tile += gridDim.x) {
        int row0 = tile * 32;
        int nxt = tile + gridDim.x;
        float creg[2][2][2];

        for (int t = 0; t < T_OBS; t++) {
            u32 ahb = smb + L_AB0 + (u32)((t & 1) * 11264);
            u32 alb = ahb + 5632;
            float2 nxy = make_float2(0.f, 0.f);
            if (t < T_OBS - 1) {
                nxy = *(const float2*)(obs + (size_t)(t + 1) * B * 2 + 2 * (size_t)(row0 + srow));
            } else if (nxt < nTiles) {
                nxy = *(const float2*)(obs + 2 * (size_t)(nxt * 32 + srow));
            }
            __syncthreads();

            float acc[2][4][4];
#pragma unroll
            for (int mt = 0; mt < 2; mt++)
#pragma unroll
                for (int g = 0; g < 4; g++)
#pragma unroll
                    for (int e = 0; e < 4; e++) acc[mt][g][e] = 0.f;
            int nkt = t ? 5 : 1;
#pragma unroll
            for (int kt = 0; kt < 5; kt++) {
                if (kt >= nkt) break;
                u32 kOff = (u32)(kt * 32);
                u32 ah0[4], ah1[4], al0[4], al1[4];
                u32 aAddr = ahb + aRowOff + aColSel + kOff;
                ldsm4(ah0, aAddr);
                ldsm4(ah1, aAddr + 16 * (WSTR * 2));
                u32 aAddrL = alb + aRowOff + aColSel + kOff;
                ldsm4(al0, aAddrL);
                ldsm4(al1, aAddrL + 16 * (WSTR * 2));
                u32 bl[4][2];
#pragma unroll
                for (int p = 0; p < 2; p++) {
                    u32 r4[4];
                    ldsm4(r4, smb + O_WL +
                          ((u32)(p * 2) * 64 + bGsel + bRow) * (WSTR * 2) + bKsel + kOff);
                    bl[2 * p][0] = r4[0]; bl[2 * p][1] = r4[1];
                    bl[2 * p + 1][0] = r4[2]; bl[2 * p + 1][1] = r4[3];
                }
                if (kt < 3) {
#pragma unroll
                    for (int g = 0; g < 4; g++) {
                        mma16816(acc[0][g], ah0, bh[kt][g]);
                        mma16816(acc[1][g], ah1, bh[kt][g]);
                        mma16816(acc[0][g], al0, bh[kt][g]);
                        mma16816(acc[1][g], al1, bh[kt][g]);
                        mma16816(acc[0][g], ah0, bl[g]);
                        mma16816(acc[1][g], ah1, bl[g]);
                    }
                } else {
                    u32 bhd[4][2];
#pragma unroll
                    for (int p = 0; p < 2; p++) {
                        u32 r4[4];
                        ldsm4(r4, smb + O_WH +
                              ((u32)(p * 2) * 64 + bGsel + bRow) * (WSTR * 2) + bKsel + kOff);
                        bhd[2 * p][0] = r4[0]; bhd[2 * p][1] = r4[1];
                        bhd[2 * p + 1][0] = r4[2]; bhd[2 * p + 1][1] = r4[3];
                    }
#pragma unroll
                    for (int g = 0; g < 4; g++) {
                        mma16816(acc[0][g], ah0, bhd[g]);
                        mma16816(acc[1][g], ah1, bhd[g]);
                        mma16816(acc[0][g], al0, bhd[g]);
                        mma16816(acc[1][g], al1, bhd[g]);
                        mma16816(acc[0][g], ah0, bl[g]);
                        mma16816(acc[1][g], ah1, bl[g]);
                    }
                }
            }

            float hn[2][2][2];
#pragma unroll
            for (int mt = 0; mt < 2; mt++)
#pragma unroll
                for (int rr = 0; rr < 2; rr++)
#pragma unroll
                    for (int cc = 0; cc < 2; cc++) {
                        int e = rr * 2 + cc;
                        float iv = acc[mt][0][e] + bj[0][cc];
                        float fv = acc[mt][1][e] + bj[1][cc];
                        float gv = acc[mt][2][e] + bj[2][cc];
                        float ov = acc[mt][3][e] + bj[3][cc];
                        float cold = t ? creg[mt][rr][cc] : 0.f;
                        lstm_cell(iv, fv, gv, ov, cold, creg[mt][rr][cc], hn[mt][rr][cc]);
                    }

            if (t < T_OBS - 1) {
                u32 ahn = smb + L_AB0 + (u32)(((t + 1) & 1) * 11264);
#pragma unroll
                for (int mt = 0; mt < 2; mt++)
#pragma unroll
                    for (int rr = 0; rr < 2; rr++) {
                        int lrow = mt * 16 + rr * 8 + (lane >> 2);
                        int off = lrow * (WSTR * 2) + (16 + j0) * 2;
                        *(u32*)(ahn - smb + sm + off) = pack_bf16_hi(hn[mt][rr][0], hn[mt][rr][1]);
                        *(u32*)(ahn + 5632 - smb + sm + off) = pack_bf16_lo(hn[mt][rr][0], hn[mt][rr][1]);
                    }
                float f0 = fmaxf(fa0 * nxy.x + fb0 * nxy.y + fc0, 0.f);
                float f1 = fmaxf(fa1 * nxy.x + fb1 * nxy.y + fc1, 0.f);
                int off = srow * (WSTR * 2) + j2 * 2;
                *(u32*)(ahn - smb + sm + off) = pack_bf16_hi(f0, f1);
                *(u32*)(ahn + 5632 - smb + sm + off) = pack_bf16_lo(f0, f1);
            } else {
#pragma unroll
                for (int mt = 0; mt < 2; mt++)
#pragma unroll
                    for (int rr = 0; rr < 2; rr++) {
                        int r = row0 + mt * 16 + rr * 8 + (lane >> 2);
                        *(float2*)(g_h + (size_t)r * 64 + j0) =
                            make_float2(hn[mt][rr][0], hn[mt][rr][1]);
                        *(float2*)(g_c + (size_t)r * 64 + j0) =
                            make_float2(creg[mt][rr][0], creg[mt][rr][1]);
                    }
                if (nxt < nTiles) {
                    float f0 = fmaxf(fa0 * nxy.x + fb0 * nxy.y + fc0, 0.f);
                    float f1 = fmaxf(fa1 * nxy.x + fb1 * nxy.y + fc1, 0.f);
                    int off = srow * (WSTR * 2) + j2 * 2;
                    *(u32*)(sm + L_AB0 + off) = pack_bf16_hi(f0, f1);
                    *(u32*)(sm + L_AB0 + 5632 + off) = pack_bf16_lo(f0, f1);
                }
            }
        }
    }
}

// ======== decode LSTM step: 2 CTAs/SM, double-buffered A, 1 sync/tile =======
__global__ void __launch_bounds__(256, 2)
k_dec(int B, int nTiles,
      const float* __restrict__ seW1, const float* __restrict__ seb1,
      const float* __restrict__ seg_, const float* __restrict__ seb_, float Ninv) {
    extern __shared__ char sm[];
    float* bs = (float*)(sm + L_BIAS);
    float* fold = (float*)(sm + L_FOLD);
    u32 smb = smem_u32(sm);
    int tid = threadIdx.x, wid = tid >> 5, lane = tid & 31;

    {
        const float4* s1 = (const float4*)g_Wh;
        const float4* s2 = (const float4*)g_Wl;
        float4* d1 = (float4*)(sm + O_WH);
        float4* d2 = (float4*)(sm + O_WL);
        for (int i = tid; i < 2816; i += 256) { d1[i] = s1[i]; d2[i] = s2[i]; }
    }
    bs[tid] = g_bias[tid];
    if (blockIdx.x == 0 && tid < 32) g_hp_stats[tid] = 0.0;
    if (tid < 16) {   // decode BN fold from se stats
        const double* st = g_se_stats;
        double mx = st[0] * Ninv, my = st[1] * Ninv;
        double vxx = st[2] * Ninv - mx * mx;
        double vyy = st[3] * Ninv - my * my;
        double cxy = st[4] * Ninv - mx * my;
        float w0 = seW1[2 * tid], w1 = seW1[2 * tid + 1];
        float mu = (float)(w0 * mx + w1 * my) + seb1[tid];
        float var = (float)((double)w0 * w0 * vxx + (double)w1 * w1 * vyy +
                            2.0 * (double)w0 * w1 * cxy);
        float sc = seg_[tid] * rsqrtf(var + EPSBN);
        fold[tid]      = w0 * sc;
        fold[16 + tid] = w1 * sc;
        fold[32 + tid] = (seb1[tid] - mu) * sc + seb_[tid];
    }
    __syncthreads();

    int wn = wid;
    int j0 = wn * 8 + (lane & 3) * 2;
    float bj[4][2];
#pragma unroll
    for (int g = 0; g < 4; g++) { bj[g][0] = bs[g * 64 + j0]; bj[g][1] = bs[g * 64 + j0 + 1]; }

    u32 bh[3][4][2];
    {
        u32 nrow = (u32)(wn * 8 + (lane & 7));
        u32 gsel = (u32)(((lane >> 4) & 1) * 64);
        u32 ksel = (u32)(((lane >> 3) & 1) * 16);
#pragma unroll
        for (int kt = 0; kt < 3; kt++) {
#pragma unroll
            for (int p = 0; p < 2; p++) {
                u32 r4[4];
                ldsm4(r4, smb + O_WH +
                      ((u32)(p * 2) * 64 + gsel + nrow) * (WSTR * 2) + ksel + (u32)(kt * 32));
                bh[kt][2 * p][0] = r4[0]; bh[kt][2 * p][1] = r4[1];
                bh[kt][2 * p + 1][0] = r4[2]; bh[kt][2 * p + 1][1] = r4[3];
            }
        }
    }

    u32 aRowOff = (u32)((lane & 15) * (WSTR * 2));
    u32 aColSel = (u32)(((lane >> 4) & 1) * 16);
    u32 bRow = (u32)(wn * 8 + (lane & 7));
    u32 bGsel = (u32)(((lane >> 4) & 1) * 64);
    u32 bKsel = (u32)(((lane >> 3) & 1) * 16);
    int srow = tid >> 3, seg8 = tid & 7, j2 = seg8 * 2;
    float fa0 = fold[j2], fb0 = fold[16 + j2], fc0 = fold[32 + j2];
    float fa1 = fold[j2 + 1], fb1 = fold[16 + j2 + 1], fc1 = fold[32 + j2 + 1];

    {   // prologue: stage first 32-row tile into buf0
        int r = blockIdx.x * 32 + srow;
        const float4* hp = (const float4*)(g_h + (size_t)r * 64 + seg8 * 8);
        float4 h0 = hp[0], h1 = hp[1];
        float2 lp = *(const float2*)(g_last + 2 * (size_t)r);
        uint4 hi, lo;
        hi.x = pack_bf16_hi(h0.x, h0.y); lo.x = pack_bf16_lo(h0.x, h0.y);
        hi.y = pack_bf16_hi(h0.z, h0.w); lo.y = pack_bf16_lo(h0.z, h0.w);
        hi.z = pack_bf16_hi(h1.x, h1.y); lo.z = pack_bf16_lo(h1.x, h1.y);
        hi.w = pack_bf16_hi(h1.z, h1.w); lo.w = pack_bf16_lo(h1.z, h1.w);
        int off = srow * (WSTR * 2) + 32 + seg8 * 16;
        *(uint4*)(sm + L_AB0 + off) = hi;
        *(uint4*)(sm + L_AB0 + 5632 + off) = lo;
        float f0 = fmaxf(fa0 * lp.x + fb0 * lp.y + fc0, 0.f);
        float f1 = fmaxf(fa1 * lp.x + fb1 * lp.y + fc1, 0.f);
        int offf = srow * (WSTR * 2) + j2 * 2;
        *(u32*)(sm + L_AB0 + offf) = pack_bf16_hi(f0, f1);
        *(u32*)(sm + L_AB0 + 5632 + offf) = pack_bf16_lo(f0, f1);
    }

    int pbuf = 0;
    for (int tile = blockIdx.x; tile < nTiles; tile += gridDim.x) {
        int row0 = tile * 32;
        int nxt = tile + gridDim.x;
        u32 ahb = smb + L_AB0 + (u32)(pbuf * 11264);
        u32 alb = ahb + 5632;

        // prefetch next tile (hide LDG under MMA) + current c (before sync)
        float4 nh0, nh1; float2 nlp;
        bool hasNext = (nxt < nTiles);
        if (hasNext) {
            int r = nxt * 32 + srow;
            const float4* hp = (const float4*)(g_h + (size_t)r * 64 + seg8 * 8);
            nh0 = hp[0]; nh1 = hp[1];
            nlp = *(const float2*)(g_last + 2 * (size_t)r);
        }
        float2 cpre[2][2];
#pragma unroll
        for (int mt = 0; mt < 2; mt++)
#pragma unroll
            for (int rr = 0; rr < 2; rr++) {
                int rw = row0 + mt * 16 + rr * 8 + (lane >> 2);
                cpre[mt][rr] = *(const float2*)(g_c + (size_t)rw * 64 + j0);
            }
        __syncthreads();   // buf pbuf staged (prev iter) + buf pbuf^1 readers done

        float acc[2][4][4];
#pragma unroll
        for (int mt = 0; mt < 2; mt++)
#pragma unroll
            for (int g = 0; g < 4; g++)
#pragma unroll
                for (int e = 0; e < 4; e++) acc[mt][g][e] = 0.f;

#pragma unroll
        for (int kt = 0; kt < 5; kt++) {
            u32 kOff = (u32)(kt * 32);
            u32 ah0[4], ah1[4], al0[4], al1[4];
            u32 aAddr = ahb + aRowOff + aColSel + kOff;
            ldsm4(ah0, aAddr);
            ldsm4(ah1, aAddr + 16 * (WSTR * 2));
            u32 aAddrL = alb + aRowOff + aColSel + kOff;
            ldsm4(al0, aAddrL);
            ldsm4(al1, aAddrL + 16 * (WSTR * 2));
            u32 bl[4][2];
#pragma unroll
            for (int p = 0; p < 2; p++) {
                u32 r4[4];
                ldsm4(r4, smb + O_WL +
                      ((u32)(p * 2) * 64 + bGsel + bRow) * (WSTR * 2) + bKsel + kOff);
                bl[2 * p][0] = r4[0]; bl[2 * p][1] = r4[1];
                bl[2 * p + 1][0] = r4[2]; bl[2 * p + 1][1] = r4[3];
            }
            if (kt < 3) {
#pragma unroll
                for (int g = 0; g < 4; g++) {
                    mma16816(acc[0][g], ah0, bh[kt][g]);
                    mma16816(acc[1][g], ah1, bh[kt][g]);
                    mma16816(acc[0][g], al0, bh[kt][g]);
                    mma16816(acc[1][g], al1, bh[kt][g]);
                    mma16816(acc[0][g], ah0, bl[g]);
                    mma16816(acc[1][g], ah1, bl[g]);
                }
            } else {
                u32 bhd[4][2];
#pragma unroll
                for (int p = 0; p < 2; p++) {
                    u32 r4[4];
                    ldsm4(r4, smb + O_WH +
                          ((u32)(p * 2) * 64 + bGsel + bRow) * (WSTR * 2) + bKsel + kOff);
                    bhd[2 * p][0] = r4[0]; bhd[2 * p][1] = r4[1];
                    bhd[2 * p + 1][0] = r4[2]; bhd[2 * p + 1][1] = r4[3];
                }
#pragma unroll
                for (int g = 0; g < 4; g++) {
                    mma16816(acc[0][g], ah0, bhd[g]);
                    mma16816(acc[1][g], ah1, bhd[g]);
                    mma16816(acc[0][g], al0, bhd[g]);
                    mma16816(acc[1][g], al1, bhd[g]);
                    mma16816(acc[0][g], ah0, bl[g]);
                    mma16816(acc[1][g], ah1, bl[g]);
                }
            }
        }

        // stage next tile into the OTHER buffer NOW (overlaps MUFU epilogue;
        // safe: that buffer's readers finished before this iteration's sync)
        if (hasNext) {
            u32 off1 = (u32)(L_AB0 + (pbuf ^ 1) * 11264);
            uint4 hi, lo;
            hi.x = pack_bf16_hi(nh0.x, nh0.y); lo.x = pack_bf16_lo(nh0.x, nh0.y);
            hi.y = pack_bf16_hi(nh0.z, nh0.w); lo.y = pack_bf16_lo(nh0.z, nh0.w);
            hi.z = pack_bf16_hi(nh1.x, nh1.y); lo.z = pack_bf16_lo(nh1.x, nh1.y);
            hi.w = pack_bf16_hi(nh1.z, nh1.w); lo.w = pack_bf16_lo(nh1.z, nh1.w);
            int off = srow * (WSTR * 2) + 32 + seg8 * 16;
            *(uint4*)(sm + off1 + off) = hi;
            *(uint4*)(sm + off1 + 5632 + off) = lo;
            float f0 = fmaxf(fa0 * nlp.x + fb0 * nlp.y + fc0, 0.f);
            float f1 = fmaxf(fa1 * nlp.x + fb1 * nlp.y + fc1, 0.f);
            int offf = srow * (WSTR * 2) + j2 * 2;
            *(u32*)(sm + off1 + offf) = pack_bf16_hi(f0, f1);
            *(u32*)(sm + off1 + 5632 + offf) = pack_bf16_lo(f0, f1);
        }

        // epilogue: pointwise -> global h, c (c was prefetched)
#pragma unroll
        for (int mt = 0; mt < 2; mt++)
#pragma unroll
            for (int rr = 0; rr < 2; rr++) {
                int rw = row0 + mt * 16 + rr * 8 + (lane >> 2);
                float2 c2 = cpre[mt][rr];
                float cn[2], hn[2];
#pragma unroll
                for (int cc = 0; cc < 2; cc++) {
                    int e = rr * 2 + cc;
                    float iv = acc[mt][0][e] + bj[0][cc];
                    float fv = acc[mt][1][e] + bj[1][cc];
                    float gv = acc[mt][2][e] + bj[2][cc];
                    float ov = acc[mt][3][e] + bj[3][cc];
                    lstm_cell(iv, fv, gv, ov, cc ? c2.y : c2.x, cn[cc], hn[cc]);
                }
                *(float2*)(g_c + (size_t)rw * 64 + j0) = make_float2(cn[0], cn[1]);
                *(float2*)(g_h + (size_t)rw * 64 + j0) = make_float2(hn[0], hn[1]);
            }
        pbuf ^= 1;
    }
}

// ===== fused hidden2pos: z-proj + stats -> grid barrier -> positions ========
__global__ void __launch_bounds__(256, 2)
k_hppos(const float* __restrict__ hpW1, const float* __restrict__ hpb1,
        const float* __restrict__ hpW2, const float* __restrict__ hpb2,
        const float* __restrict__ gamma, const float* __restrict__ beta,
        float* __restrict__ out, const void* pxm, const void* pym,
        float Binv, int B) {
    __shared__ float Ws[1024];
    __shared__ float red[8][32];
    __shared__ float scp[34];   // sc[16], sh[16], b2x, b2y
    for (int i = threadIdx.x; i < 1024; i += 256) Ws[i] = hpW1[i];
    if (blockIdx.x == 0 && threadIdx.x < 5) g_se_stats[threadIdx.x] = 0.0;
    __syncthreads();
    int tid = threadIdx.x;
    int r0 = (blockIdx.x * 256 + tid) * 2;

    // ---- phase 1: z projection (z stays in registers) + hp stats ----
    float z0[16], z1[16];
#pragma unroll
    for (int jj = 0; jj < 16; jj++) { float b = hpb1[jj]; z0[jj] = b; z1[jj] = b; }
    const float4* ha = (const float4*)(g_h + (size_t)r0 * 64);
    const float4* hb = (const float4*)(g_h + (size_t)(r0 + 1) * 64);
#pragma unroll 4
    for (int kk = 0; kk < 16; kk++) {
        float4 a = ha[kk], b = hb[kk];
#pragma unroll
        for (int jj = 0; jj < 16; jj++) {
            const float* w = &Ws[jj * 64 + 4 * kk];
            z0[jj] += a.x * w[0] + a.y * w[1] + a.z * w[2] + a.w * w[3];
            z1[jj] += b.x * w[0] + b.y * w[1] + b.z * w[2] + b.w * w[3];
        }
    }
    float sv[16], qv[16];
#pragma unroll
    for (int jj = 0; jj < 16; jj++) {
        sv[jj] = z0[jj] + z1[jj];
        qv[jj] = z0[jj] * z0[jj] + z1[jj] * z1[jj];
    }
    int wid = tid >> 5, lane = tid & 31;
#pragma unroll
    for (int jj = 0; jj < 16; jj++) { sv[jj] = wred(sv[jj]); qv[jj] = wred(qv[jj]); }
    if (lane == 0) {
#pragma unroll
        for (int jj = 0; jj < 16; jj++) { red[wid][jj] = sv[jj]; red[wid][16 + jj] = qv[jj]; }
    }
    __syncthreads();
    if (wid == 0) {
        float t = 0.f;
#pragma unroll
        for (int w = 0; w < 8; w++) t += red[w][lane];
        atomicAdd(&g_hp_stats[lane], (double)t);
    }

    grid_barrier();

    // ---- phase 2: BN fold + positions + se moments ----
    if (tid < 16) {
        int j = tid;
        double mu = vload(&g_hp_stats[j]) * Binv;
        double var = vload(&g_hp_stats[16 + j]) * Binv - mu * mu;
        float s = gamma[j] * rsqrtf((float)var + EPSBN);
        scp[j] = s;
        scp[16 + j] = beta[j] - (float)mu * s;
    }
    if (tid == 16) { scp[32] = hpb2[0]; scp[33] = hpb2[1]; }
    __syncthreads();

    float px0 = scp[32], py0 = scp[33], px1 = scp[32], py1 = scp[33];
#pragma unroll
    for (int j = 0; j < 16; j++) {
        float w2x = __ldg(hpW2 + j), w2y = __ldg(hpW2 + 16 + j);
        float t0 = fmaxf(z0[j] * scp[j] + scp[16 + j], 0.f);
        float t1 = fmaxf(z1[j] * scp[j] + scp[16 + j], 0.f);
        px0 += t0 * w2x; py0 += t0 * w2y;
        px1 += t1 * w2x; py1 += t1 * w2y;
    }
    float xmax = scalar_f(pxm), ymax = scalar_f(pym);
    float2 lp0 = *(const float2*)(g_last + 2 * (size_t)r0);
    float2 lp1 = *(const float2*)(g_last + 2 * (size_t)(r0 + 1));
    float lx0 = fast_sig(px0 + lp0.x), ly0 = fast_sig(py0 + lp0.y);
    float lx1 = fast_sig(px1 + lp1.x), ly1 = fast_sig(py1 + lp1.y);
    *(float2*)(g_last + 2 * (size_t)r0) = make_float2(lx0, ly0);
    *(float2*)(g_last + 2 * (size_t)(r0 + 1)) = make_float2(lx1, ly1);
    float4 ov = make_float4(lx0 * xmax, ly0 * ymax, lx1 * xmax, ly1 * ymax);
    *(float4*)(out + 2 * (size_t)r0) = ov;

    float s[5] = {lx0 + lx1, ly0 + ly1, lx0 * lx0 + lx1 * lx1,
                  ly0 * ly0 + ly1 * ly1, lx0 * ly0 + lx1 * ly1};
#pragma unroll
    for (int k = 0; k < 5; k++) s[k] = wred(s[k]);
    __syncthreads();
    if (lane == 0) {
#pragma unroll
        for (int k = 0; k < 5; k++) red[wid][k] = s[k];
    }
    __syncthreads();
    if (wid == 0 && lane < 5) {
        float t = 0.f;
#pragma unroll
        for (int w = 0; w < 8; w++) t += red[w][lane];
        atomicAdd(&g_se_stats[lane], (double)t);
    }
}

// ---------------- launch ------------------------------------------------------
extern "C" void kernel_launch(void* const* d_in, const int* in_sizes, int n_in,
                              void* d_out, int out_size) {
    const float* obs  = (const float*)d_in[0];
    const float* seW1 = (const float*)d_in[1];
    const float* seb1 = (const float*)d_in[2];
    const float* seg  = (const float*)d_in[3];
    const float* seb  = (const float*)d_in[4];
    const float* seW2 = (const float*)d_in[5];
    const float* seb2 = (const float*)d_in[6];
    const float* hpW1 = (const float*)d_in[7];
    const float* hpb1 = (const float*)d_in[8];
    const float* hpg  = (const float*)d_in[9];
    const float* hpb  = (const float*)d_in[10];
    const float* hpW2 = (const float*)d_in[11];
    const float* hpb2 = (const float*)d_in[12];
    const float* Wih  = (const float*)d_in[13];
    const float* Whh  = (const float*)d_in[14];
    const float* bih  = (const float*)d_in[15];
    const float* bhh  = (const float*)d_in[16];
    const void*  pxm  = d_in[17];
    const void*  pym  = d_in[18];

    int B = in_sizes[0] / (T_OBS * 2);
    int TB = T_OBS * B;
    int predLen = out_size / (2 * B);
    float* out = (float*)d_out;

    cudaFuncSetAttribute(k_enc, cudaFuncAttributeMaxDynamicSharedMemorySize, LSTM_SMEM);
    cudaFuncSetAttribute(k_dec, cudaFuncAttributeMaxDynamicSharedMemorySize, LSTM_SMEM);

    k_prep<<<1, 256>>>(Wih, Whh, bih, bhh, seW2, seb2);
    k_moments<<<512, 256>>>(obs, pxm, pym, TB, B);
    k_enc<<<296, 256, LSTM_SMEM>>>(obs, B, B / 32, seW1, seb1, seg, seb,
                                   pxm, pym, 1.0f / (float)TB);

    for (int s = 0; s < predLen; s++) {
        k_hppos<<<B / 512, 256>>>(hpW1, hpb1, hpW2, hpb2, hpg, hpb,
                                  out + (size_t)s * B * 2, pxm, pym,
                                  1.0f / (float)B, B);
        if (s + 1 < predLen)
            k_dec<<<296, 256, LSTM_SMEM>>>(B, B / 32, seW1, seb1, seg, seb,
                                           1.0f / (float)B);
    }
}